// round 1
// baseline (speedup 1.0000x reference)
#include <cuda_runtime.h>
#include <math.h>

// Problem constants
#define B_  2
#define T_  2048
#define C_  1024
#define U_  1024
#define H_  16
#define DH_ 64
#define M_  4096   // B_*T_

// Scratch (device globals; no allocation allowed)
__device__ float g_Q[(size_t)M_ * U_];
__device__ float g_K[(size_t)M_ * U_];
__device__ float g_V[(size_t)M_ * U_];
__device__ float g_O[(size_t)M_ * U_];
__device__ float g_mask[M_];

// ---------------------------------------------------------------------------
// Key/query mask: sign(|sum_c x[b,t,c]|)
// ---------------------------------------------------------------------------
__global__ __launch_bounds__(256) void mask_kernel(const float* __restrict__ x) {
    int row = blockIdx.x;
    const float4* xr = reinterpret_cast<const float4*>(x + (size_t)row * C_);
    float4 v = xr[threadIdx.x];            // 256 threads * 4 = 1024
    float s = v.x + v.y + v.z + v.w;
    __shared__ float red[8];
#pragma unroll
    for (int o = 16; o; o >>= 1) s += __shfl_xor_sync(0xffffffffu, s, o);
    if ((threadIdx.x & 31) == 0) red[threadIdx.x >> 5] = s;
    __syncthreads();
    if (threadIdx.x == 0) {
        float t = 0.0f;
#pragma unroll
        for (int i = 0; i < 8; i++) t += red[i];
        g_mask[row] = (t != 0.0f) ? 1.0f : 0.0f;
    }
}

// ---------------------------------------------------------------------------
// Y = relu(X @ W + b), X:[4096,1024], W:[1024,1024]. Tiled SGEMM 128x128x16,
// 256 threads, 8x8 per-thread microtile, global->reg prefetch.
// sel: 0->g_Q, 1->g_K, 2->g_V
// ---------------------------------------------------------------------------
__global__ __launch_bounds__(256, 2) void gemm_relu_kernel(
    const float* __restrict__ X, const float* __restrict__ W,
    const float* __restrict__ bias, int sel) {
    float* __restrict__ Y = (sel == 0) ? g_Q : (sel == 1) ? g_K : g_V;
    __shared__ float As[16][128];   // A transposed: As[k][m]
    __shared__ float Bs[16][128];   // Bs[k][n]

    int tid = threadIdx.x;
    int tx = tid & 15, ty = tid >> 4;
    int m0 = blockIdx.y * 128, n0 = blockIdx.x * 128;

    int ar = tid >> 2;            // 0..63 (A row in tile, +64 for second half)
    int ac = (tid & 3) << 2;      // 0,4,8,12 (A k-col base)
    int kr = tid >> 5;            // 0..7 (B k-row, +8 for second half)
    int nc = (tid & 31) << 2;     // 0..124 step 4 (B col base)

    float acc[8][8];
#pragma unroll
    for (int i = 0; i < 8; i++)
#pragma unroll
        for (int j = 0; j < 8; j++) acc[i][j] = 0.0f;

    // prefetch first k-slab
    float4 pa0 = *reinterpret_cast<const float4*>(&X[(size_t)(m0 + ar) * C_ + ac]);
    float4 pa1 = *reinterpret_cast<const float4*>(&X[(size_t)(m0 + ar + 64) * C_ + ac]);
    float4 pb0 = *reinterpret_cast<const float4*>(&W[(size_t)kr * U_ + n0 + nc]);
    float4 pb1 = *reinterpret_cast<const float4*>(&W[(size_t)(kr + 8) * U_ + n0 + nc]);

    for (int k0 = 0; k0 < C_; k0 += 16) {
        As[ac + 0][ar] = pa0.x; As[ac + 1][ar] = pa0.y;
        As[ac + 2][ar] = pa0.z; As[ac + 3][ar] = pa0.w;
        As[ac + 0][ar + 64] = pa1.x; As[ac + 1][ar + 64] = pa1.y;
        As[ac + 2][ar + 64] = pa1.z; As[ac + 3][ar + 64] = pa1.w;
        *reinterpret_cast<float4*>(&Bs[kr][nc]) = pb0;
        *reinterpret_cast<float4*>(&Bs[kr + 8][nc]) = pb1;
        __syncthreads();

        int kn = k0 + 16;
        if (kn < C_) {
            pa0 = *reinterpret_cast<const float4*>(&X[(size_t)(m0 + ar) * C_ + kn + ac]);
            pa1 = *reinterpret_cast<const float4*>(&X[(size_t)(m0 + ar + 64) * C_ + kn + ac]);
            pb0 = *reinterpret_cast<const float4*>(&W[(size_t)(kn + kr) * U_ + n0 + nc]);
            pb1 = *reinterpret_cast<const float4*>(&W[(size_t)(kn + kr + 8) * U_ + n0 + nc]);
        }

#pragma unroll
        for (int k = 0; k < 16; ++k) {
            float4 a0 = *reinterpret_cast<const float4*>(&As[k][ty * 8]);
            float4 a1 = *reinterpret_cast<const float4*>(&As[k][ty * 8 + 4]);
            float4 b0 = *reinterpret_cast<const float4*>(&Bs[k][tx * 8]);
            float4 b1 = *reinterpret_cast<const float4*>(&Bs[k][tx * 8 + 4]);
            float av[8] = {a0.x, a0.y, a0.z, a0.w, a1.x, a1.y, a1.z, a1.w};
            float bv[8] = {b0.x, b0.y, b0.z, b0.w, b1.x, b1.y, b1.z, b1.w};
#pragma unroll
            for (int i = 0; i < 8; i++)
#pragma unroll
                for (int j = 0; j < 8; j++)
                    acc[i][j] = fmaf(av[i], bv[j], acc[i][j]);
        }
        __syncthreads();
    }

    // epilogue: bias + relu
    float bvals[8];
#pragma unroll
    for (int j = 0; j < 8; j++) bvals[j] = bias[n0 + tx * 8 + j];
#pragma unroll
    for (int i = 0; i < 8; ++i) {
        size_t rowoff = (size_t)(m0 + ty * 8 + i) * U_ + n0 + tx * 8;
        float4 o0, o1;
        o0.x = fmaxf(acc[i][0] + bvals[0], 0.0f);
        o0.y = fmaxf(acc[i][1] + bvals[1], 0.0f);
        o0.z = fmaxf(acc[i][2] + bvals[2], 0.0f);
        o0.w = fmaxf(acc[i][3] + bvals[3], 0.0f);
        o1.x = fmaxf(acc[i][4] + bvals[4], 0.0f);
        o1.y = fmaxf(acc[i][5] + bvals[5], 0.0f);
        o1.z = fmaxf(acc[i][6] + bvals[6], 0.0f);
        o1.w = fmaxf(acc[i][7] + bvals[7], 0.0f);
        *reinterpret_cast<float4*>(&Y[rowoff]) = o0;
        *reinterpret_cast<float4*>(&Y[rowoff + 4]) = o1;
    }
}

// ---------------------------------------------------------------------------
// Flash-attention, causal. Tile BQ=64, BK=64, dh=64. 256 threads = 16x16;
// each thread owns 4 q-rows (ty*4+i) x 4 cols (tx*4+j).
// Dynamic smem: Qst[d][q] 16KB + Kst[d][k] 16KB + Vs[k][d] 16KB + Ps[q][k] 16KB.
// ---------------------------------------------------------------------------
__global__ __launch_bounds__(256, 2) void attn_kernel() {
    extern __shared__ float sm[];
    float* Qst = sm;            // [64][64] d-major
    float* Kst = sm + 4096;     // [64][64] d-major
    float* Vs  = sm + 8192;     // [64][64] k-major (natural)
    float* Ps  = sm + 12288;    // [64][64] q-major

    int tid = threadIdx.x;
    int tx = tid & 15, ty = tid >> 4;
    int qt = blockIdx.x;        // 0..31 (q tiles of 64)
    int bh = blockIdx.y;        // 0..31
    int b = bh >> 4, h = bh & 15;
    size_t base = (size_t)b * T_ * U_;
    int hcol = h * DH_;

    int li = tid >> 2;          // 0..63 tile row for loading
    int db = (tid & 3) << 4;    // 0,16,32,48

    // load Q tile transposed (d-major)
    {
        size_t off = base + (size_t)(qt * 64 + li) * U_ + hcol + db;
#pragma unroll
        for (int ii = 0; ii < 4; ++ii) {
            float4 v = *reinterpret_cast<const float4*>(&g_Q[off + ii * 4]);
            int d = db + ii * 4;
            Qst[(d + 0) * 64 + li] = v.x;
            Qst[(d + 1) * 64 + li] = v.y;
            Qst[(d + 2) * 64 + li] = v.z;
            Qst[(d + 3) * 64 + li] = v.w;
        }
    }

    float O[4][4];
#pragma unroll
    for (int i = 0; i < 4; i++)
#pragma unroll
        for (int j = 0; j < 4; j++) O[i][j] = 0.0f;
    float mrow[4] = {-INFINITY, -INFINITY, -INFINITY, -INFINITY};
    float lrow[4] = {0.0f, 0.0f, 0.0f, 0.0f};
    float qm[4];
#pragma unroll
    for (int i = 0; i < 4; i++) qm[i] = g_mask[b * T_ + qt * 64 + ty * 4 + i];

    const float NEGV = -4294967296.0f;  // float32(-2^32+1), matches reference cast

    for (int kt = 0; kt <= qt; ++kt) {
        __syncthreads();  // previous PV done before overwriting K/V/Ps
        // load K (transposed to d-major) and V (natural)
        {
            size_t koff = base + (size_t)(kt * 64 + li) * U_ + hcol + db;
#pragma unroll
            for (int ii = 0; ii < 4; ++ii) {
                int d = db + ii * 4;
                float4 kv = *reinterpret_cast<const float4*>(&g_K[koff + ii * 4]);
                Kst[(d + 0) * 64 + li] = kv.x;
                Kst[(d + 1) * 64 + li] = kv.y;
                Kst[(d + 2) * 64 + li] = kv.z;
                Kst[(d + 3) * 64 + li] = kv.w;
                float4 vv = *reinterpret_cast<const float4*>(&g_V[koff + ii * 4]);
                *reinterpret_cast<float4*>(&Vs[li * 64 + d]) = vv;
            }
        }
        __syncthreads();

        // S = Q K^T (tile), rank-1 updates over d
        float s[4][4];
#pragma unroll
        for (int i = 0; i < 4; i++)
#pragma unroll
            for (int j = 0; j < 4; j++) s[i][j] = 0.0f;
#pragma unroll 8
        for (int d = 0; d < 64; ++d) {
            float4 aq = *reinterpret_cast<const float4*>(&Qst[d * 64 + ty * 4]);
            float4 bk = *reinterpret_cast<const float4*>(&Kst[d * 64 + tx * 4]);
            s[0][0] = fmaf(aq.x, bk.x, s[0][0]); s[0][1] = fmaf(aq.x, bk.y, s[0][1]);
            s[0][2] = fmaf(aq.x, bk.z, s[0][2]); s[0][3] = fmaf(aq.x, bk.w, s[0][3]);
            s[1][0] = fmaf(aq.y, bk.x, s[1][0]); s[1][1] = fmaf(aq.y, bk.y, s[1][1]);
            s[1][2] = fmaf(aq.y, bk.z, s[1][2]); s[1][3] = fmaf(aq.y, bk.w, s[1][3]);
            s[2][0] = fmaf(aq.z, bk.x, s[2][0]); s[2][1] = fmaf(aq.z, bk.y, s[2][1]);
            s[2][2] = fmaf(aq.z, bk.z, s[2][2]); s[2][3] = fmaf(aq.z, bk.w, s[2][3]);
            s[3][0] = fmaf(aq.w, bk.x, s[3][0]); s[3][1] = fmaf(aq.w, bk.y, s[3][1]);
            s[3][2] = fmaf(aq.w, bk.z, s[3][2]); s[3][3] = fmaf(aq.w, bk.w, s[3][3]);
        }

        // scale + key mask + causal mask
        int qg0 = qt * 64 + ty * 4;
        int kg0 = kt * 64 + tx * 4;
        float km[4];
#pragma unroll
        for (int j = 0; j < 4; j++) km[j] = g_mask[b * T_ + kg0 + j];
#pragma unroll
        for (int i = 0; i < 4; i++)
#pragma unroll
            for (int j = 0; j < 4; j++) {
                float sv = s[i][j] * 0.125f;  // 1/sqrt(64)
                if (km[j] == 0.0f || (kg0 + j) > (qg0 + i)) sv = NEGV;
                s[i][j] = sv;
            }

        // online softmax per q-row, all-reduce over the 16 tx lanes
#pragma unroll
        for (int i = 0; i < 4; ++i) {
            float mt = fmaxf(fmaxf(s[i][0], s[i][1]), fmaxf(s[i][2], s[i][3]));
#pragma unroll
            for (int o = 8; o >= 1; o >>= 1)
                mt = fmaxf(mt, __shfl_xor_sync(0xffffffffu, mt, o));
            float mnew = fmaxf(mrow[i], mt);
            float p0 = __expf(s[i][0] - mnew);
            float p1 = __expf(s[i][1] - mnew);
            float p2 = __expf(s[i][2] - mnew);
            float p3 = __expf(s[i][3] - mnew);
            float ps = p0 + p1 + p2 + p3;
#pragma unroll
            for (int o = 8; o >= 1; o >>= 1)
                ps += __shfl_xor_sync(0xffffffffu, ps, o);
            float alpha = __expf(mrow[i] - mnew);
            lrow[i] = lrow[i] * alpha + ps;
            mrow[i] = mnew;
            O[i][0] *= alpha; O[i][1] *= alpha; O[i][2] *= alpha; O[i][3] *= alpha;
            *reinterpret_cast<float4*>(&Ps[(ty * 4 + i) * 64 + tx * 4]) =
                make_float4(p0, p1, p2, p3);
        }
        __syncthreads();

        // O += P @ V
#pragma unroll 8
        for (int k = 0; k < 64; ++k) {
            float4 v4 = *reinterpret_cast<const float4*>(&Vs[k * 64 + tx * 4]);
#pragma unroll
            for (int i = 0; i < 4; ++i) {
                float p = Ps[(ty * 4 + i) * 64 + k];
                O[i][0] = fmaf(p, v4.x, O[i][0]);
                O[i][1] = fmaf(p, v4.y, O[i][1]);
                O[i][2] = fmaf(p, v4.z, O[i][2]);
                O[i][3] = fmaf(p, v4.w, O[i][3]);
            }
        }
    }

    // normalize by l, apply query mask, write out
#pragma unroll
    for (int i = 0; i < 4; ++i) {
        float inv = qm[i] / lrow[i];
        float4 o = make_float4(O[i][0] * inv, O[i][1] * inv, O[i][2] * inv, O[i][3] * inv);
        *reinterpret_cast<float4*>(
            &g_O[base + (size_t)(qt * 64 + ty * 4 + i) * U_ + hcol + tx * 4]) = o;
    }
}

// ---------------------------------------------------------------------------
// Residual + LayerNorm (biased variance, eps=1e-8) + affine
// ---------------------------------------------------------------------------
__global__ __launch_bounds__(256) void ln_kernel(
    const float* __restrict__ x, const float* __restrict__ gamma,
    const float* __restrict__ beta, float* __restrict__ out) {
    int row = blockIdx.x;
    int tid = threadIdx.x;
    __shared__ float rsum[8], rsq[8];
    __shared__ float smean, srstd;

    const float4* x4 = reinterpret_cast<const float4*>(x + (size_t)row * U_);
    const float4* o4 = reinterpret_cast<const float4*>(g_O + (size_t)row * U_);
    float4 xv = x4[tid], ov = o4[tid];
    float4 sv = make_float4(xv.x + ov.x, xv.y + ov.y, xv.z + ov.z, xv.w + ov.w);

    float s1 = sv.x + sv.y + sv.z + sv.w;
    float s2 = sv.x * sv.x + sv.y * sv.y + sv.z * sv.z + sv.w * sv.w;
#pragma unroll
    for (int o = 16; o; o >>= 1) {
        s1 += __shfl_xor_sync(0xffffffffu, s1, o);
        s2 += __shfl_xor_sync(0xffffffffu, s2, o);
    }
    if ((tid & 31) == 0) { rsum[tid >> 5] = s1; rsq[tid >> 5] = s2; }
    __syncthreads();
    if (tid == 0) {
        float t1 = 0, t2 = 0;
#pragma unroll
        for (int i = 0; i < 8; i++) { t1 += rsum[i]; t2 += rsq[i]; }
        float mean = t1 * (1.0f / U_);
        float var = t2 * (1.0f / U_) - mean * mean;
        smean = mean;
        srstd = rsqrtf(var + 1e-8f);
    }
    __syncthreads();
    float mean = smean, rstd = srstd;

    const float4* g4 = reinterpret_cast<const float4*>(gamma);
    const float4* b4 = reinterpret_cast<const float4*>(beta);
    float4 gv = g4[tid], bv = b4[tid];
    float4 o;
    o.x = gv.x * ((sv.x - mean) * rstd) + bv.x;
    o.y = gv.y * ((sv.y - mean) * rstd) + bv.y;
    o.z = gv.z * ((sv.z - mean) * rstd) + bv.z;
    o.w = gv.w * ((sv.w - mean) * rstd) + bv.w;
    reinterpret_cast<float4*>(out + (size_t)row * U_)[tid] = o;
}

// ---------------------------------------------------------------------------
extern "C" void kernel_launch(void* const* d_in, const int* in_sizes, int n_in,
                              void* d_out, int out_size) {
    const float* x     = (const float*)d_in[0];
    const float* Wq    = (const float*)d_in[1];
    const float* bq    = (const float*)d_in[2];
    const float* Wk    = (const float*)d_in[3];
    const float* bk    = (const float*)d_in[4];
    const float* Wv    = (const float*)d_in[5];
    const float* bv    = (const float*)d_in[6];
    const float* gamma = (const float*)d_in[7];
    const float* beta  = (const float*)d_in[8];
    float* out = (float*)d_out;

    cudaFuncSetAttribute(attn_kernel,
                         cudaFuncAttributeMaxDynamicSharedMemorySize, 65536);

    mask_kernel<<<M_, 256>>>(x);
    dim3 gg(U_ / 128, M_ / 128);
    gemm_relu_kernel<<<gg, 256>>>(x, Wq, bq, 0);
    gemm_relu_kernel<<<gg, 256>>>(x, Wk, bk, 1);
    gemm_relu_kernel<<<gg, 256>>>(x, Wv, bv, 2);
    attn_kernel<<<dim3(T_ / 64, B_ * H_), 256, 65536>>>();
    ln_kernel<<<M_, 256>>>(x, gamma, beta, out);
}

// round 4
// speedup vs baseline: 1.2951x; 1.2951x over previous
#include <cuda_runtime.h>
#include <math.h>
#include <stdint.h>

// Problem constants
#define B_  2
#define T_  2048
#define C_  1024
#define U_  1024
#define H_  16
#define DH_ 64
#define M_  4096   // B_*T_

// Scratch (device globals; no allocation allowed)
__device__ float g_Q[(size_t)M_ * U_];
__device__ float g_K[(size_t)M_ * U_];
__device__ float g_V[(size_t)M_ * U_];
__device__ float g_O[(size_t)M_ * U_];
__device__ float g_Wt[3][(size_t)C_ * U_];   // transposed weights [N][K]
__device__ float g_mask[M_];

__device__ __forceinline__ float to_tf32(float x) {
    float r;
    asm("cvt.rna.tf32.f32 %0, %1;" : "=f"(r) : "f"(x));
    return r;
}

#define MMA_TF32(d, a, b) \
    asm volatile("mma.sync.aligned.m16n8k8.row.col.f32.tf32.tf32.f32 " \
        "{%0,%1,%2,%3}, {%4,%5,%6,%7}, {%8,%9}, {%0,%1,%2,%3};" \
        : "+f"((d)[0]), "+f"((d)[1]), "+f"((d)[2]), "+f"((d)[3]) \
        : "r"((a)[0]), "r"((a)[1]), "r"((a)[2]), "r"((a)[3]), \
          "r"((b)[0]), "r"((b)[1]))

// ---------------------------------------------------------------------------
// Key/query mask: sign(|sum_c x[b,t,c]|)
// ---------------------------------------------------------------------------
__global__ __launch_bounds__(256) void mask_kernel(const float* __restrict__ x) {
    int row = blockIdx.x;
    const float4* xr = reinterpret_cast<const float4*>(x + (size_t)row * C_);
    float4 v = xr[threadIdx.x];
    float s = v.x + v.y + v.z + v.w;
    __shared__ float red[8];
#pragma unroll
    for (int o = 16; o; o >>= 1) s += __shfl_xor_sync(0xffffffffu, s, o);
    if ((threadIdx.x & 31) == 0) red[threadIdx.x >> 5] = s;
    __syncthreads();
    if (threadIdx.x == 0) {
        float t = 0.0f;
#pragma unroll
        for (int i = 0; i < 8; i++) t += red[i];
        g_mask[row] = (t != 0.0f) ? 1.0f : 0.0f;
    }
}

// ---------------------------------------------------------------------------
// Transpose W [K,N] -> Wt [N,K] once (3 weights)
// ---------------------------------------------------------------------------
__global__ __launch_bounds__(256) void wtrans_kernel(
    const float* __restrict__ Wq, const float* __restrict__ Wk,
    const float* __restrict__ Wv) {
    __shared__ float t[32][33];
    const float* W = blockIdx.z == 0 ? Wq : blockIdx.z == 1 ? Wk : Wv;
    float* Wt = g_Wt[blockIdx.z];
    int x = blockIdx.x * 32 + threadIdx.x;
    int y0 = blockIdx.y * 32;
#pragma unroll
    for (int j = 0; j < 32; j += 8)
        t[threadIdx.y + j][threadIdx.x] = W[(size_t)(y0 + threadIdx.y + j) * U_ + x];
    __syncthreads();
    int ox = y0 + threadIdx.x;
    int oy0 = blockIdx.x * 32;
#pragma unroll
    for (int j = 0; j < 32; j += 8)
        Wt[(size_t)(oy0 + threadIdx.y + j) * C_ + ox] = t[threadIdx.x][threadIdx.y + j];
}

// ---------------------------------------------------------------------------
// QKV projection via mma.sync tf32. Y = relu(X @ W + b).
// CTA tile 128x128, Kc=32. 8 warps (2x4), warp tile 64x32, m16n8k8.
// Smem rows padded to 36 floats -> conflict-free fragment gathers.
// Grid (8, 32, 3): x = N tile, y = M tile, z = weight select.
// ---------------------------------------------------------------------------
#define KC   32
#define NC   (C_ / KC)      // 32 stages
#define SROW 36             // padded row stride (floats)
#define ABUF (128 * SROW)   // 4608 floats per A stage

__global__ __launch_bounds__(256) void qkv_mma_kernel(
    const float* __restrict__ X,
    const float* __restrict__ bq, const float* __restrict__ bk,
    const float* __restrict__ bv) {
    extern __shared__ float sm[];
    // layout: A0 [0,4608) A1 [4608,9216) B0 [9216,13824) B1 [13824,18432)
    int tid = threadIdx.x;
    int wid = tid >> 5, lane = tid & 31;
    int gid = lane >> 2, tig = lane & 3;
    int wm = wid >> 2, wn = wid & 3;      // 2 x 4 warp grid
    int sel = blockIdx.z;
    const float* Wt = g_Wt[sel];
    float* Y = sel == 0 ? g_Q : sel == 1 ? g_K : g_V;
    const float* bias = sel == 0 ? bq : sel == 1 ? bk : bv;
    int n0 = blockIdx.x * 128, m0 = blockIdx.y * 128;

    // Global load mapping: each thread owns 16 floats of A and 16 of B per stage
    int arow = tid >> 1, acol = (tid & 1) * 16;
    const float* Ap = X + (size_t)(m0 + arow) * C_ + acol;
    const float* Bp = Wt + (size_t)(n0 + arow) * C_ + acol;

    float acc[4][4][4];
#pragma unroll
    for (int i = 0; i < 4; i++)
#pragma unroll
        for (int j = 0; j < 4; j++)
#pragma unroll
            for (int r = 0; r < 4; r++) acc[i][j][r] = 0.0f;

    float4 ra[4], rb[4];
#pragma unroll
    for (int i = 0; i < 4; i++) {
        ra[i] = *reinterpret_cast<const float4*>(Ap + i * 4);
        rb[i] = *reinterpret_cast<const float4*>(Bp + i * 4);
    }
    // store stage 0
    {
        float* As = sm;
        float* Bs = sm + 2 * ABUF;
#pragma unroll
        for (int i = 0; i < 4; i++) {
            float4 a = ra[i], b = rb[i];
            int off = arow * SROW + acol + i * 4;
            As[off + 0] = to_tf32(a.x); As[off + 1] = to_tf32(a.y);
            As[off + 2] = to_tf32(a.z); As[off + 3] = to_tf32(a.w);
            Bs[off + 0] = to_tf32(b.x); Bs[off + 1] = to_tf32(b.y);
            Bs[off + 2] = to_tf32(b.z); Bs[off + 3] = to_tf32(b.w);
        }
    }
    __syncthreads();

#pragma unroll 1
    for (int c = 0; c < NC; c++) {
        int b = c & 1;
        if (c + 1 < NC) {
            const float* Apn = Ap + (c + 1) * KC;
            const float* Bpn = Bp + (c + 1) * KC;
#pragma unroll
            for (int i = 0; i < 4; i++) {
                ra[i] = *reinterpret_cast<const float4*>(Apn + i * 4);
                rb[i] = *reinterpret_cast<const float4*>(Bpn + i * 4);
            }
        }

        const float* As = sm + b * ABUF;
        const float* Bs = sm + 2 * ABUF + b * ABUF;
#pragma unroll
        for (int ks = 0; ks < 4; ks++) {
            int k0 = ks * 8 + tig;
            uint32_t af[4][4];
#pragma unroll
            for (int mi = 0; mi < 4; mi++) {
                int r0 = (wm * 64 + mi * 16 + gid) * SROW;
                af[mi][0] = __float_as_uint(As[r0 + k0]);
                af[mi][1] = __float_as_uint(As[r0 + 8 * SROW + k0]);
                af[mi][2] = __float_as_uint(As[r0 + k0 + 4]);
                af[mi][3] = __float_as_uint(As[r0 + 8 * SROW + k0 + 4]);
            }
            uint32_t bf[4][2];
#pragma unroll
            for (int ni = 0; ni < 4; ni++) {
                int nr = (wn * 32 + ni * 8 + gid) * SROW;
                bf[ni][0] = __float_as_uint(Bs[nr + k0]);
                bf[ni][1] = __float_as_uint(Bs[nr + k0 + 4]);
            }
#pragma unroll
            for (int mi = 0; mi < 4; mi++)
#pragma unroll
                for (int ni = 0; ni < 4; ni++)
                    MMA_TF32(acc[mi][ni], af[mi], bf[ni]);
        }

        if (c + 1 < NC) {
            float* Asn = sm + (b ^ 1) * ABUF;
            float* Bsn = sm + 2 * ABUF + (b ^ 1) * ABUF;
#pragma unroll
            for (int i = 0; i < 4; i++) {
                float4 a = ra[i], bb = rb[i];
                int off = arow * SROW + acol + i * 4;
                Asn[off + 0] = to_tf32(a.x); Asn[off + 1] = to_tf32(a.y);
                Asn[off + 2] = to_tf32(a.z); Asn[off + 3] = to_tf32(a.w);
                Bsn[off + 0] = to_tf32(bb.x); Bsn[off + 1] = to_tf32(bb.y);
                Bsn[off + 2] = to_tf32(bb.z); Bsn[off + 3] = to_tf32(bb.w);
            }
        }
        __syncthreads();
    }

    // Epilogue: bias + relu, float2 stores
#pragma unroll
    for (int mi = 0; mi < 4; mi++) {
        int gr0 = m0 + wm * 64 + mi * 16 + gid;
#pragma unroll
        for (int ni = 0; ni < 4; ni++) {
            int gc = n0 + wn * 32 + ni * 8 + 2 * tig;
            float b0v = bias[gc], b1v = bias[gc + 1];
            float2 o0, o1;
            o0.x = fmaxf(acc[mi][ni][0] + b0v, 0.0f);
            o0.y = fmaxf(acc[mi][ni][1] + b1v, 0.0f);
            o1.x = fmaxf(acc[mi][ni][2] + b0v, 0.0f);
            o1.y = fmaxf(acc[mi][ni][3] + b1v, 0.0f);
            *reinterpret_cast<float2*>(&Y[(size_t)gr0 * U_ + gc]) = o0;
            *reinterpret_cast<float2*>(&Y[(size_t)(gr0 + 8) * U_ + gc]) = o1;
        }
    }
}

// ---------------------------------------------------------------------------
// Flash-attention, causal. Tile BQ=64, BK=64, dh=64. 256 threads = 16x16.
// ---------------------------------------------------------------------------
__global__ __launch_bounds__(256, 2) void attn_kernel() {
    extern __shared__ float smf[];
    float* Qst = smf;           // [64][64] d-major
    float* Kst = smf + 4096;    // [64][64] d-major
    float* Vs  = smf + 8192;    // [64][64] k-major
    float* Ps  = smf + 12288;   // [64][64] q-major

    int tid = threadIdx.x;
    int tx = tid & 15, ty = tid >> 4;
    int qt = blockIdx.x;
    int bh = blockIdx.y;
    int b = bh >> 4, h = bh & 15;
    size_t base = (size_t)b * T_ * U_;
    int hcol = h * DH_;

    int li = tid >> 2;
    int db = (tid & 3) << 4;

    {
        size_t off = base + (size_t)(qt * 64 + li) * U_ + hcol + db;
#pragma unroll
        for (int ii = 0; ii < 4; ++ii) {
            float4 v = *reinterpret_cast<const float4*>(&g_Q[off + ii * 4]);
            int d = db + ii * 4;
            Qst[(d + 0) * 64 + li] = v.x;
            Qst[(d + 1) * 64 + li] = v.y;
            Qst[(d + 2) * 64 + li] = v.z;
            Qst[(d + 3) * 64 + li] = v.w;
        }
    }

    float O[4][4];
#pragma unroll
    for (int i = 0; i < 4; i++)
#pragma unroll
        for (int j = 0; j < 4; j++) O[i][j] = 0.0f;
    float mrow[4] = {-INFINITY, -INFINITY, -INFINITY, -INFINITY};
    float lrow[4] = {0.0f, 0.0f, 0.0f, 0.0f};
    float qm[4];
#pragma unroll
    for (int i = 0; i < 4; i++) qm[i] = g_mask[b * T_ + qt * 64 + ty * 4 + i];

    const float NEGV = -4294967296.0f;

    for (int kt = 0; kt <= qt; ++kt) {
        __syncthreads();
        {
            size_t koff = base + (size_t)(kt * 64 + li) * U_ + hcol + db;
#pragma unroll
            for (int ii = 0; ii < 4; ++ii) {
                int d = db + ii * 4;
                float4 kv = *reinterpret_cast<const float4*>(&g_K[koff + ii * 4]);
                Kst[(d + 0) * 64 + li] = kv.x;
                Kst[(d + 1) * 64 + li] = kv.y;
                Kst[(d + 2) * 64 + li] = kv.z;
                Kst[(d + 3) * 64 + li] = kv.w;
                float4 vv = *reinterpret_cast<const float4*>(&g_V[koff + ii * 4]);
                *reinterpret_cast<float4*>(&Vs[li * 64 + d]) = vv;
            }
        }
        __syncthreads();

        float s[4][4];
#pragma unroll
        for (int i = 0; i < 4; i++)
#pragma unroll
            for (int j = 0; j < 4; j++) s[i][j] = 0.0f;
#pragma unroll 8
        for (int d = 0; d < 64; ++d) {
            float4 aq = *reinterpret_cast<const float4*>(&Qst[d * 64 + ty * 4]);
            float4 bk = *reinterpret_cast<const float4*>(&Kst[d * 64 + tx * 4]);
            s[0][0] = fmaf(aq.x, bk.x, s[0][0]); s[0][1] = fmaf(aq.x, bk.y, s[0][1]);
            s[0][2] = fmaf(aq.x, bk.z, s[0][2]); s[0][3] = fmaf(aq.x, bk.w, s[0][3]);
            s[1][0] = fmaf(aq.y, bk.x, s[1][0]); s[1][1] = fmaf(aq.y, bk.y, s[1][1]);
            s[1][2] = fmaf(aq.y, bk.z, s[1][2]); s[1][3] = fmaf(aq.y, bk.w, s[1][3]);
            s[2][0] = fmaf(aq.z, bk.x, s[2][0]); s[2][1] = fmaf(aq.z, bk.y, s[2][1]);
            s[2][2] = fmaf(aq.z, bk.z, s[2][2]); s[2][3] = fmaf(aq.z, bk.w, s[2][3]);
            s[3][0] = fmaf(aq.w, bk.x, s[3][0]); s[3][1] = fmaf(aq.w, bk.y, s[3][1]);
            s[3][2] = fmaf(aq.w, bk.z, s[3][2]); s[3][3] = fmaf(aq.w, bk.w, s[3][3]);
        }

        int qg0 = qt * 64 + ty * 4;
        int kg0 = kt * 64 + tx * 4;
        float km[4];
#pragma unroll
        for (int j = 0; j < 4; j++) km[j] = g_mask[b * T_ + kg0 + j];
#pragma unroll
        for (int i = 0; i < 4; i++)
#pragma unroll
            for (int j = 0; j < 4; j++) {
                float sv = s[i][j] * 0.125f;
                if (km[j] == 0.0f || (kg0 + j) > (qg0 + i)) sv = NEGV;
                s[i][j] = sv;
            }

#pragma unroll
        for (int i = 0; i < 4; ++i) {
            float mt = fmaxf(fmaxf(s[i][0], s[i][1]), fmaxf(s[i][2], s[i][3]));
#pragma unroll
            for (int o = 8; o >= 1; o >>= 1)
                mt = fmaxf(mt, __shfl_xor_sync(0xffffffffu, mt, o));
            float mnew = fmaxf(mrow[i], mt);
            float p0 = __expf(s[i][0] - mnew);
            float p1 = __expf(s[i][1] - mnew);
            float p2 = __expf(s[i][2] - mnew);
            float p3 = __expf(s[i][3] - mnew);
            float ps = p0 + p1 + p2 + p3;
#pragma unroll
            for (int o = 8; o >= 1; o >>= 1)
                ps += __shfl_xor_sync(0xffffffffu, ps, o);
            float alpha = __expf(mrow[i] - mnew);
            lrow[i] = lrow[i] * alpha + ps;
            mrow[i] = mnew;
            O[i][0] *= alpha; O[i][1] *= alpha; O[i][2] *= alpha; O[i][3] *= alpha;
            *reinterpret_cast<float4*>(&Ps[(ty * 4 + i) * 64 + tx * 4]) =
                make_float4(p0, p1, p2, p3);
        }
        __syncthreads();

#pragma unroll 8
        for (int k = 0; k < 64; ++k) {
            float4 v4 = *reinterpret_cast<const float4*>(&Vs[k * 64 + tx * 4]);
#pragma unroll
            for (int i = 0; i < 4; ++i) {
                float p = Ps[(ty * 4 + i) * 64 + k];
                O[i][0] = fmaf(p, v4.x, O[i][0]);
                O[i][1] = fmaf(p, v4.y, O[i][1]);
                O[i][2] = fmaf(p, v4.z, O[i][2]);
                O[i][3] = fmaf(p, v4.w, O[i][3]);
            }
        }
    }

#pragma unroll
    for (int i = 0; i < 4; ++i) {
        float inv = qm[i] / lrow[i];
        float4 o = make_float4(O[i][0] * inv, O[i][1] * inv, O[i][2] * inv, O[i][3] * inv);
        *reinterpret_cast<float4*>(
            &g_O[base + (size_t)(qt * 64 + ty * 4 + i) * U_ + hcol + tx * 4]) = o;
    }
}

// ---------------------------------------------------------------------------
// Residual + LayerNorm (biased variance, eps=1e-8) + affine
// ---------------------------------------------------------------------------
__global__ __launch_bounds__(256) void ln_kernel(
    const float* __restrict__ x, const float* __restrict__ gamma,
    const float* __restrict__ beta, float* __restrict__ out) {
    int row = blockIdx.x;
    int tid = threadIdx.x;
    __shared__ float rsum[8], rsq[8];
    __shared__ float smean, srstd;

    const float4* x4 = reinterpret_cast<const float4*>(x + (size_t)row * U_);
    const float4* o4 = reinterpret_cast<const float4*>(g_O + (size_t)row * U_);
    float4 xv = x4[tid], ov = o4[tid];
    float4 sv = make_float4(xv.x + ov.x, xv.y + ov.y, xv.z + ov.z, xv.w + ov.w);

    float s1 = sv.x + sv.y + sv.z + sv.w;
    float s2 = sv.x * sv.x + sv.y * sv.y + sv.z * sv.z + sv.w * sv.w;
#pragma unroll
    for (int o = 16; o; o >>= 1) {
        s1 += __shfl_xor_sync(0xffffffffu, s1, o);
        s2 += __shfl_xor_sync(0xffffffffu, s2, o);
    }
    if ((tid & 31) == 0) { rsum[tid >> 5] = s1; rsq[tid >> 5] = s2; }
    __syncthreads();
    if (tid == 0) {
        float t1 = 0, t2 = 0;
#pragma unroll
        for (int i = 0; i < 8; i++) { t1 += rsum[i]; t2 += rsq[i]; }
        float mean = t1 * (1.0f / U_);
        float var = t2 * (1.0f / U_) - mean * mean;
        smean = mean;
        srstd = rsqrtf(var + 1e-8f);
    }
    __syncthreads();
    float mean = smean, rstd = srstd;

    const float4* g4 = reinterpret_cast<const float4*>(gamma);
    const float4* b4 = reinterpret_cast<const float4*>(beta);
    float4 gv = g4[tid], bv = b4[tid];
    float4 o;
    o.x = gv.x * ((sv.x - mean) * rstd) + bv.x;
    o.y = gv.y * ((sv.y - mean) * rstd) + bv.y;
    o.z = gv.z * ((sv.z - mean) * rstd) + bv.z;
    o.w = gv.w * ((sv.w - mean) * rstd) + bv.w;
    reinterpret_cast<float4*>(out + (size_t)row * U_)[tid] = o;
}

// ---------------------------------------------------------------------------
extern "C" void kernel_launch(void* const* d_in, const int* in_sizes, int n_in,
                              void* d_out, int out_size) {
    const float* x     = (const float*)d_in[0];
    const float* Wq    = (const float*)d_in[1];
    const float* bq    = (const float*)d_in[2];
    const float* Wk    = (const float*)d_in[3];
    const float* bk    = (const float*)d_in[4];
    const float* Wv    = (const float*)d_in[5];
    const float* bv    = (const float*)d_in[6];
    const float* gamma = (const float*)d_in[7];
    const float* beta  = (const float*)d_in[8];
    float* out = (float*)d_out;

    const int QKV_SMEM = 4 * ABUF * 4;   // 73728 bytes
    cudaFuncSetAttribute(qkv_mma_kernel,
                         cudaFuncAttributeMaxDynamicSharedMemorySize, QKV_SMEM);
    cudaFuncSetAttribute(attn_kernel,
                         cudaFuncAttributeMaxDynamicSharedMemorySize, 65536);

    mask_kernel<<<M_, 256>>>(x);
    wtrans_kernel<<<dim3(32, 32, 3), dim3(32, 8)>>>(Wq, Wk, Wv);
    qkv_mma_kernel<<<dim3(U_ / 128, M_ / 128, 3), 256, QKV_SMEM>>>(x, bq, bk, bv);
    attn_kernel<<<dim3(T_ / 64, B_ * H_), 256, 65536>>>();
    ln_kernel<<<M_, 256>>>(x, gamma, beta, out);
}

// round 5
// speedup vs baseline: 1.8102x; 1.3978x over previous
#include <cuda_runtime.h>
#include <math.h>
#include <stdint.h>

// Problem constants
#define B_  2
#define T_  2048
#define C_  1024
#define U_  1024
#define H_  16
#define DH_ 64
#define M_  4096   // B_*T_

// Scratch (device globals; no allocation allowed)
__device__ float g_Q[(size_t)M_ * U_];
__device__ float g_K[(size_t)M_ * U_];
__device__ float g_V[(size_t)M_ * U_];
__device__ float g_O[(size_t)M_ * U_];
__device__ float g_Wt[3][(size_t)C_ * U_];   // transposed weights [N][K]
__device__ float g_mask[M_];

__device__ __forceinline__ float to_tf32(float x) {
    float r;
    asm("cvt.rna.tf32.f32 %0, %1;" : "=f"(r) : "f"(x));
    return r;
}

#define MMA_TF32(d, a, b) \
    asm volatile("mma.sync.aligned.m16n8k8.row.col.f32.tf32.tf32.f32 " \
        "{%0,%1,%2,%3}, {%4,%5,%6,%7}, {%8,%9}, {%0,%1,%2,%3};" \
        : "+f"((d)[0]), "+f"((d)[1]), "+f"((d)[2]), "+f"((d)[3]) \
        : "r"((a)[0]), "r"((a)[1]), "r"((a)[2]), "r"((a)[3]), \
          "r"((b)[0]), "r"((b)[1]))

// ---------------------------------------------------------------------------
// Key/query mask: sign(|sum_c x[b,t,c]|)
// ---------------------------------------------------------------------------
__global__ __launch_bounds__(256) void mask_kernel(const float* __restrict__ x) {
    int row = blockIdx.x;
    const float4* xr = reinterpret_cast<const float4*>(x + (size_t)row * C_);
    float4 v = xr[threadIdx.x];
    float s = v.x + v.y + v.z + v.w;
    __shared__ float red[8];
#pragma unroll
    for (int o = 16; o; o >>= 1) s += __shfl_xor_sync(0xffffffffu, s, o);
    if ((threadIdx.x & 31) == 0) red[threadIdx.x >> 5] = s;
    __syncthreads();
    if (threadIdx.x == 0) {
        float t = 0.0f;
#pragma unroll
        for (int i = 0; i < 8; i++) t += red[i];
        g_mask[row] = (t != 0.0f) ? 1.0f : 0.0f;
    }
}

// ---------------------------------------------------------------------------
// Transpose W [K,N] -> Wt [N,K] once (3 weights)
// ---------------------------------------------------------------------------
__global__ __launch_bounds__(256) void wtrans_kernel(
    const float* __restrict__ Wq, const float* __restrict__ Wk,
    const float* __restrict__ Wv) {
    __shared__ float t[32][33];
    const float* W = blockIdx.z == 0 ? Wq : blockIdx.z == 1 ? Wk : Wv;
    float* Wt = g_Wt[blockIdx.z];
    int x = blockIdx.x * 32 + threadIdx.x;
    int y0 = blockIdx.y * 32;
#pragma unroll
    for (int j = 0; j < 32; j += 8)
        t[threadIdx.y + j][threadIdx.x] = W[(size_t)(y0 + threadIdx.y + j) * U_ + x];
    __syncthreads();
    int ox = y0 + threadIdx.x;
    int oy0 = blockIdx.x * 32;
#pragma unroll
    for (int j = 0; j < 32; j += 8)
        Wt[(size_t)(oy0 + threadIdx.y + j) * C_ + ox] = t[threadIdx.x][threadIdx.y + j];
}

// ---------------------------------------------------------------------------
// QKV projection via mma.sync tf32. Y = relu(X @ W + b).
// CTA tile 128x128, Kc=32. 8 warps (2x4), warp tile 64x32, m16n8k8.
// ---------------------------------------------------------------------------
#define KC   32
#define NC   (C_ / KC)      // 32 stages
#define SROW 36             // padded row stride (floats)
#define ABUF (128 * SROW)   // 4608 floats per A stage

__global__ __launch_bounds__(256) void qkv_mma_kernel(
    const float* __restrict__ X,
    const float* __restrict__ bq, const float* __restrict__ bk,
    const float* __restrict__ bv) {
    extern __shared__ float sm[];
    int tid = threadIdx.x;
    int wid = tid >> 5, lane = tid & 31;
    int gid = lane >> 2, tig = lane & 3;
    int wm = wid >> 2, wn = wid & 3;      // 2 x 4 warp grid
    int sel = blockIdx.z;
    const float* Wt = g_Wt[sel];
    float* Y = sel == 0 ? g_Q : sel == 1 ? g_K : g_V;
    const float* bias = sel == 0 ? bq : sel == 1 ? bk : bv;
    int n0 = blockIdx.x * 128, m0 = blockIdx.y * 128;

    int arow = tid >> 1, acol = (tid & 1) * 16;
    const float* Ap = X + (size_t)(m0 + arow) * C_ + acol;
    const float* Bp = Wt + (size_t)(n0 + arow) * C_ + acol;

    float acc[4][4][4];
#pragma unroll
    for (int i = 0; i < 4; i++)
#pragma unroll
        for (int j = 0; j < 4; j++)
#pragma unroll
            for (int r = 0; r < 4; r++) acc[i][j][r] = 0.0f;

    float4 ra[4], rb[4];
#pragma unroll
    for (int i = 0; i < 4; i++) {
        ra[i] = *reinterpret_cast<const float4*>(Ap + i * 4);
        rb[i] = *reinterpret_cast<const float4*>(Bp + i * 4);
    }
    {
        float* As = sm;
        float* Bs = sm + 2 * ABUF;
#pragma unroll
        for (int i = 0; i < 4; i++) {
            float4 a = ra[i], b = rb[i];
            int off = arow * SROW + acol + i * 4;
            As[off + 0] = to_tf32(a.x); As[off + 1] = to_tf32(a.y);
            As[off + 2] = to_tf32(a.z); As[off + 3] = to_tf32(a.w);
            Bs[off + 0] = to_tf32(b.x); Bs[off + 1] = to_tf32(b.y);
            Bs[off + 2] = to_tf32(b.z); Bs[off + 3] = to_tf32(b.w);
        }
    }
    __syncthreads();

#pragma unroll 1
    for (int c = 0; c < NC; c++) {
        int b = c & 1;
        if (c + 1 < NC) {
            const float* Apn = Ap + (c + 1) * KC;
            const float* Bpn = Bp + (c + 1) * KC;
#pragma unroll
            for (int i = 0; i < 4; i++) {
                ra[i] = *reinterpret_cast<const float4*>(Apn + i * 4);
                rb[i] = *reinterpret_cast<const float4*>(Bpn + i * 4);
            }
        }

        const float* As = sm + b * ABUF;
        const float* Bs = sm + 2 * ABUF + b * ABUF;
#pragma unroll
        for (int ks = 0; ks < 4; ks++) {
            int k0 = ks * 8 + tig;
            uint32_t af[4][4];
#pragma unroll
            for (int mi = 0; mi < 4; mi++) {
                int r0 = (wm * 64 + mi * 16 + gid) * SROW;
                af[mi][0] = __float_as_uint(As[r0 + k0]);
                af[mi][1] = __float_as_uint(As[r0 + 8 * SROW + k0]);
                af[mi][2] = __float_as_uint(As[r0 + k0 + 4]);
                af[mi][3] = __float_as_uint(As[r0 + 8 * SROW + k0 + 4]);
            }
            uint32_t bf[4][2];
#pragma unroll
            for (int ni = 0; ni < 4; ni++) {
                int nr = (wn * 32 + ni * 8 + gid) * SROW;
                bf[ni][0] = __float_as_uint(Bs[nr + k0]);
                bf[ni][1] = __float_as_uint(Bs[nr + k0 + 4]);
            }
#pragma unroll
            for (int mi = 0; mi < 4; mi++)
#pragma unroll
                for (int ni = 0; ni < 4; ni++)
                    MMA_TF32(acc[mi][ni], af[mi], bf[ni]);
        }

        if (c + 1 < NC) {
            float* Asn = sm + (b ^ 1) * ABUF;
            float* Bsn = sm + 2 * ABUF + (b ^ 1) * ABUF;
#pragma unroll
            for (int i = 0; i < 4; i++) {
                float4 a = ra[i], bb = rb[i];
                int off = arow * SROW + acol + i * 4;
                Asn[off + 0] = to_tf32(a.x); Asn[off + 1] = to_tf32(a.y);
                Asn[off + 2] = to_tf32(a.z); Asn[off + 3] = to_tf32(a.w);
                Bsn[off + 0] = to_tf32(bb.x); Bsn[off + 1] = to_tf32(bb.y);
                Bsn[off + 2] = to_tf32(bb.z); Bsn[off + 3] = to_tf32(bb.w);
            }
        }
        __syncthreads();
    }

#pragma unroll
    for (int mi = 0; mi < 4; mi++) {
        int gr0 = m0 + wm * 64 + mi * 16 + gid;
#pragma unroll
        for (int ni = 0; ni < 4; ni++) {
            int gc = n0 + wn * 32 + ni * 8 + 2 * tig;
            float b0v = bias[gc], b1v = bias[gc + 1];
            float2 o0, o1;
            o0.x = fmaxf(acc[mi][ni][0] + b0v, 0.0f);
            o0.y = fmaxf(acc[mi][ni][1] + b1v, 0.0f);
            o1.x = fmaxf(acc[mi][ni][2] + b0v, 0.0f);
            o1.y = fmaxf(acc[mi][ni][3] + b1v, 0.0f);
            *reinterpret_cast<float2*>(&Y[(size_t)gr0 * U_ + gc]) = o0;
            *reinterpret_cast<float2*>(&Y[(size_t)(gr0 + 8) * U_ + gc]) = o1;
        }
    }
}

// ---------------------------------------------------------------------------
// Flash-attention on mma.sync tf32. BQ=64, BK=64, dh=64. 128 threads, 4 warps,
// each warp owns 16 q-rows. PV computed as O^T = V^T x P^T so Q/K/V all stay
// in natural row-major smem layouts (no transposes).
// Smem: Qs[64][68] Ks[64][68] Vs[64][68] Ps[4][16][68] Al[64] Ll[64] Ms[64]
// ---------------------------------------------------------------------------
#define SP 68
#define ATT_SMEM ((4 * 64 * SP + 3 * 64) * 4)

__global__ __launch_bounds__(128, 3) void attn_mma_kernel() {
    extern __shared__ float smf[];
    float* Qs = smf;                     // [64][SP]
    float* Ks = smf + 64 * SP;           // [64][SP]
    float* Vs = smf + 2 * 64 * SP;       // [64][SP]
    float* Ps = smf + 3 * 64 * SP;       // 4 x [16][SP]
    float* Al = smf + 4 * 64 * SP;       // [64] alpha (per warp 16)
    float* Ll = Al + 64;                 // [64] l
    float* Ms = Ll + 64;                 // [64] key mask

    int tid = threadIdx.x;
    int w = tid >> 5, lane = tid & 31;
    int gid = lane >> 2, tig = lane & 3;
    int qt = (int)gridDim.x - 1 - (int)blockIdx.x;   // big tiles first
    int bh = blockIdx.y;
    int b = bh >> 4, h = bh & 15;
    size_t base = (size_t)b * T_ * U_;
    int hcol = h * DH_;
    int qrow0 = w * 16;

    int r = tid & 63, half = (tid >> 6) * 32;
    const float NEGV = -4294967296.0f;

    // Load Q tile (tf32)
    {
        const float* src = g_Q + base + (size_t)(qt * 64 + r) * U_ + hcol + half;
        float* dst = Qs + r * SP + half;
#pragma unroll
        for (int i = 0; i < 8; i++) {
            float4 v = *reinterpret_cast<const float4*>(src + i * 4);
            v.x = to_tf32(v.x); v.y = to_tf32(v.y);
            v.z = to_tf32(v.z); v.w = to_tf32(v.w);
            *reinterpret_cast<float4*>(dst + i * 4) = v;
        }
    }

    float o[4][2][4];
#pragma unroll
    for (int mi = 0; mi < 4; mi++)
#pragma unroll
        for (int nj = 0; nj < 2; nj++)
#pragma unroll
            for (int rg = 0; rg < 4; rg++) o[mi][nj][rg] = 0.0f;
    float mrow[2] = {-INFINITY, -INFINITY};
    float lrow[2] = {0.0f, 0.0f};

#pragma unroll 1
    for (int kt = 0; kt <= qt; kt++) {
        __syncthreads();
        // Load K, V tiles (tf32) + key mask
        {
            size_t goff = base + (size_t)(kt * 64 + r) * U_ + hcol + half;
            const float* kg = g_K + goff;
            const float* vg = g_V + goff;
            float* kd = Ks + r * SP + half;
            float* vd = Vs + r * SP + half;
#pragma unroll
            for (int i = 0; i < 8; i++) {
                float4 kv = *reinterpret_cast<const float4*>(kg + i * 4);
                kv.x = to_tf32(kv.x); kv.y = to_tf32(kv.y);
                kv.z = to_tf32(kv.z); kv.w = to_tf32(kv.w);
                *reinterpret_cast<float4*>(kd + i * 4) = kv;
                float4 vv = *reinterpret_cast<const float4*>(vg + i * 4);
                vv.x = to_tf32(vv.x); vv.y = to_tf32(vv.y);
                vv.z = to_tf32(vv.z); vv.w = to_tf32(vv.w);
                *reinterpret_cast<float4*>(vd + i * 4) = vv;
            }
            if (tid < 64) Ms[tid] = g_mask[b * T_ + kt * 64 + tid];
        }
        __syncthreads();

        // S = Q K^T
        float s[8][4];
#pragma unroll
        for (int ni = 0; ni < 8; ni++)
#pragma unroll
            for (int rg = 0; rg < 4; rg++) s[ni][rg] = 0.0f;
#pragma unroll
        for (int ks = 0; ks < 8; ks++) {
            int k = ks * 8 + tig;
            uint32_t af[4];
            af[0] = __float_as_uint(Qs[(qrow0 + gid) * SP + k]);
            af[1] = __float_as_uint(Qs[(qrow0 + gid + 8) * SP + k]);
            af[2] = __float_as_uint(Qs[(qrow0 + gid) * SP + k + 4]);
            af[3] = __float_as_uint(Qs[(qrow0 + gid + 8) * SP + k + 4]);
#pragma unroll
            for (int ni = 0; ni < 8; ni++) {
                uint32_t bf[2];
                bf[0] = __float_as_uint(Ks[(ni * 8 + gid) * SP + k]);
                bf[1] = __float_as_uint(Ks[(ni * 8 + gid) * SP + k + 4]);
                MMA_TF32(s[ni], af, bf);
            }
        }

        // scale + masks
        bool diag = (kt == qt);
        int r0 = qrow0 + gid, r1 = r0 + 8;   // local q rows
#pragma unroll
        for (int ni = 0; ni < 8; ni++) {
            int c0 = ni * 8 + 2 * tig, c1 = c0 + 1;
            float km0 = Ms[c0], km1 = Ms[c1];
            float v0 = s[ni][0] * 0.125f;
            float v1 = s[ni][1] * 0.125f;
            float v2 = s[ni][2] * 0.125f;
            float v3 = s[ni][3] * 0.125f;
            if (km0 == 0.0f || (diag && c0 > r0)) v0 = NEGV;
            if (km1 == 0.0f || (diag && c1 > r0)) v1 = NEGV;
            if (km0 == 0.0f || (diag && c0 > r1)) v2 = NEGV;
            if (km1 == 0.0f || (diag && c1 > r1)) v3 = NEGV;
            s[ni][0] = v0; s[ni][1] = v1; s[ni][2] = v2; s[ni][3] = v3;
        }

        // online softmax (rows r0, r1 per lane; reduce across tig lanes)
        float ml0 = -INFINITY, ml1 = -INFINITY;
#pragma unroll
        for (int ni = 0; ni < 8; ni++) {
            ml0 = fmaxf(ml0, fmaxf(s[ni][0], s[ni][1]));
            ml1 = fmaxf(ml1, fmaxf(s[ni][2], s[ni][3]));
        }
        ml0 = fmaxf(ml0, __shfl_xor_sync(0xffffffffu, ml0, 1));
        ml0 = fmaxf(ml0, __shfl_xor_sync(0xffffffffu, ml0, 2));
        ml1 = fmaxf(ml1, __shfl_xor_sync(0xffffffffu, ml1, 1));
        ml1 = fmaxf(ml1, __shfl_xor_sync(0xffffffffu, ml1, 2));
        float mn0 = fmaxf(mrow[0], ml0);
        float mn1 = fmaxf(mrow[1], ml1);
        float al0 = __expf(mrow[0] - mn0);
        float al1 = __expf(mrow[1] - mn1);
        float sum0 = 0.0f, sum1 = 0.0f;
#pragma unroll
        for (int ni = 0; ni < 8; ni++) {
            s[ni][0] = __expf(s[ni][0] - mn0);
            s[ni][1] = __expf(s[ni][1] - mn0);
            s[ni][2] = __expf(s[ni][2] - mn1);
            s[ni][3] = __expf(s[ni][3] - mn1);
            sum0 += s[ni][0] + s[ni][1];
            sum1 += s[ni][2] + s[ni][3];
        }
        sum0 += __shfl_xor_sync(0xffffffffu, sum0, 1);
        sum0 += __shfl_xor_sync(0xffffffffu, sum0, 2);
        sum1 += __shfl_xor_sync(0xffffffffu, sum1, 1);
        sum1 += __shfl_xor_sync(0xffffffffu, sum1, 2);
        lrow[0] = lrow[0] * al0 + sum0;
        lrow[1] = lrow[1] * al1 + sum1;
        mrow[0] = mn0; mrow[1] = mn1;

        if (tig == 0) { Al[w * 16 + gid] = al0; Al[w * 16 + gid + 8] = al1; }
        float* Pw = Ps + w * 16 * SP;
#pragma unroll
        for (int ni = 0; ni < 8; ni++) {
            *reinterpret_cast<float2*>(Pw + gid * SP + ni * 8 + 2 * tig) =
                make_float2(to_tf32(s[ni][0]), to_tf32(s[ni][1]));
            *reinterpret_cast<float2*>(Pw + (gid + 8) * SP + ni * 8 + 2 * tig) =
                make_float2(to_tf32(s[ni][2]), to_tf32(s[ni][3]));
        }
        __syncwarp();

        // rescale O^T columns by alpha of their q
        float ac0 = Al[w * 16 + 2 * tig];
        float ac1 = Al[w * 16 + 2 * tig + 1];
        float ac2 = Al[w * 16 + 8 + 2 * tig];
        float ac3 = Al[w * 16 + 8 + 2 * tig + 1];
#pragma unroll
        for (int mi = 0; mi < 4; mi++) {
            o[mi][0][0] *= ac0; o[mi][0][1] *= ac1;
            o[mi][0][2] *= ac0; o[mi][0][3] *= ac1;
            o[mi][1][0] *= ac2; o[mi][1][1] *= ac3;
            o[mi][1][2] *= ac2; o[mi][1][3] *= ac3;
        }

        // O^T += V^T P^T : A = V (row-major [k][d] -> A[d-rows? no: A[m=d][k]]),
        // B = P ([q][k]); C[d][q]
#pragma unroll
        for (int ks = 0; ks < 8; ks++) {
            int kk = ks * 8 + tig;
            uint32_t bf0[2], bf1[2];
            bf0[0] = __float_as_uint(Pw[gid * SP + kk]);
            bf0[1] = __float_as_uint(Pw[gid * SP + kk + 4]);
            bf1[0] = __float_as_uint(Pw[(gid + 8) * SP + kk]);
            bf1[1] = __float_as_uint(Pw[(gid + 8) * SP + kk + 4]);
#pragma unroll
            for (int mi = 0; mi < 4; mi++) {
                uint32_t af[4];
                af[0] = __float_as_uint(Vs[kk * SP + mi * 16 + gid]);
                af[1] = __float_as_uint(Vs[kk * SP + mi * 16 + gid + 8]);
                af[2] = __float_as_uint(Vs[(kk + 4) * SP + mi * 16 + gid]);
                af[3] = __float_as_uint(Vs[(kk + 4) * SP + mi * 16 + gid + 8]);
                MMA_TF32(o[mi][0], af, bf0);
                MMA_TF32(o[mi][1], af, bf1);
            }
        }
    }

    // Final: normalize by l, query mask, write O^T -> g_O[q][d]
    if (tig == 0) { Ll[w * 16 + gid] = lrow[0]; Ll[w * 16 + gid + 8] = lrow[1]; }
    __syncwarp();
#pragma unroll
    for (int nj = 0; nj < 2; nj++) {
        int qa = nj * 8 + 2 * tig;
        int qb = qa + 1;
        float la = Ll[w * 16 + qa], lb = Ll[w * 16 + qb];
        int qga = qt * 64 + qrow0 + qa;
        int qgb = qga + 1;
        float inva = g_mask[b * T_ + qga] / la;
        float invb = g_mask[b * T_ + qgb] / lb;
        size_t roa = base + (size_t)qga * U_ + hcol;
        size_t rob = base + (size_t)qgb * U_ + hcol;
#pragma unroll
        for (int mi = 0; mi < 4; mi++) {
            int d0 = mi * 16 + gid, d1 = d0 + 8;
            g_O[roa + d0] = o[mi][nj][0] * inva;
            g_O[rob + d0] = o[mi][nj][1] * invb;
            g_O[roa + d1] = o[mi][nj][2] * inva;
            g_O[rob + d1] = o[mi][nj][3] * invb;
        }
    }
}

// ---------------------------------------------------------------------------
// Residual + LayerNorm (biased variance, eps=1e-8) + affine
// ---------------------------------------------------------------------------
__global__ __launch_bounds__(256) void ln_kernel(
    const float* __restrict__ x, const float* __restrict__ gamma,
    const float* __restrict__ beta, float* __restrict__ out) {
    int row = blockIdx.x;
    int tid = threadIdx.x;
    __shared__ float rsum[8], rsq[8];
    __shared__ float smean, srstd;

    const float4* x4 = reinterpret_cast<const float4*>(x + (size_t)row * U_);
    const float4* o4 = reinterpret_cast<const float4*>(g_O + (size_t)row * U_);
    float4 xv = x4[tid], ov = o4[tid];
    float4 sv = make_float4(xv.x + ov.x, xv.y + ov.y, xv.z + ov.z, xv.w + ov.w);

    float s1 = sv.x + sv.y + sv.z + sv.w;
    float s2 = sv.x * sv.x + sv.y * sv.y + sv.z * sv.z + sv.w * sv.w;
#pragma unroll
    for (int o = 16; o; o >>= 1) {
        s1 += __shfl_xor_sync(0xffffffffu, s1, o);
        s2 += __shfl_xor_sync(0xffffffffu, s2, o);
    }
    if ((tid & 31) == 0) { rsum[tid >> 5] = s1; rsq[tid >> 5] = s2; }
    __syncthreads();
    if (tid == 0) {
        float t1 = 0, t2 = 0;
#pragma unroll
        for (int i = 0; i < 8; i++) { t1 += rsum[i]; t2 += rsq[i]; }
        float mean = t1 * (1.0f / U_);
        float var = t2 * (1.0f / U_) - mean * mean;
        smean = mean;
        srstd = rsqrtf(var + 1e-8f);
    }
    __syncthreads();
    float mean = smean, rstd = srstd;

    const float4* g4 = reinterpret_cast<const float4*>(gamma);
    const float4* b4 = reinterpret_cast<const float4*>(beta);
    float4 gv = g4[tid], bv = b4[tid];
    float4 o;
    o.x = gv.x * ((sv.x - mean) * rstd) + bv.x;
    o.y = gv.y * ((sv.y - mean) * rstd) + bv.y;
    o.z = gv.z * ((sv.z - mean) * rstd) + bv.z;
    o.w = gv.w * ((sv.w - mean) * rstd) + bv.w;
    reinterpret_cast<float4*>(out + (size_t)row * U_)[tid] = o;
}

// ---------------------------------------------------------------------------
extern "C" void kernel_launch(void* const* d_in, const int* in_sizes, int n_in,
                              void* d_out, int out_size) {
    const float* x     = (const float*)d_in[0];
    const float* Wq    = (const float*)d_in[1];
    const float* bq    = (const float*)d_in[2];
    const float* Wk    = (const float*)d_in[3];
    const float* bk    = (const float*)d_in[4];
    const float* Wv    = (const float*)d_in[5];
    const float* bv    = (const float*)d_in[6];
    const float* gamma = (const float*)d_in[7];
    const float* beta  = (const float*)d_in[8];
    float* out = (float*)d_out;

    const int QKV_SMEM = 4 * ABUF * 4;   // 73728 bytes
    cudaFuncSetAttribute(qkv_mma_kernel,
                         cudaFuncAttributeMaxDynamicSharedMemorySize, QKV_SMEM);
    cudaFuncSetAttribute(attn_mma_kernel,
                         cudaFuncAttributeMaxDynamicSharedMemorySize, ATT_SMEM);

    mask_kernel<<<M_, 256>>>(x);
    wtrans_kernel<<<dim3(32, 32, 3), dim3(32, 8)>>>(Wq, Wk, Wv);
    qkv_mma_kernel<<<dim3(U_ / 128, M_ / 128, 3), 256, QKV_SMEM>>>(x, bq, bk, bv);
    attn_mma_kernel<<<dim3(T_ / 64, B_ * H_), 128, ATT_SMEM>>>();
    ln_kernel<<<M_, 256>>>(x, gamma, beta, out);
}

// round 6
// speedup vs baseline: 2.1323x; 1.1779x over previous
#include <cuda_runtime.h>
#include <math.h>
#include <stdint.h>

// Problem constants
#define B_  2
#define T_  2048
#define C_  1024
#define U_  1024
#define H_  16
#define DH_ 64
#define M_  4096   // B_*T_

// Scratch (device globals; no allocation allowed)
__device__ float g_Q[(size_t)M_ * U_];
__device__ float g_K[(size_t)M_ * U_];
__device__ float g_V[(size_t)M_ * U_];
__device__ float g_O[(size_t)M_ * U_];
__device__ float g_Wt[3][(size_t)C_ * U_];   // transposed weights [N][K]
__device__ float g_mask[M_];

__device__ __forceinline__ float to_tf32(float x) {
    float r;
    asm("cvt.rna.tf32.f32 %0, %1;" : "=f"(r) : "f"(x));
    return r;
}
__device__ __forceinline__ uint32_t smem_u32(const void* p) {
    uint32_t a;
    asm("{ .reg .u64 t; cvta.to.shared.u64 t, %1; cvt.u32.u64 %0, t; }"
        : "=r"(a) : "l"(p));
    return a;
}
__device__ __forceinline__ void cp_async16(uint32_t dst, const void* src) {
    asm volatile("cp.async.cg.shared.global [%0], [%1], 16;"
                 :: "r"(dst), "l"(src));
}
#define CP_COMMIT() asm volatile("cp.async.commit_group;" ::: "memory")
#define CP_WAIT(n)  asm volatile("cp.async.wait_group %0;" :: "n"(n) : "memory")

#define MMA_TF32(d, a, b) \
    asm volatile("mma.sync.aligned.m16n8k8.row.col.f32.tf32.tf32.f32 " \
        "{%0,%1,%2,%3}, {%4,%5,%6,%7}, {%8,%9}, {%0,%1,%2,%3};" \
        : "+f"((d)[0]), "+f"((d)[1]), "+f"((d)[2]), "+f"((d)[3]) \
        : "r"((a)[0]), "r"((a)[1]), "r"((a)[2]), "r"((a)[3]), \
          "r"((b)[0]), "r"((b)[1]))

// ---------------------------------------------------------------------------
// Key/query mask: sign(|sum_c x[b,t,c]|)
// ---------------------------------------------------------------------------
__global__ __launch_bounds__(256) void mask_kernel(const float* __restrict__ x) {
    int row = blockIdx.x;
    const float4* xr = reinterpret_cast<const float4*>(x + (size_t)row * C_);
    float4 v = xr[threadIdx.x];
    float s = v.x + v.y + v.z + v.w;
    __shared__ float red[8];
#pragma unroll
    for (int o = 16; o; o >>= 1) s += __shfl_xor_sync(0xffffffffu, s, o);
    if ((threadIdx.x & 31) == 0) red[threadIdx.x >> 5] = s;
    __syncthreads();
    if (threadIdx.x == 0) {
        float t = 0.0f;
#pragma unroll
        for (int i = 0; i < 8; i++) t += red[i];
        g_mask[row] = (t != 0.0f) ? 1.0f : 0.0f;
    }
}

// ---------------------------------------------------------------------------
// Transpose W [K,N] -> Wt [N,K] once (3 weights)
// ---------------------------------------------------------------------------
__global__ __launch_bounds__(256) void wtrans_kernel(
    const float* __restrict__ Wq, const float* __restrict__ Wk,
    const float* __restrict__ Wv) {
    __shared__ float t[32][33];
    const float* W = blockIdx.z == 0 ? Wq : blockIdx.z == 1 ? Wk : Wv;
    float* Wt = g_Wt[blockIdx.z];
    int x = blockIdx.x * 32 + threadIdx.x;
    int y0 = blockIdx.y * 32;
#pragma unroll
    for (int j = 0; j < 32; j += 8)
        t[threadIdx.y + j][threadIdx.x] = W[(size_t)(y0 + threadIdx.y + j) * U_ + x];
    __syncthreads();
    int ox = y0 + threadIdx.x;
    int oy0 = blockIdx.x * 32;
#pragma unroll
    for (int j = 0; j < 32; j += 8)
        Wt[(size_t)(oy0 + threadIdx.y + j) * C_ + ox] = t[threadIdx.x][threadIdx.y + j];
}

// ---------------------------------------------------------------------------
// QKV projection via mma.sync tf32 (unchanged from round 4).
// ---------------------------------------------------------------------------
#define KC   32
#define NC   (C_ / KC)      // 32 stages
#define SROW 36             // padded row stride (floats)
#define ABUF (128 * SROW)   // 4608 floats per A stage

__global__ __launch_bounds__(256) void qkv_mma_kernel(
    const float* __restrict__ X,
    const float* __restrict__ bq, const float* __restrict__ bk,
    const float* __restrict__ bv) {
    extern __shared__ float sm[];
    int tid = threadIdx.x;
    int wid = tid >> 5, lane = tid & 31;
    int gid = lane >> 2, tig = lane & 3;
    int wm = wid >> 2, wn = wid & 3;
    int sel = blockIdx.z;
    const float* Wt = g_Wt[sel];
    float* Y = sel == 0 ? g_Q : sel == 1 ? g_K : g_V;
    const float* bias = sel == 0 ? bq : sel == 1 ? bk : bv;
    int n0 = blockIdx.x * 128, m0 = blockIdx.y * 128;

    int arow = tid >> 1, acol = (tid & 1) * 16;
    const float* Ap = X + (size_t)(m0 + arow) * C_ + acol;
    const float* Bp = Wt + (size_t)(n0 + arow) * C_ + acol;

    float acc[4][4][4];
#pragma unroll
    for (int i = 0; i < 4; i++)
#pragma unroll
        for (int j = 0; j < 4; j++)
#pragma unroll
            for (int r = 0; r < 4; r++) acc[i][j][r] = 0.0f;

    float4 ra[4], rb[4];
#pragma unroll
    for (int i = 0; i < 4; i++) {
        ra[i] = *reinterpret_cast<const float4*>(Ap + i * 4);
        rb[i] = *reinterpret_cast<const float4*>(Bp + i * 4);
    }
    {
        float* As = sm;
        float* Bs = sm + 2 * ABUF;
#pragma unroll
        for (int i = 0; i < 4; i++) {
            float4 a = ra[i], b = rb[i];
            int off = arow * SROW + acol + i * 4;
            As[off + 0] = to_tf32(a.x); As[off + 1] = to_tf32(a.y);
            As[off + 2] = to_tf32(a.z); As[off + 3] = to_tf32(a.w);
            Bs[off + 0] = to_tf32(b.x); Bs[off + 1] = to_tf32(b.y);
            Bs[off + 2] = to_tf32(b.z); Bs[off + 3] = to_tf32(b.w);
        }
    }
    __syncthreads();

#pragma unroll 1
    for (int c = 0; c < NC; c++) {
        int b = c & 1;
        if (c + 1 < NC) {
            const float* Apn = Ap + (c + 1) * KC;
            const float* Bpn = Bp + (c + 1) * KC;
#pragma unroll
            for (int i = 0; i < 4; i++) {
                ra[i] = *reinterpret_cast<const float4*>(Apn + i * 4);
                rb[i] = *reinterpret_cast<const float4*>(Bpn + i * 4);
            }
        }

        const float* As = sm + b * ABUF;
        const float* Bs = sm + 2 * ABUF + b * ABUF;
#pragma unroll
        for (int ks = 0; ks < 4; ks++) {
            int k0 = ks * 8 + tig;
            uint32_t af[4][4];
#pragma unroll
            for (int mi = 0; mi < 4; mi++) {
                int r0 = (wm * 64 + mi * 16 + gid) * SROW;
                af[mi][0] = __float_as_uint(As[r0 + k0]);
                af[mi][1] = __float_as_uint(As[r0 + 8 * SROW + k0]);
                af[mi][2] = __float_as_uint(As[r0 + k0 + 4]);
                af[mi][3] = __float_as_uint(As[r0 + 8 * SROW + k0 + 4]);
            }
            uint32_t bf[4][2];
#pragma unroll
            for (int ni = 0; ni < 4; ni++) {
                int nr = (wn * 32 + ni * 8 + gid) * SROW;
                bf[ni][0] = __float_as_uint(Bs[nr + k0]);
                bf[ni][1] = __float_as_uint(Bs[nr + k0 + 4]);
            }
#pragma unroll
            for (int mi = 0; mi < 4; mi++)
#pragma unroll
                for (int ni = 0; ni < 4; ni++)
                    MMA_TF32(acc[mi][ni], af[mi], bf[ni]);
        }

        if (c + 1 < NC) {
            float* Asn = sm + (b ^ 1) * ABUF;
            float* Bsn = sm + 2 * ABUF + (b ^ 1) * ABUF;
#pragma unroll
            for (int i = 0; i < 4; i++) {
                float4 a = ra[i], bb = rb[i];
                int off = arow * SROW + acol + i * 4;
                Asn[off + 0] = to_tf32(a.x); Asn[off + 1] = to_tf32(a.y);
                Asn[off + 2] = to_tf32(a.z); Asn[off + 3] = to_tf32(a.w);
                Bsn[off + 0] = to_tf32(bb.x); Bsn[off + 1] = to_tf32(bb.y);
                Bsn[off + 2] = to_tf32(bb.z); Bsn[off + 3] = to_tf32(bb.w);
            }
        }
        __syncthreads();
    }

#pragma unroll
    for (int mi = 0; mi < 4; mi++) {
        int gr0 = m0 + wm * 64 + mi * 16 + gid;
#pragma unroll
        for (int ni = 0; ni < 4; ni++) {
            int gc = n0 + wn * 32 + ni * 8 + 2 * tig;
            float b0v = bias[gc], b1v = bias[gc + 1];
            float2 o0, o1;
            o0.x = fmaxf(acc[mi][ni][0] + b0v, 0.0f);
            o0.y = fmaxf(acc[mi][ni][1] + b1v, 0.0f);
            o1.x = fmaxf(acc[mi][ni][2] + b0v, 0.0f);
            o1.y = fmaxf(acc[mi][ni][3] + b1v, 0.0f);
            *reinterpret_cast<float2*>(&Y[(size_t)gr0 * U_ + gc]) = o0;
            *reinterpret_cast<float2*>(&Y[(size_t)(gr0 + 8) * U_ + gc]) = o1;
        }
    }
}

// ---------------------------------------------------------------------------
// Flash-attention v2: Q fragments in registers, cp.async double-buffered K/V,
// P via quad shuffles (no smem round-trip), lane-local softmax state.
// BQ=64, BK=64, dh=64. 128 threads, 4 warps x 16 q-rows.
// Smem: Ks[2][64*68] + Vs[2][64*72]  (K stride 68, V stride 72: both
// fragment-gather patterns hit all 32 banks).
// ---------------------------------------------------------------------------
#define SPK 68
#define SPV 72
#define KS_OFF(bb) ((bb) * 64 * SPK)
#define VS_OFF(bb) (2 * 64 * SPK + (bb) * 64 * SPV)
#define ATT_SMEM ((2 * 64 * SPK + 2 * 64 * SPV) * 4)   // 71680 bytes

__global__ __launch_bounds__(128, 3) void attn_mma_kernel() {
    extern __shared__ float smf[];
    uint32_t sb = smem_u32(smf);

    int tid = threadIdx.x;
    int w = tid >> 5, lane = tid & 31;
    int gid = lane >> 2, tig = lane & 3;
    int qt = (int)gridDim.x - 1 - (int)blockIdx.x;   // big tiles first
    int bh = blockIdx.y;
    int b = bh >> 4, h = bh & 15;
    size_t base = (size_t)b * T_ * U_;
    int hcol = h * DH_;
    int qrow0 = w * 16;

    // cp.async tile loader: row = tid>>1, 32-col half = (tid&1)*32
    int lrow = tid >> 1, lcb = (tid & 1) * 32;

    // prologue: issue K/V tile 0
    {
        size_t goff = base + (size_t)(0 * 64 + lrow) * U_ + hcol + lcb;
        uint32_t kd = sb + (uint32_t)(KS_OFF(0) + lrow * SPK + lcb) * 4;
        uint32_t vd = sb + (uint32_t)(VS_OFF(0) + lrow * SPV + lcb) * 4;
#pragma unroll
        for (int i = 0; i < 8; i++) {
            cp_async16(kd + i * 16, g_K + goff + i * 4);
            cp_async16(vd + i * 16, g_V + goff + i * 4);
        }
        CP_COMMIT();
    }

    // Q fragments in registers (one-time)
    uint32_t aq[8][4];
    {
        int qg = qt * 64 + qrow0 + gid;
        const float* q0 = g_Q + base + (size_t)qg * U_ + hcol;
        const float* q1 = q0 + 8 * U_;
#pragma unroll
        for (int ks = 0; ks < 8; ks++) {
            int k = ks * 8 + tig;
            aq[ks][0] = __float_as_uint(to_tf32(q0[k]));
            aq[ks][1] = __float_as_uint(to_tf32(q1[k]));
            aq[ks][2] = __float_as_uint(to_tf32(q0[k + 4]));
            aq[ks][3] = __float_as_uint(to_tf32(q1[k + 4]));
        }
    }

    float o[8][4];
#pragma unroll
    for (int d = 0; d < 8; d++)
#pragma unroll
        for (int r = 0; r < 4; r++) o[d][r] = 0.0f;
    float m0r = -INFINITY, m1r = -INFINITY;
    float l0r = 0.0f, l1r = 0.0f;

    const float NEGV = -4294967296.0f;
    int srcA = (lane & 28) | (tig >> 1);
    int srcB = srcA + 2;
    bool odd = (tig & 1) != 0;

#pragma unroll 1
    for (int kt = 0; kt <= qt; kt++) {
        if (kt < qt) {
            size_t goff = base + (size_t)((kt + 1) * 64 + lrow) * U_ + hcol + lcb;
            int bb = (kt + 1) & 1;
            uint32_t kd = sb + (uint32_t)(KS_OFF(bb) + lrow * SPK + lcb) * 4;
            uint32_t vd = sb + (uint32_t)(VS_OFF(bb) + lrow * SPV + lcb) * 4;
#pragma unroll
            for (int i = 0; i < 8; i++) {
                cp_async16(kd + i * 16, g_K + goff + i * 4);
                cp_async16(vd + i * 16, g_V + goff + i * 4);
            }
            CP_COMMIT();
            CP_WAIT(1);
        } else {
            CP_WAIT(0);
        }
        __syncthreads();

        const float* Ks = smf + KS_OFF(kt & 1);
        const float* Vs = smf + VS_OFF(kt & 1);

        // S = Q K^T
        float s[8][4];
#pragma unroll
        for (int ni = 0; ni < 8; ni++)
#pragma unroll
            for (int r = 0; r < 4; r++) s[ni][r] = 0.0f;
#pragma unroll
        for (int ks = 0; ks < 8; ks++) {
            int k = ks * 8 + tig;
#pragma unroll
            for (int ni = 0; ni < 8; ni++) {
                uint32_t bf[2];
                bf[0] = __float_as_uint(Ks[(ni * 8 + gid) * SPK + k]);
                bf[1] = __float_as_uint(Ks[(ni * 8 + gid) * SPK + k + 4]);
                MMA_TF32(s[ni], aq[ks], bf);
            }
        }

        // scale + key mask + causal
        bool diag = (kt == qt);
        int r0l = qrow0 + gid, r1l = r0l + 8;
        const float* mrowp = g_mask + b * T_ + kt * 64;
#pragma unroll
        for (int ni = 0; ni < 8; ni++) {
            int c0 = ni * 8 + 2 * tig, c1 = c0 + 1;
            float km0 = mrowp[c0], km1 = mrowp[c1];
            float v0 = s[ni][0] * 0.125f;
            float v1 = s[ni][1] * 0.125f;
            float v2 = s[ni][2] * 0.125f;
            float v3 = s[ni][3] * 0.125f;
            if (km0 == 0.0f || (diag && c0 > r0l)) v0 = NEGV;
            if (km1 == 0.0f || (diag && c1 > r0l)) v1 = NEGV;
            if (km0 == 0.0f || (diag && c0 > r1l)) v2 = NEGV;
            if (km1 == 0.0f || (diag && c1 > r1l)) v3 = NEGV;
            s[ni][0] = v0; s[ni][1] = v1; s[ni][2] = v2; s[ni][3] = v3;
        }

        // online softmax (rows r0l, r1l; reduce over tig quad)
        float ml0 = -INFINITY, ml1 = -INFINITY;
#pragma unroll
        for (int ni = 0; ni < 8; ni++) {
            ml0 = fmaxf(ml0, fmaxf(s[ni][0], s[ni][1]));
            ml1 = fmaxf(ml1, fmaxf(s[ni][2], s[ni][3]));
        }
        ml0 = fmaxf(ml0, __shfl_xor_sync(0xffffffffu, ml0, 1));
        ml0 = fmaxf(ml0, __shfl_xor_sync(0xffffffffu, ml0, 2));
        ml1 = fmaxf(ml1, __shfl_xor_sync(0xffffffffu, ml1, 1));
        ml1 = fmaxf(ml1, __shfl_xor_sync(0xffffffffu, ml1, 2));
        float mn0 = fmaxf(m0r, ml0);
        float mn1 = fmaxf(m1r, ml1);
        float al0 = __expf(m0r - mn0);
        float al1 = __expf(m1r - mn1);
        float sum0 = 0.0f, sum1 = 0.0f;
#pragma unroll
        for (int ni = 0; ni < 8; ni++) {
            s[ni][0] = __expf(s[ni][0] - mn0);
            s[ni][1] = __expf(s[ni][1] - mn0);
            s[ni][2] = __expf(s[ni][2] - mn1);
            s[ni][3] = __expf(s[ni][3] - mn1);
            sum0 += s[ni][0] + s[ni][1];
            sum1 += s[ni][2] + s[ni][3];
        }
        sum0 += __shfl_xor_sync(0xffffffffu, sum0, 1);
        sum0 += __shfl_xor_sync(0xffffffffu, sum0, 2);
        sum1 += __shfl_xor_sync(0xffffffffu, sum1, 1);
        sum1 += __shfl_xor_sync(0xffffffffu, sum1, 2);
        l0r = l0r * al0 + sum0;
        l1r = l1r * al1 + sum1;
        m0r = mn0; m1r = mn1;

        // rescale O: c0,c1 belong to row r0l (al0); c2,c3 to row r1l (al1)
#pragma unroll
        for (int d = 0; d < 8; d++) {
            o[d][0] *= al0; o[d][1] *= al0;
            o[d][2] *= al1; o[d][3] *= al1;
        }

        // O += P V : per k-step build P A-fragment via quad shuffles
#pragma unroll
        for (int ks = 0; ks < 8; ks++) {
            float v0 = __shfl_sync(0xffffffffu, s[ks][0], srcA);
            float v1 = __shfl_sync(0xffffffffu, s[ks][1], srcA);
            float v2 = __shfl_sync(0xffffffffu, s[ks][2], srcA);
            float v3 = __shfl_sync(0xffffffffu, s[ks][3], srcA);
            float w0 = __shfl_sync(0xffffffffu, s[ks][0], srcB);
            float w1 = __shfl_sync(0xffffffffu, s[ks][1], srcB);
            float w2 = __shfl_sync(0xffffffffu, s[ks][2], srcB);
            float w3 = __shfl_sync(0xffffffffu, s[ks][3], srcB);
            uint32_t pa[4];
            pa[0] = __float_as_uint(to_tf32(odd ? v1 : v0));
            pa[1] = __float_as_uint(to_tf32(odd ? v3 : v2));
            pa[2] = __float_as_uint(to_tf32(odd ? w1 : w0));
            pa[3] = __float_as_uint(to_tf32(odd ? w3 : w2));
            int kk = ks * 8;
#pragma unroll
            for (int d = 0; d < 8; d++) {
                uint32_t bf[2];
                bf[0] = __float_as_uint(Vs[(kk + tig) * SPV + d * 8 + gid]);
                bf[1] = __float_as_uint(Vs[(kk + tig + 4) * SPV + d * 8 + gid]);
                MMA_TF32(o[d], pa, bf);
            }
        }
        __syncthreads();   // compute done before next issue overwrites buffer
    }

    // epilogue: normalize, query mask, write [q][d]
    {
        int qg0 = qt * 64 + qrow0 + gid;
        int qg1 = qg0 + 8;
        float inv0 = g_mask[b * T_ + qg0] / l0r;
        float inv1 = g_mask[b * T_ + qg1] / l1r;
        float* o0p = g_O + base + (size_t)qg0 * U_ + hcol;
        float* o1p = g_O + base + (size_t)qg1 * U_ + hcol;
#pragma unroll
        for (int d = 0; d < 8; d++) {
            int c = d * 8 + 2 * tig;
            *reinterpret_cast<float2*>(o0p + c) =
                make_float2(o[d][0] * inv0, o[d][1] * inv0);
            *reinterpret_cast<float2*>(o1p + c) =
                make_float2(o[d][2] * inv1, o[d][3] * inv1);
        }
    }
}

// ---------------------------------------------------------------------------
// Residual + LayerNorm (biased variance, eps=1e-8) + affine
// ---------------------------------------------------------------------------
__global__ __launch_bounds__(256) void ln_kernel(
    const float* __restrict__ x, const float* __restrict__ gamma,
    const float* __restrict__ beta, float* __restrict__ out) {
    int row = blockIdx.x;
    int tid = threadIdx.x;
    __shared__ float rsum[8], rsq[8];
    __shared__ float smean, srstd;

    const float4* x4 = reinterpret_cast<const float4*>(x + (size_t)row * U_);
    const float4* o4 = reinterpret_cast<const float4*>(g_O + (size_t)row * U_);
    float4 xv = x4[tid], ov = o4[tid];
    float4 sv = make_float4(xv.x + ov.x, xv.y + ov.y, xv.z + ov.z, xv.w + ov.w);

    float s1 = sv.x + sv.y + sv.z + sv.w;
    float s2 = sv.x * sv.x + sv.y * sv.y + sv.z * sv.z + sv.w * sv.w;
#pragma unroll
    for (int o = 16; o; o >>= 1) {
        s1 += __shfl_xor_sync(0xffffffffu, s1, o);
        s2 += __shfl_xor_sync(0xffffffffu, s2, o);
    }
    if ((tid & 31) == 0) { rsum[tid >> 5] = s1; rsq[tid >> 5] = s2; }
    __syncthreads();
    if (tid == 0) {
        float t1 = 0, t2 = 0;
#pragma unroll
        for (int i = 0; i < 8; i++) { t1 += rsum[i]; t2 += rsq[i]; }
        float mean = t1 * (1.0f / U_);
        float var = t2 * (1.0f / U_) - mean * mean;
        smean = mean;
        srstd = rsqrtf(var + 1e-8f);
    }
    __syncthreads();
    float mean = smean, rstd = srstd;

    const float4* g4 = reinterpret_cast<const float4*>(gamma);
    const float4* b4 = reinterpret_cast<const float4*>(beta);
    float4 gv = g4[tid], bv = b4[tid];
    float4 o;
    o.x = gv.x * ((sv.x - mean) * rstd) + bv.x;
    o.y = gv.y * ((sv.y - mean) * rstd) + bv.y;
    o.z = gv.z * ((sv.z - mean) * rstd) + bv.z;
    o.w = gv.w * ((sv.w - mean) * rstd) + bv.w;
    reinterpret_cast<float4*>(out + (size_t)row * U_)[tid] = o;
}

// ---------------------------------------------------------------------------
extern "C" void kernel_launch(void* const* d_in, const int* in_sizes, int n_in,
                              void* d_out, int out_size) {
    const float* x     = (const float*)d_in[0];
    const float* Wq    = (const float*)d_in[1];
    const float* bq    = (const float*)d_in[2];
    const float* Wk    = (const float*)d_in[3];
    const float* bk    = (const float*)d_in[4];
    const float* Wv    = (const float*)d_in[5];
    const float* bv    = (const float*)d_in[6];
    const float* gamma = (const float*)d_in[7];
    const float* beta  = (const float*)d_in[8];
    float* out = (float*)d_out;

    const int QKV_SMEM = 4 * ABUF * 4;   // 73728 bytes
    cudaFuncSetAttribute(qkv_mma_kernel,
                         cudaFuncAttributeMaxDynamicSharedMemorySize, QKV_SMEM);
    cudaFuncSetAttribute(attn_mma_kernel,
                         cudaFuncAttributeMaxDynamicSharedMemorySize, ATT_SMEM);

    mask_kernel<<<M_, 256>>>(x);
    wtrans_kernel<<<dim3(32, 32, 3), dim3(32, 8)>>>(Wq, Wk, Wv);
    qkv_mma_kernel<<<dim3(U_ / 128, M_ / 128, 3), 256, QKV_SMEM>>>(x, bq, bk, bv);
    attn_mma_kernel<<<dim3(T_ / 64, B_ * H_), 128, ATT_SMEM>>>();
    ln_kernel<<<M_, 256>>>(x, gamma, beta, out);
}

// round 7
// speedup vs baseline: 2.2945x; 1.0761x over previous
#include <cuda_runtime.h>
#include <math.h>
#include <stdint.h>

// Problem constants
#define B_  2
#define T_  2048
#define C_  1024
#define U_  1024
#define H_  16
#define DH_ 64
#define M_  4096   // B_*T_

// Scratch (device globals; no allocation allowed)
__device__ float g_Q[(size_t)M_ * U_];    // d-dim permuted within groups of 8
__device__ float g_K[(size_t)M_ * U_];    // d-dim permuted within groups of 8
__device__ float g_V[(size_t)M_ * U_];    // natural layout
__device__ float g_O[(size_t)M_ * U_];
__device__ float g_Xp[(size_t)M_ * C_];   // X with k-dim permuted within 8s
__device__ float g_Wt[3][(size_t)C_ * U_];// W^T [N][K], K-dim permuted within 8s
__device__ float g_mask[M_];

__device__ __forceinline__ float to_tf32(float x) {
    float r;
    asm("cvt.rna.tf32.f32 %0, %1;" : "=f"(r) : "f"(x));
    return r;
}
__device__ __forceinline__ uint32_t smem_u32(const void* p) {
    uint32_t a;
    asm("{ .reg .u64 t; cvta.to.shared.u64 t, %1; cvt.u32.u64 %0, t; }"
        : "=r"(a) : "l"(p));
    return a;
}
__device__ __forceinline__ void cp_async16(uint32_t dst, const void* src) {
    asm volatile("cp.async.cg.shared.global [%0], [%1], 16;"
                 :: "r"(dst), "l"(src));
}
#define CP_COMMIT() asm volatile("cp.async.commit_group;" ::: "memory")
#define CP_WAIT(n)  asm volatile("cp.async.wait_group %0;" :: "n"(n) : "memory")

#define MMA_TF32(d, a, b) \
    asm volatile("mma.sync.aligned.m16n8k8.row.col.f32.tf32.tf32.f32 " \
        "{%0,%1,%2,%3}, {%4,%5,%6,%7}, {%8,%9}, {%0,%1,%2,%3};" \
        : "+f"((d)[0]), "+f"((d)[1]), "+f"((d)[2]), "+f"((d)[3]) \
        : "r"((a)[0]), "r"((a)[1]), "r"((a)[2]), "r"((a)[3]), \
          "r"((b)[0]), "r"((b)[1]))

// within-8 rotation: logical k stored at P8(k)
__device__ __forceinline__ int P8(int k) {
    return (k & ~7) | ((k & 3) << 1) | ((k >> 2) & 1);
}

// ---------------------------------------------------------------------------
// Key/query mask: sign(|sum_c x[b,t,c]|)
// ---------------------------------------------------------------------------
__global__ __launch_bounds__(256) void mask_kernel(const float* __restrict__ x) {
    int row = blockIdx.x;
    const float4* xr = reinterpret_cast<const float4*>(x + (size_t)row * C_);
    float4 v = xr[threadIdx.x];
    float s = v.x + v.y + v.z + v.w;
    __shared__ float red[8];
#pragma unroll
    for (int o = 16; o; o >>= 1) s += __shfl_xor_sync(0xffffffffu, s, o);
    if ((threadIdx.x & 31) == 0) red[threadIdx.x >> 5] = s;
    __syncthreads();
    if (threadIdx.x == 0) {
        float t = 0.0f;
#pragma unroll
        for (int i = 0; i < 8; i++) t += red[i];
        g_mask[row] = (t != 0.0f) ? 1.0f : 0.0f;
    }
}

// ---------------------------------------------------------------------------
// X -> Xp with within-8 column permutation. out[8g+{0..7}] = in{0,4,1,5,2,6,3,7}
// ---------------------------------------------------------------------------
__global__ __launch_bounds__(128) void permx_kernel(const float* __restrict__ x) {
    size_t ro = (size_t)blockIdx.x * C_ + threadIdx.x * 8;
    float4 a = *reinterpret_cast<const float4*>(x + ro);
    float4 b = *reinterpret_cast<const float4*>(x + ro + 4);
    float4 o0 = make_float4(a.x, b.x, a.y, b.y);
    float4 o1 = make_float4(a.z, b.z, a.w, b.w);
    *reinterpret_cast<float4*>(g_Xp + ro) = o0;
    *reinterpret_cast<float4*>(g_Xp + ro + 4) = o1;
}

// ---------------------------------------------------------------------------
// Transpose W [K,N] -> Wt [N,K] with K permuted within 8s
// ---------------------------------------------------------------------------
__global__ __launch_bounds__(256) void wtrans_kernel(
    const float* __restrict__ Wq, const float* __restrict__ Wk,
    const float* __restrict__ Wv) {
    __shared__ float t[32][33];
    const float* W = blockIdx.z == 0 ? Wq : blockIdx.z == 1 ? Wk : Wv;
    float* Wt = g_Wt[blockIdx.z];
    int x = blockIdx.x * 32 + threadIdx.x;
    int y0 = blockIdx.y * 32;
#pragma unroll
    for (int j = 0; j < 32; j += 8)
        t[threadIdx.y + j][threadIdx.x] = W[(size_t)(y0 + threadIdx.y + j) * U_ + x];
    __syncthreads();
    int ox = P8(y0 + threadIdx.x);       // permuted k position
    int oy0 = blockIdx.x * 32;
#pragma unroll
    for (int j = 0; j < 32; j += 8)
        Wt[(size_t)(oy0 + threadIdx.y + j) * C_ + ox] = t[threadIdx.x][threadIdx.y + j];
}

// ---------------------------------------------------------------------------
// QKV projection via mma.sync tf32, cp.async double-buffered, v2 fragments.
// CTA 128x128, Kc=32, 8 warps (2x4), warp tile 64x32.
// Smem: per stage A[128][40] + B[128][40]; 2 stages = 81920 B.
// ---------------------------------------------------------------------------
#define KC    32
#define NCH   (C_ / KC)     // 32 chunks
#define QROW  40            // padded stride
#define STG   (2 * 128 * QROW)              // floats per stage (A+B)
#define QKV_SMEM (2 * STG * 4)              // 81920 bytes

__global__ __launch_bounds__(256, 2) void qkv_mma_kernel(
    const float* __restrict__ bq, const float* __restrict__ bk,
    const float* __restrict__ bv) {
    extern __shared__ float sm[];
    uint32_t sb = smem_u32(sm);
    int tid = threadIdx.x;
    int wid = tid >> 5, lane = tid & 31;
    int gid = lane >> 2, tig = lane & 3;
    int wm = wid >> 2, wn = wid & 3;
    int sel = blockIdx.z;
    const float* Wt = g_Wt[sel];
    float* Y = sel == 0 ? g_Q : sel == 1 ? g_K : g_V;
    const float* bias = sel == 0 ? bq : sel == 1 ? bk : bv;
    int n0 = blockIdx.x * 128, m0 = blockIdx.y * 128;

    int lrow = tid >> 1, lcb = (tid & 1) * 16;
    const float* Ap = g_Xp + (size_t)(m0 + lrow) * C_ + lcb;
    const float* Bp = Wt + (size_t)(n0 + lrow) * C_ + lcb;
    uint32_t adst = sb + (uint32_t)(lrow * QROW + lcb) * 4;
    uint32_t bdst = adst + 128 * QROW * 4;

    float acc[4][4][4];
#pragma unroll
    for (int i = 0; i < 4; i++)
#pragma unroll
        for (int j = 0; j < 4; j++)
#pragma unroll
            for (int r = 0; r < 4; r++) acc[i][j][r] = 0.0f;

    // prologue: stage 0
#pragma unroll
    for (int i = 0; i < 4; i++) {
        cp_async16(adst + i * 16, Ap + i * 4);
        cp_async16(bdst + i * 16, Bp + i * 4);
    }
    CP_COMMIT();

#pragma unroll 1
    for (int c = 0; c < NCH; c++) {
        if (c + 1 < NCH) {
            uint32_t so = ((c + 1) & 1) * STG * 4;
#pragma unroll
            for (int i = 0; i < 4; i++) {
                cp_async16(adst + so + i * 16, Ap + (c + 1) * KC + i * 4);
                cp_async16(bdst + so + i * 16, Bp + (c + 1) * KC + i * 4);
            }
            CP_COMMIT();
            CP_WAIT(1);
        } else {
            CP_WAIT(0);
        }
        __syncthreads();

        const float* As = sm + (c & 1) * STG;
        const float* Bs = As + 128 * QROW;
#pragma unroll
        for (int ks = 0; ks < 4; ks++) {
            int kp = ks * 8 + 2 * tig;
            uint32_t af[4][4];
#pragma unroll
            for (int mi = 0; mi < 4; mi++) {
                int r0 = (wm * 64 + mi * 16 + gid) * QROW;
                float2 lo = *reinterpret_cast<const float2*>(&As[r0 + kp]);
                float2 hi = *reinterpret_cast<const float2*>(&As[r0 + 8 * QROW + kp]);
                af[mi][0] = __float_as_uint(lo.x);
                af[mi][2] = __float_as_uint(lo.y);
                af[mi][1] = __float_as_uint(hi.x);
                af[mi][3] = __float_as_uint(hi.y);
            }
            uint32_t bf[4][2];
#pragma unroll
            for (int ni = 0; ni < 4; ni++) {
                int nr = (wn * 32 + ni * 8 + gid) * QROW;
                float2 bb = *reinterpret_cast<const float2*>(&Bs[nr + kp]);
                bf[ni][0] = __float_as_uint(bb.x);
                bf[ni][1] = __float_as_uint(bb.y);
            }
#pragma unroll
            for (int mi = 0; mi < 4; mi++)
#pragma unroll
                for (int ni = 0; ni < 4; ni++)
                    MMA_TF32(acc[mi][ni], af[mi], bf[ni]);
        }
        __syncthreads();
    }

    // Epilogue: bias + relu. Q/K stored with d-permutation, V natural.
#pragma unroll
    for (int mi = 0; mi < 4; mi++) {
        int gr0 = m0 + wm * 64 + mi * 16 + gid;
#pragma unroll
        for (int ni = 0; ni < 4; ni++) {
            int gc = n0 + wn * 32 + ni * 8 + 2 * tig;
            float b0v = bias[gc], b1v = bias[gc + 1];
            float v00 = fmaxf(acc[mi][ni][0] + b0v, 0.0f);
            float v01 = fmaxf(acc[mi][ni][1] + b1v, 0.0f);
            float v10 = fmaxf(acc[mi][ni][2] + b0v, 0.0f);
            float v11 = fmaxf(acc[mi][ni][3] + b1v, 0.0f);
            if (sel == 2) {
                *reinterpret_cast<float2*>(&Y[(size_t)gr0 * U_ + gc]) =
                    make_float2(v00, v01);
                *reinterpret_cast<float2*>(&Y[(size_t)(gr0 + 8) * U_ + gc]) =
                    make_float2(v10, v11);
            } else {
                int pc0 = P8(gc), pc1 = P8(gc + 1);
                Y[(size_t)gr0 * U_ + pc0] = v00;
                Y[(size_t)gr0 * U_ + pc1] = v01;
                Y[(size_t)(gr0 + 8) * U_ + pc0] = v10;
                Y[(size_t)(gr0 + 8) * U_ + pc1] = v11;
            }
        }
    }
}

// ---------------------------------------------------------------------------
// Flash-attention: Q frags in regs (v2 loads on permuted g_Q), cp.async K/V +
// mask, v2 LDS for K fragments, P via quad shuffles, lane-local softmax.
// BQ=64, BK=64, dh=64, 128 threads, 4 warps x 16 q-rows.
// ---------------------------------------------------------------------------
#define SPK 72
#define SPV 72
#define KS_OFF(bb) ((bb) * 64 * SPK)
#define VS_OFF(bb) (2 * 64 * SPK + (bb) * 64 * SPV)
#define MS_OFF(bb) (2 * 64 * SPK + 2 * 64 * SPV + (bb) * 64)
#define ATT_SMEM ((2 * 64 * SPK + 2 * 64 * SPV + 2 * 64) * 4)   // 74240 B

__global__ __launch_bounds__(128, 3) void attn_mma_kernel() {
    extern __shared__ float smf[];
    uint32_t sb = smem_u32(smf);

    int tid = threadIdx.x;
    int lane = tid & 31;
    int gid = lane >> 2, tig = lane & 3;
    int qt = (int)gridDim.x - 1 - (int)blockIdx.x;   // big tiles first
    int bh = blockIdx.y;
    int b = bh >> 4, h = bh & 15;
    size_t base = (size_t)b * T_ * U_;
    int hcol = h * DH_;
    int qrow0 = (tid >> 5) * 16;

    int lrow = tid >> 1, lcb = (tid & 1) * 32;

    // prologue: issue K/V tile 0 + mask
    {
        size_t goff = base + (size_t)lrow * U_ + hcol + lcb;
        uint32_t kd = sb + (uint32_t)(KS_OFF(0) + lrow * SPK + lcb) * 4;
        uint32_t vd = sb + (uint32_t)(VS_OFF(0) + lrow * SPV + lcb) * 4;
#pragma unroll
        for (int i = 0; i < 8; i++) {
            cp_async16(kd + i * 16, g_K + goff + i * 4);
            cp_async16(vd + i * 16, g_V + goff + i * 4);
        }
        if (tid < 16)
            cp_async16(sb + (uint32_t)(MS_OFF(0) + tid * 4) * 4,
                       g_mask + b * T_ + tid * 4);
        CP_COMMIT();
    }

    // Q fragments (permuted g_Q -> v2 global loads)
    uint32_t aq[8][4];
    {
        int qg = qt * 64 + qrow0 + gid;
        const float* q0 = g_Q + base + (size_t)qg * U_ + hcol;
        const float* q1 = q0 + 8 * U_;
#pragma unroll
        for (int ks = 0; ks < 8; ks++) {
            int kp = ks * 8 + 2 * tig;
            float2 v0 = *reinterpret_cast<const float2*>(q0 + kp);
            float2 v1 = *reinterpret_cast<const float2*>(q1 + kp);
            aq[ks][0] = __float_as_uint(to_tf32(v0.x));
            aq[ks][2] = __float_as_uint(to_tf32(v0.y));
            aq[ks][1] = __float_as_uint(to_tf32(v1.x));
            aq[ks][3] = __float_as_uint(to_tf32(v1.y));
        }
    }

    float o[8][4];
#pragma unroll
    for (int d = 0; d < 8; d++)
#pragma unroll
        for (int r = 0; r < 4; r++) o[d][r] = 0.0f;
    float m0r = -INFINITY, m1r = -INFINITY;
    float l0r = 0.0f, l1r = 0.0f;

    const float NEGV = -4294967296.0f;
    int srcA = (lane & 28) | (tig >> 1);
    int srcB = srcA + 2;
    bool odd = (tig & 1) != 0;

#pragma unroll 1
    for (int kt = 0; kt <= qt; kt++) {
        if (kt < qt) {
            size_t goff = base + (size_t)((kt + 1) * 64 + lrow) * U_ + hcol + lcb;
            int bb = (kt + 1) & 1;
            uint32_t kd = sb + (uint32_t)(KS_OFF(bb) + lrow * SPK + lcb) * 4;
            uint32_t vd = sb + (uint32_t)(VS_OFF(bb) + lrow * SPV + lcb) * 4;
#pragma unroll
            for (int i = 0; i < 8; i++) {
                cp_async16(kd + i * 16, g_K + goff + i * 4);
                cp_async16(vd + i * 16, g_V + goff + i * 4);
            }
            if (tid < 16)
                cp_async16(sb + (uint32_t)(MS_OFF(bb) + tid * 4) * 4,
                           g_mask + b * T_ + (kt + 1) * 64 + tid * 4);
            CP_COMMIT();
            CP_WAIT(1);
        } else {
            CP_WAIT(0);
        }
        __syncthreads();

        const float* Ks = smf + KS_OFF(kt & 1);
        const float* Vs = smf + VS_OFF(kt & 1);
        const float* Ms = smf + MS_OFF(kt & 1);

        // S = Q K^T (v2 K fragment loads on permuted d)
        float s[8][4];
#pragma unroll
        for (int ni = 0; ni < 8; ni++)
#pragma unroll
            for (int r = 0; r < 4; r++) s[ni][r] = 0.0f;
#pragma unroll
        for (int ks = 0; ks < 8; ks++) {
            int kp = ks * 8 + 2 * tig;
#pragma unroll
            for (int ni = 0; ni < 8; ni++) {
                float2 kb = *reinterpret_cast<const float2*>(
                    &Ks[(ni * 8 + gid) * SPK + kp]);
                uint32_t bf[2];
                bf[0] = __float_as_uint(kb.x);
                bf[1] = __float_as_uint(kb.y);
                MMA_TF32(s[ni], aq[ks], bf);
            }
        }

        // scale + key mask + causal
        bool diag = (kt == qt);
        int r0l = qrow0 + gid, r1l = r0l + 8;
#pragma unroll
        for (int ni = 0; ni < 8; ni++) {
            int c0 = ni * 8 + 2 * tig, c1 = c0 + 1;
            float2 km = *reinterpret_cast<const float2*>(&Ms[c0]);
            float v0 = s[ni][0] * 0.125f;
            float v1 = s[ni][1] * 0.125f;
            float v2 = s[ni][2] * 0.125f;
            float v3 = s[ni][3] * 0.125f;
            if (km.x == 0.0f || (diag && c0 > r0l)) v0 = NEGV;
            if (km.y == 0.0f || (diag && c1 > r0l)) v1 = NEGV;
            if (km.x == 0.0f || (diag && c0 > r1l)) v2 = NEGV;
            if (km.y == 0.0f || (diag && c1 > r1l)) v3 = NEGV;
            s[ni][0] = v0; s[ni][1] = v1; s[ni][2] = v2; s[ni][3] = v3;
        }

        // online softmax
        float ml0 = -INFINITY, ml1 = -INFINITY;
#pragma unroll
        for (int ni = 0; ni < 8; ni++) {
            ml0 = fmaxf(ml0, fmaxf(s[ni][0], s[ni][1]));
            ml1 = fmaxf(ml1, fmaxf(s[ni][2], s[ni][3]));
        }
        ml0 = fmaxf(ml0, __shfl_xor_sync(0xffffffffu, ml0, 1));
        ml0 = fmaxf(ml0, __shfl_xor_sync(0xffffffffu, ml0, 2));
        ml1 = fmaxf(ml1, __shfl_xor_sync(0xffffffffu, ml1, 1));
        ml1 = fmaxf(ml1, __shfl_xor_sync(0xffffffffu, ml1, 2));
        float mn0 = fmaxf(m0r, ml0);
        float mn1 = fmaxf(m1r, ml1);
        float al0 = __expf(m0r - mn0);
        float al1 = __expf(m1r - mn1);
        float sum0 = 0.0f, sum1 = 0.0f;
#pragma unroll
        for (int ni = 0; ni < 8; ni++) {
            s[ni][0] = __expf(s[ni][0] - mn0);
            s[ni][1] = __expf(s[ni][1] - mn0);
            s[ni][2] = __expf(s[ni][2] - mn1);
            s[ni][3] = __expf(s[ni][3] - mn1);
            sum0 += s[ni][0] + s[ni][1];
            sum1 += s[ni][2] + s[ni][3];
        }
        sum0 += __shfl_xor_sync(0xffffffffu, sum0, 1);
        sum0 += __shfl_xor_sync(0xffffffffu, sum0, 2);
        sum1 += __shfl_xor_sync(0xffffffffu, sum1, 1);
        sum1 += __shfl_xor_sync(0xffffffffu, sum1, 2);
        l0r = l0r * al0 + sum0;
        l1r = l1r * al1 + sum1;
        m0r = mn0; m1r = mn1;

#pragma unroll
        for (int d = 0; d < 8; d++) {
            o[d][0] *= al0; o[d][1] *= al0;
            o[d][2] *= al1; o[d][3] *= al1;
        }

        // O += P V via quad shuffles
#pragma unroll
        for (int ks = 0; ks < 8; ks++) {
            float v0 = __shfl_sync(0xffffffffu, s[ks][0], srcA);
            float v1 = __shfl_sync(0xffffffffu, s[ks][1], srcA);
            float v2 = __shfl_sync(0xffffffffu, s[ks][2], srcA);
            float v3 = __shfl_sync(0xffffffffu, s[ks][3], srcA);
            float w0 = __shfl_sync(0xffffffffu, s[ks][0], srcB);
            float w1 = __shfl_sync(0xffffffffu, s[ks][1], srcB);
            float w2 = __shfl_sync(0xffffffffu, s[ks][2], srcB);
            float w3 = __shfl_sync(0xffffffffu, s[ks][3], srcB);
            uint32_t pa[4];
            pa[0] = __float_as_uint(to_tf32(odd ? v1 : v0));
            pa[1] = __float_as_uint(to_tf32(odd ? v3 : v2));
            pa[2] = __float_as_uint(to_tf32(odd ? w1 : w0));
            pa[3] = __float_as_uint(to_tf32(odd ? w3 : w2));
            int kk = ks * 8;
#pragma unroll
            for (int d = 0; d < 8; d++) {
                uint32_t bf[2];
                bf[0] = __float_as_uint(Vs[(kk + tig) * SPV + d * 8 + gid]);
                bf[1] = __float_as_uint(Vs[(kk + tig + 4) * SPV + d * 8 + gid]);
                MMA_TF32(o[d], pa, bf);
            }
        }
        __syncthreads();
    }

    // epilogue
    {
        int qg0 = qt * 64 + qrow0 + gid;
        int qg1 = qg0 + 8;
        float inv0 = g_mask[b * T_ + qg0] / l0r;
        float inv1 = g_mask[b * T_ + qg1] / l1r;
        float* o0p = g_O + base + (size_t)qg0 * U_ + hcol;
        float* o1p = g_O + base + (size_t)qg1 * U_ + hcol;
#pragma unroll
        for (int d = 0; d < 8; d++) {
            int c = d * 8 + 2 * tig;
            *reinterpret_cast<float2*>(o0p + c) =
                make_float2(o[d][0] * inv0, o[d][1] * inv0);
            *reinterpret_cast<float2*>(o1p + c) =
                make_float2(o[d][2] * inv1, o[d][3] * inv1);
        }
    }
}

// ---------------------------------------------------------------------------
// Residual + LayerNorm (biased variance, eps=1e-8) + affine
// ---------------------------------------------------------------------------
__global__ __launch_bounds__(256) void ln_kernel(
    const float* __restrict__ x, const float* __restrict__ gamma,
    const float* __restrict__ beta, float* __restrict__ out) {
    int row = blockIdx.x;
    int tid = threadIdx.x;
    __shared__ float rsum[8], rsq[8];
    __shared__ float smean, srstd;

    const float4* x4 = reinterpret_cast<const float4*>(x + (size_t)row * U_);
    const float4* o4 = reinterpret_cast<const float4*>(g_O + (size_t)row * U_);
    float4 xv = x4[tid], ov = o4[tid];
    float4 sv = make_float4(xv.x + ov.x, xv.y + ov.y, xv.z + ov.z, xv.w + ov.w);

    float s1 = sv.x + sv.y + sv.z + sv.w;
    float s2 = sv.x * sv.x + sv.y * sv.y + sv.z * sv.z + sv.w * sv.w;
#pragma unroll
    for (int o = 16; o; o >>= 1) {
        s1 += __shfl_xor_sync(0xffffffffu, s1, o);
        s2 += __shfl_xor_sync(0xffffffffu, s2, o);
    }
    if ((tid & 31) == 0) { rsum[tid >> 5] = s1; rsq[tid >> 5] = s2; }
    __syncthreads();
    if (tid == 0) {
        float t1 = 0, t2 = 0;
#pragma unroll
        for (int i = 0; i < 8; i++) { t1 += rsum[i]; t2 += rsq[i]; }
        float mean = t1 * (1.0f / U_);
        float var = t2 * (1.0f / U_) - mean * mean;
        smean = mean;
        srstd = rsqrtf(var + 1e-8f);
    }
    __syncthreads();
    float mean = smean, rstd = srstd;

    const float4* g4 = reinterpret_cast<const float4*>(gamma);
    const float4* b4 = reinterpret_cast<const float4*>(beta);
    float4 gv = g4[tid], bv = b4[tid];
    float4 o;
    o.x = gv.x * ((sv.x - mean) * rstd) + bv.x;
    o.y = gv.y * ((sv.y - mean) * rstd) + bv.y;
    o.z = gv.z * ((sv.z - mean) * rstd) + bv.z;
    o.w = gv.w * ((sv.w - mean) * rstd) + bv.w;
    reinterpret_cast<float4*>(out + (size_t)row * U_)[tid] = o;
}

// ---------------------------------------------------------------------------
extern "C" void kernel_launch(void* const* d_in, const int* in_sizes, int n_in,
                              void* d_out, int out_size) {
    const float* x     = (const float*)d_in[0];
    const float* Wq    = (const float*)d_in[1];
    const float* bq    = (const float*)d_in[2];
    const float* Wk    = (const float*)d_in[3];
    const float* bk    = (const float*)d_in[4];
    const float* Wv    = (const float*)d_in[5];
    const float* bv    = (const float*)d_in[6];
    const float* gamma = (const float*)d_in[7];
    const float* beta  = (const float*)d_in[8];
    float* out = (float*)d_out;

    cudaFuncSetAttribute(qkv_mma_kernel,
                         cudaFuncAttributeMaxDynamicSharedMemorySize, QKV_SMEM);
    cudaFuncSetAttribute(attn_mma_kernel,
                         cudaFuncAttributeMaxDynamicSharedMemorySize, ATT_SMEM);

    mask_kernel<<<M_, 256>>>(x);
    permx_kernel<<<M_, 128>>>(x);
    wtrans_kernel<<<dim3(32, 32, 3), dim3(32, 8)>>>(Wq, Wk, Wv);
    qkv_mma_kernel<<<dim3(U_ / 128, M_ / 128, 3), 256, QKV_SMEM>>>(bq, bk, bv);
    attn_mma_kernel<<<dim3(T_ / 64, B_ * H_), 128, ATT_SMEM>>>();
    ln_kernel<<<M_, 256>>>(x, gamma, beta, out);
}

// round 8
// speedup vs baseline: 4.8632x; 2.1195x over previous
#include <cuda_runtime.h>
#include <cuda_fp16.h>
#include <math.h>
#include <stdint.h>

// Problem constants
#define B_  2
#define T_  2048
#define C_  1024
#define U_  1024
#define H_  16
#define DH_ 64
#define M_  4096   // B_*T_

// Scratch (device globals; no allocation allowed)
__device__ __half g_Xh[(size_t)M_ * C_];        // x in fp16
__device__ __half g_Wth[3][(size_t)C_ * U_];    // W^T [N][K] fp16
__device__ __half g_Qh[(size_t)M_ * U_];        // Q fp16 [t][U]
__device__ __half g_Kh[(size_t)M_ * U_];        // K fp16 [t][U]
__device__ __half g_Vth[(size_t)M_ * U_];       // V fp16 transposed: [(b*H+h)*64+d][T]
__device__ float  g_O[(size_t)M_ * U_];
__device__ float  g_mask[M_];

__device__ __forceinline__ uint32_t smem_u32(const void* p) {
    uint32_t a;
    asm("{ .reg .u64 t; cvta.to.shared.u64 t, %1; cvt.u32.u64 %0, t; }"
        : "=r"(a) : "l"(p));
    return a;
}
__device__ __forceinline__ void cp_async16(uint32_t dst, const void* src) {
    asm volatile("cp.async.cg.shared.global [%0], [%1], 16;"
                 :: "r"(dst), "l"(src));
}
#define CP_COMMIT() asm volatile("cp.async.commit_group;" ::: "memory")
#define CP_WAIT(n)  asm volatile("cp.async.wait_group %0;" :: "n"(n) : "memory")

#define MMA_F16(d, a, b) \
    asm volatile("mma.sync.aligned.m16n8k16.row.col.f32.f16.f16.f32 " \
        "{%0,%1,%2,%3}, {%4,%5,%6,%7}, {%8,%9}, {%0,%1,%2,%3};" \
        : "+f"((d)[0]), "+f"((d)[1]), "+f"((d)[2]), "+f"((d)[3]) \
        : "r"((a)[0]), "r"((a)[1]), "r"((a)[2]), "r"((a)[3]), \
          "r"((b)[0]), "r"((b)[1]))

__device__ __forceinline__ uint32_t packh2(float lo, float hi) {
    __half2 h = __floats2half2_rn(lo, hi);
    return *reinterpret_cast<uint32_t*>(&h);
}

// ---------------------------------------------------------------------------
// x -> fp16 + row-sum mask (fused)
// ---------------------------------------------------------------------------
__global__ __launch_bounds__(128) void xconv_kernel(const float* __restrict__ x) {
    int row = blockIdx.x, tid = threadIdx.x;
    const float4* xr = reinterpret_cast<const float4*>(x + (size_t)row * C_);
    float4 a = xr[tid * 2], b = xr[tid * 2 + 1];
    float s = a.x + a.y + a.z + a.w + b.x + b.y + b.z + b.w;
    uint4 pk;
    pk.x = packh2(a.x, a.y); pk.y = packh2(a.z, a.w);
    pk.z = packh2(b.x, b.y); pk.w = packh2(b.z, b.w);
    *reinterpret_cast<uint4*>(g_Xh + (size_t)row * C_ + tid * 8) = pk;

    __shared__ float red[4];
#pragma unroll
    for (int o = 16; o; o >>= 1) s += __shfl_xor_sync(0xffffffffu, s, o);
    if ((tid & 31) == 0) red[tid >> 5] = s;
    __syncthreads();
    if (tid == 0) {
        float t = red[0] + red[1] + red[2] + red[3];
        g_mask[row] = (t != 0.0f) ? 1.0f : 0.0f;
    }
}

// ---------------------------------------------------------------------------
// W [K,N] f32 -> Wt [N,K] fp16
// ---------------------------------------------------------------------------
__global__ __launch_bounds__(256) void wtrans_kernel(
    const float* __restrict__ Wq, const float* __restrict__ Wk,
    const float* __restrict__ Wv) {
    __shared__ float t[32][33];
    const float* W = blockIdx.z == 0 ? Wq : blockIdx.z == 1 ? Wk : Wv;
    __half* Wt = g_Wth[blockIdx.z];
    int x = blockIdx.x * 32 + threadIdx.x;
    int y0 = blockIdx.y * 32;
#pragma unroll
    for (int j = 0; j < 32; j += 8)
        t[threadIdx.y + j][threadIdx.x] = W[(size_t)(y0 + threadIdx.y + j) * U_ + x];
    __syncthreads();
    int ox = y0 + threadIdx.x;
    int oy0 = blockIdx.x * 32;
#pragma unroll
    for (int j = 0; j < 32; j += 8)
        Wt[(size_t)(oy0 + threadIdx.y + j) * C_ + ox] =
            __float2half(t[threadIdx.x][threadIdx.y + j]);
}

// ---------------------------------------------------------------------------
// QKV projection via mma.sync fp16 m16n8k16. Y = relu(X @ W + b).
// CTA 128x128, Kc=32, 8 warps (2x4), warp tile 64x32. cp.async 2-stage.
// Smem (halves): per stage A[128][40] + B[128][40]; 2 stages = 40960 B.
// ---------------------------------------------------------------------------
#define KC    32
#define NCH   (C_ / KC)          // 32 chunks
#define QROWH 40                 // row stride in halves (20 words, conflict-free)
#define STGH  (2 * 128 * QROWH)  // halves per stage
#define QKV_SMEM (2 * STGH * 2)  // 40960 bytes

__global__ __launch_bounds__(256, 2) void qkv_mma_kernel(
    const float* __restrict__ bq, const float* __restrict__ bk,
    const float* __restrict__ bv) {
    extern __shared__ char smc[];
    uint32_t sb = smem_u32(smc);
    int tid = threadIdx.x;
    int wid = tid >> 5, lane = tid & 31;
    int gid = lane >> 2, tig = lane & 3;
    int wm = wid >> 2, wn = wid & 3;
    int sel = blockIdx.z;
    const __half* Wt = g_Wth[sel];
    const float* bias = sel == 0 ? bq : sel == 1 ? bk : bv;
    int n0 = blockIdx.x * 128, m0 = blockIdx.y * 128;

    int lrow = tid >> 1, lcb = (tid & 1) * 16;   // halves
    const __half* Ap = g_Xh + (size_t)(m0 + lrow) * C_ + lcb;
    const __half* Bp = Wt + (size_t)(n0 + lrow) * C_ + lcb;
    uint32_t adst = sb + (uint32_t)(lrow * QROWH + lcb) * 2;
    uint32_t bdst = adst + 128 * QROWH * 2;

    float acc[4][4][4];
#pragma unroll
    for (int i = 0; i < 4; i++)
#pragma unroll
        for (int j = 0; j < 4; j++)
#pragma unroll
            for (int r = 0; r < 4; r++) acc[i][j][r] = 0.0f;

    // prologue: stage 0
    cp_async16(adst, Ap); cp_async16(adst + 16, Ap + 8);
    cp_async16(bdst, Bp); cp_async16(bdst + 16, Bp + 8);
    CP_COMMIT();

#pragma unroll 1
    for (int c = 0; c < NCH; c++) {
        if (c + 1 < NCH) {
            uint32_t so = ((c + 1) & 1) * STGH * 2;
            const __half* An = Ap + (c + 1) * KC;
            const __half* Bn = Bp + (c + 1) * KC;
            cp_async16(adst + so, An); cp_async16(adst + so + 16, An + 8);
            cp_async16(bdst + so, Bn); cp_async16(bdst + so + 16, Bn + 8);
            CP_COMMIT();
            CP_WAIT(1);
        } else {
            CP_WAIT(0);
        }
        __syncthreads();

        const uint32_t* As = reinterpret_cast<const uint32_t*>(smc) +
                             (c & 1) * (STGH / 2);
        const uint32_t* Bs = As + 128 * (QROWH / 2);
#pragma unroll
        for (int ks = 0; ks < 2; ks++) {
            int kwo = ks * 8 + tig;   // word offset within row
            uint32_t af[4][4];
#pragma unroll
            for (int mi = 0; mi < 4; mi++) {
                int r = (wm * 64 + mi * 16 + gid) * 20;
                af[mi][0] = As[r + kwo];
                af[mi][1] = As[r + 160 + kwo];       // +8 rows
                af[mi][2] = As[r + kwo + 4];
                af[mi][3] = As[r + 160 + kwo + 4];
            }
            uint32_t bf[4][2];
#pragma unroll
            for (int ni = 0; ni < 4; ni++) {
                int nr = (wn * 32 + ni * 8 + gid) * 20;
                bf[ni][0] = Bs[nr + kwo];
                bf[ni][1] = Bs[nr + kwo + 4];
            }
#pragma unroll
            for (int mi = 0; mi < 4; mi++)
#pragma unroll
                for (int ni = 0; ni < 4; ni++)
                    MMA_F16(acc[mi][ni], af[mi], bf[ni]);
        }
        __syncthreads();
    }

    // Epilogue: bias + relu -> fp16. Q/K natural [t][U]; V transposed [d][t].
#pragma unroll
    for (int mi = 0; mi < 4; mi++) {
        int gr0 = m0 + wm * 64 + mi * 16 + gid;
#pragma unroll
        for (int ni = 0; ni < 4; ni++) {
            int gc = n0 + wn * 32 + ni * 8 + 2 * tig;
            float b0v = bias[gc], b1v = bias[gc + 1];
            float v00 = fmaxf(acc[mi][ni][0] + b0v, 0.0f);
            float v01 = fmaxf(acc[mi][ni][1] + b1v, 0.0f);
            float v10 = fmaxf(acc[mi][ni][2] + b0v, 0.0f);
            float v11 = fmaxf(acc[mi][ni][3] + b1v, 0.0f);
            if (sel == 2) {
                int bb = gr0 >> 11, tl = gr0 & (T_ - 1);
                int h = gc >> 6, d = gc & 63;
                __half* vp = g_Vth + ((size_t)(bb * H_ + h) * 64 + d) * T_;
                vp[tl] = __float2half(v00);
                vp[T_ + tl] = __float2half(v01);          // d+1
                vp[tl + 8] = __float2half(v10);           // token +8
                vp[T_ + tl + 8] = __float2half(v11);
            } else {
                __half* Y = (sel == 0 ? g_Qh : g_Kh);
                *reinterpret_cast<uint32_t*>(&Y[(size_t)gr0 * U_ + gc]) =
                    packh2(v00, v01);
                *reinterpret_cast<uint32_t*>(&Y[(size_t)(gr0 + 8) * U_ + gc]) =
                    packh2(v10, v11);
            }
        }
    }
}

// ---------------------------------------------------------------------------
// Flash-attention fp16 m16n8k16. BQ=64, BK=64, dh=64, 128 threads, 4 warps.
// Q frags in regs; cp.async double-buffered K (natural) + Vt (d-major) + mask.
// P fragment = pure register packs (fp16 frag pairs == accum pairs).
// Smem bytes: K 2x9216, Vt 2x9216, mask 2x256 -> 37376 B.
// ---------------------------------------------------------------------------
#define KS_B(bb) ((bb) * 9216)
#define VS_B(bb) (18432 + (bb) * 9216)
#define MS_B(bb) (36864 + (bb) * 256)
#define ATT_SMEM 37376
#define SPH 72   // tile row stride in halves (36 words, conflict-free)

__global__ __launch_bounds__(128, 4) void attn_mma_kernel() {
    extern __shared__ char smc[];
    uint32_t sb = smem_u32(smc);

    int tid = threadIdx.x;
    int lane = tid & 31;
    int gid = lane >> 2, tig = lane & 3;
    int qt = (int)gridDim.x - 1 - (int)blockIdx.x;   // big tiles first
    int bh = blockIdx.y;
    int b = bh >> 4;
    size_t baseU = (size_t)b * T_ * U_;
    int hcol = (bh & 15) * DH_;
    int qrow0 = (tid >> 5) * 16;

    int lrow = tid >> 1, lcb = (tid & 1) * 32;       // halves

    const __half* Kb = g_Kh + baseU + hcol + lcb;    // + token*U_
    const __half* Vb = g_Vth + ((size_t)bh * 64 + lrow) * T_ + lcb;  // + t

    // prologue: tile 0
    {
        const __half* ks = Kb + (size_t)lrow * U_;
        uint32_t kd = sb + KS_B(0) + (uint32_t)(lrow * SPH + lcb) * 2;
        uint32_t vd = sb + VS_B(0) + (uint32_t)(lrow * SPH + lcb) * 2;
#pragma unroll
        for (int i = 0; i < 4; i++) {
            cp_async16(kd + i * 16, ks + i * 8);
            cp_async16(vd + i * 16, Vb + i * 8);
        }
        if (tid < 16)
            cp_async16(sb + MS_B(0) + tid * 16, g_mask + b * T_ + tid * 4);
        CP_COMMIT();
    }

    // Q fragments
    uint32_t aq[4][4];
    {
        int qg = qt * 64 + qrow0 + gid;
        const __half* q0 = g_Qh + baseU + (size_t)qg * U_ + hcol;
        const __half* q1 = q0 + 8 * U_;
#pragma unroll
        for (int ks = 0; ks < 4; ks++) {
            int kh = ks * 16 + 2 * tig;
            aq[ks][0] = *reinterpret_cast<const uint32_t*>(q0 + kh);
            aq[ks][1] = *reinterpret_cast<const uint32_t*>(q1 + kh);
            aq[ks][2] = *reinterpret_cast<const uint32_t*>(q0 + kh + 8);
            aq[ks][3] = *reinterpret_cast<const uint32_t*>(q1 + kh + 8);
        }
    }

    float o[8][4];
#pragma unroll
    for (int d = 0; d < 8; d++)
#pragma unroll
        for (int r = 0; r < 4; r++) o[d][r] = 0.0f;
    float m0r = -INFINITY, m1r = -INFINITY;
    float l0r = 0.0f, l1r = 0.0f;
    const float NEGV = -4294967296.0f;

#pragma unroll 1
    for (int kt = 0; kt <= qt; kt++) {
        if (kt < qt) {
            int bb = (kt + 1) & 1;
            const __half* ksrc = Kb + (size_t)((kt + 1) * 64 + lrow) * U_;
            const __half* vsrc = Vb + (kt + 1) * 64;
            uint32_t kd = sb + KS_B(bb) + (uint32_t)(lrow * SPH + lcb) * 2;
            uint32_t vd = sb + VS_B(bb) + (uint32_t)(lrow * SPH + lcb) * 2;
#pragma unroll
            for (int i = 0; i < 4; i++) {
                cp_async16(kd + i * 16, ksrc + i * 8);
                cp_async16(vd + i * 16, vsrc + i * 8);
            }
            if (tid < 16)
                cp_async16(sb + MS_B(bb) + tid * 16,
                           g_mask + b * T_ + (kt + 1) * 64 + tid * 4);
            CP_COMMIT();
            CP_WAIT(1);
        } else {
            CP_WAIT(0);
        }
        __syncthreads();

        const uint32_t* Ksw = reinterpret_cast<const uint32_t*>(smc + KS_B(kt & 1));
        const uint32_t* Vw  = reinterpret_cast<const uint32_t*>(smc + VS_B(kt & 1));
        const float* Ms = reinterpret_cast<const float*>(smc + MS_B(kt & 1));

        // S = Q K^T
        float s[8][4];
#pragma unroll
        for (int ni = 0; ni < 8; ni++)
#pragma unroll
            for (int r = 0; r < 4; r++) s[ni][r] = 0.0f;
#pragma unroll
        for (int ks = 0; ks < 4; ks++) {
            int kwo = ks * 8 + tig;
#pragma unroll
            for (int ni = 0; ni < 8; ni++) {
                int nr = (ni * 8 + gid) * 36;
                uint32_t bf[2] = {Ksw[nr + kwo], Ksw[nr + kwo + 4]};
                MMA_F16(s[ni], aq[ks], bf);
            }
        }

        // scale + key mask + causal
        bool diag = (kt == qt);
        int r0l = qrow0 + gid, r1l = r0l + 8;
#pragma unroll
        for (int ni = 0; ni < 8; ni++) {
            int c0 = ni * 8 + 2 * tig, c1 = c0 + 1;
            float2 km = *reinterpret_cast<const float2*>(&Ms[c0]);
            float v0 = s[ni][0] * 0.125f;
            float v1 = s[ni][1] * 0.125f;
            float v2 = s[ni][2] * 0.125f;
            float v3 = s[ni][3] * 0.125f;
            if (km.x == 0.0f || (diag && c0 > r0l)) v0 = NEGV;
            if (km.y == 0.0f || (diag && c1 > r0l)) v1 = NEGV;
            if (km.x == 0.0f || (diag && c0 > r1l)) v2 = NEGV;
            if (km.y == 0.0f || (diag && c1 > r1l)) v3 = NEGV;
            s[ni][0] = v0; s[ni][1] = v1; s[ni][2] = v2; s[ni][3] = v3;
        }

        // online softmax (lane-local rows, quad reduce)
        float ml0 = -INFINITY, ml1 = -INFINITY;
#pragma unroll
        for (int ni = 0; ni < 8; ni++) {
            ml0 = fmaxf(ml0, fmaxf(s[ni][0], s[ni][1]));
            ml1 = fmaxf(ml1, fmaxf(s[ni][2], s[ni][3]));
        }
        ml0 = fmaxf(ml0, __shfl_xor_sync(0xffffffffu, ml0, 1));
        ml0 = fmaxf(ml0, __shfl_xor_sync(0xffffffffu, ml0, 2));
        ml1 = fmaxf(ml1, __shfl_xor_sync(0xffffffffu, ml1, 1));
        ml1 = fmaxf(ml1, __shfl_xor_sync(0xffffffffu, ml1, 2));
        float mn0 = fmaxf(m0r, ml0);
        float mn1 = fmaxf(m1r, ml1);
        float al0 = __expf(m0r - mn0);
        float al1 = __expf(m1r - mn1);
        float sum0 = 0.0f, sum1 = 0.0f;
#pragma unroll
        for (int ni = 0; ni < 8; ni++) {
            s[ni][0] = __expf(s[ni][0] - mn0);
            s[ni][1] = __expf(s[ni][1] - mn0);
            s[ni][2] = __expf(s[ni][2] - mn1);
            s[ni][3] = __expf(s[ni][3] - mn1);
            sum0 += s[ni][0] + s[ni][1];
            sum1 += s[ni][2] + s[ni][3];
        }
        sum0 += __shfl_xor_sync(0xffffffffu, sum0, 1);
        sum0 += __shfl_xor_sync(0xffffffffu, sum0, 2);
        sum1 += __shfl_xor_sync(0xffffffffu, sum1, 1);
        sum1 += __shfl_xor_sync(0xffffffffu, sum1, 2);
        l0r = l0r * al0 + sum0;
        l1r = l1r * al1 + sum1;
        m0r = mn0; m1r = mn1;

#pragma unroll
        for (int d = 0; d < 8; d++) {
            o[d][0] *= al0; o[d][1] *= al0;
            o[d][2] *= al1; o[d][3] *= al1;
        }

        // O += P V^T : P fragment is a pure register pack
#pragma unroll
        for (int ks = 0; ks < 4; ks++) {
            uint32_t pa[4];
            pa[0] = packh2(s[2 * ks][0], s[2 * ks][1]);
            pa[1] = packh2(s[2 * ks][2], s[2 * ks][3]);
            pa[2] = packh2(s[2 * ks + 1][0], s[2 * ks + 1][1]);
            pa[3] = packh2(s[2 * ks + 1][2], s[2 * ks + 1][3]);
            int kwo = ks * 8 + tig;
#pragma unroll
            for (int d = 0; d < 8; d++) {
                int nr = (d * 8 + gid) * 36;
                uint32_t bf[2] = {Vw[nr + kwo], Vw[nr + kwo + 4]};
                MMA_F16(o[d], pa, bf);
            }
        }
        __syncthreads();
    }

    // epilogue: normalize, query mask, write f32 [q][d]
    {
        int qg0 = qt * 64 + qrow0 + gid;
        int qg1 = qg0 + 8;
        float inv0 = g_mask[b * T_ + qg0] / l0r;
        float inv1 = g_mask[b * T_ + qg1] / l1r;
        float* o0p = g_O + baseU + (size_t)qg0 * U_ + hcol;
        float* o1p = g_O + baseU + (size_t)qg1 * U_ + hcol;
#pragma unroll
        for (int d = 0; d < 8; d++) {
            int c = d * 8 + 2 * tig;
            *reinterpret_cast<float2*>(o0p + c) =
                make_float2(o[d][0] * inv0, o[d][1] * inv0);
            *reinterpret_cast<float2*>(o1p + c) =
                make_float2(o[d][2] * inv1, o[d][3] * inv1);
        }
    }
}

// ---------------------------------------------------------------------------
// Residual + LayerNorm (biased variance, eps=1e-8) + affine
// ---------------------------------------------------------------------------
__global__ __launch_bounds__(256) void ln_kernel(
    const float* __restrict__ x, const float* __restrict__ gamma,
    const float* __restrict__ beta, float* __restrict__ out) {
    int row = blockIdx.x;
    int tid = threadIdx.x;
    __shared__ float rsum[8], rsq[8];
    __shared__ float smean, srstd;

    const float4* x4 = reinterpret_cast<const float4*>(x + (size_t)row * U_);
    const float4* o4 = reinterpret_cast<const float4*>(g_O + (size_t)row * U_);
    float4 xv = x4[tid], ov = o4[tid];
    float4 sv = make_float4(xv.x + ov.x, xv.y + ov.y, xv.z + ov.z, xv.w + ov.w);

    float s1 = sv.x + sv.y + sv.z + sv.w;
    float s2 = sv.x * sv.x + sv.y * sv.y + sv.z * sv.z + sv.w * sv.w;
#pragma unroll
    for (int o = 16; o; o >>= 1) {
        s1 += __shfl_xor_sync(0xffffffffu, s1, o);
        s2 += __shfl_xor_sync(0xffffffffu, s2, o);
    }
    if ((tid & 31) == 0) { rsum[tid >> 5] = s1; rsq[tid >> 5] = s2; }
    __syncthreads();
    if (tid == 0) {
        float t1 = 0, t2 = 0;
#pragma unroll
        for (int i = 0; i < 8; i++) { t1 += rsum[i]; t2 += rsq[i]; }
        float mean = t1 * (1.0f / U_);
        float var = t2 * (1.0f / U_) - mean * mean;
        smean = mean;
        srstd = rsqrtf(var + 1e-8f);
    }
    __syncthreads();
    float mean = smean, rstd = srstd;

    const float4* g4 = reinterpret_cast<const float4*>(gamma);
    const float4* b4 = reinterpret_cast<const float4*>(beta);
    float4 gv = g4[tid], bv = b4[tid];
    float4 o;
    o.x = gv.x * ((sv.x - mean) * rstd) + bv.x;
    o.y = gv.y * ((sv.y - mean) * rstd) + bv.y;
    o.z = gv.z * ((sv.z - mean) * rstd) + bv.z;
    o.w = gv.w * ((sv.w - mean) * rstd) + bv.w;
    reinterpret_cast<float4*>(out + (size_t)row * U_)[tid] = o;
}

// ---------------------------------------------------------------------------
extern "C" void kernel_launch(void* const* d_in, const int* in_sizes, int n_in,
                              void* d_out, int out_size) {
    const float* x     = (const float*)d_in[0];
    const float* Wq    = (const float*)d_in[1];
    const float* bq    = (const float*)d_in[2];
    const float* Wk    = (const float*)d_in[3];
    const float* bk    = (const float*)d_in[4];
    const float* Wv    = (const float*)d_in[5];
    const float* bv    = (const float*)d_in[6];
    const float* gamma = (const float*)d_in[7];
    const float* beta  = (const float*)d_in[8];
    float* out = (float*)d_out;

    cudaFuncSetAttribute(qkv_mma_kernel,
                         cudaFuncAttributeMaxDynamicSharedMemorySize, QKV_SMEM);
    cudaFuncSetAttribute(attn_mma_kernel,
                         cudaFuncAttributeMaxDynamicSharedMemorySize, ATT_SMEM);

    xconv_kernel<<<M_, 128>>>(x);
    wtrans_kernel<<<dim3(32, 32, 3), dim3(32, 8)>>>(Wq, Wk, Wv);
    qkv_mma_kernel<<<dim3(U_ / 128, M_ / 128, 3), 256, QKV_SMEM>>>(bq, bk, bv);
    attn_mma_kernel<<<dim3(T_ / 64, B_ * H_), 128, ATT_SMEM>>>();
    ln_kernel<<<M_, 256>>>(x, gamma, beta, out);
}

// round 10
// speedup vs baseline: 5.0473x; 1.0379x over previous
#include <cuda_runtime.h>
#include <cuda_fp16.h>
#include <math.h>
#include <stdint.h>

// Problem constants
#define B_  2
#define T_  2048
#define C_  1024
#define U_  1024
#define H_  16
#define DH_ 64
#define M_  4096   // B_*T_

// Scratch (device globals; no allocation allowed)
__device__ __half g_Xh[(size_t)M_ * C_];        // x in fp16
__device__ __half g_Wth[3][(size_t)C_ * U_];    // W^T [N][K] fp16
__device__ __half g_Qh[(size_t)M_ * U_];        // Q fp16 [t][U]
__device__ __half g_Kh[(size_t)M_ * U_];        // K fp16 [t][U]
__device__ __half g_Vth[(size_t)M_ * U_];       // V fp16 transposed: [(b*H+h)*64+d][T]
__device__ float  g_O[(size_t)M_ * U_];
__device__ float  g_mask[M_];
__device__ __half g_maskh[M_];

__device__ __forceinline__ uint32_t smem_u32(const void* p) {
    uint32_t a;
    asm("{ .reg .u64 t; cvta.to.shared.u64 t, %1; cvt.u32.u64 %0, t; }"
        : "=r"(a) : "l"(p));
    return a;
}
__device__ __forceinline__ void cp_async16(uint32_t dst, const void* src) {
    asm volatile("cp.async.cg.shared.global [%0], [%1], 16;"
                 :: "r"(dst), "l"(src));
}
#define CP_COMMIT() asm volatile("cp.async.commit_group;" ::: "memory")
#define CP_WAIT(n)  asm volatile("cp.async.wait_group %0;" :: "n"(n) : "memory")

#define MMA_F16(d, a, b) \
    asm volatile("mma.sync.aligned.m16n8k16.row.col.f32.f16.f16.f32 " \
        "{%0,%1,%2,%3}, {%4,%5,%6,%7}, {%8,%9}, {%0,%1,%2,%3};" \
        : "+f"((d)[0]), "+f"((d)[1]), "+f"((d)[2]), "+f"((d)[3]) \
        : "r"((a)[0]), "r"((a)[1]), "r"((a)[2]), "r"((a)[3]), \
          "r"((b)[0]), "r"((b)[1]))

__device__ __forceinline__ uint32_t packh2(float lo, float hi) {
    __half2 h = __floats2half2_rn(lo, hi);
    return *reinterpret_cast<uint32_t*>(&h);
}
__device__ __forceinline__ uint32_t ex2h2(uint32_t t) {
    uint32_t r;
    asm("ex2.approx.f16x2 %0, %1;" : "=r"(r) : "r"(t));
    return r;
}
__device__ __forceinline__ uint32_t mulh2(uint32_t a, uint32_t b) {
    __half2 r = __hmul2(*reinterpret_cast<__half2*>(&a),
                        *reinterpret_cast<__half2*>(&b));
    return *reinterpret_cast<uint32_t*>(&r);
}

// ---------------------------------------------------------------------------
// x -> fp16 + row-sum mask (fused); mask stored f32 + f16
// ---------------------------------------------------------------------------
__global__ __launch_bounds__(128) void xconv_kernel(const float* __restrict__ x) {
    int row = blockIdx.x, tid = threadIdx.x;
    const float4* xr = reinterpret_cast<const float4*>(x + (size_t)row * C_);
    float4 a = xr[tid * 2], b = xr[tid * 2 + 1];
    float s = a.x + a.y + a.z + a.w + b.x + b.y + b.z + b.w;
    uint4 pk;
    pk.x = packh2(a.x, a.y); pk.y = packh2(a.z, a.w);
    pk.z = packh2(b.x, b.y); pk.w = packh2(b.z, b.w);
    *reinterpret_cast<uint4*>(g_Xh + (size_t)row * C_ + tid * 8) = pk;

    __shared__ float red[4];
#pragma unroll
    for (int o = 16; o; o >>= 1) s += __shfl_xor_sync(0xffffffffu, s, o);
    if ((tid & 31) == 0) red[tid >> 5] = s;
    __syncthreads();
    if (tid == 0) {
        float t = red[0] + red[1] + red[2] + red[3];
        float m = (t != 0.0f) ? 1.0f : 0.0f;
        g_mask[row] = m;
        g_maskh[row] = __float2half(m);
    }
}

// ---------------------------------------------------------------------------
// W [K,N] f32 -> Wt [N,K] fp16
// ---------------------------------------------------------------------------
__global__ __launch_bounds__(256) void wtrans_kernel(
    const float* __restrict__ Wq, const float* __restrict__ Wk,
    const float* __restrict__ Wv) {
    __shared__ float t[32][33];
    const float* W = blockIdx.z == 0 ? Wq : blockIdx.z == 1 ? Wk : Wv;
    __half* Wt = g_Wth[blockIdx.z];
    int x = blockIdx.x * 32 + threadIdx.x;
    int y0 = blockIdx.y * 32;
#pragma unroll
    for (int j = 0; j < 32; j += 8)
        t[threadIdx.y + j][threadIdx.x] = W[(size_t)(y0 + threadIdx.y + j) * U_ + x];
    __syncthreads();
    int ox = y0 + threadIdx.x;
    int oy0 = blockIdx.x * 32;
#pragma unroll
    for (int j = 0; j < 32; j += 8)
        Wt[(size_t)(oy0 + threadIdx.y + j) * C_ + ox] =
            __float2half(t[threadIdx.x][threadIdx.y + j]);
}

// ---------------------------------------------------------------------------
// QKV projection via mma.sync fp16 m16n8k16 (unchanged from round 8).
// ---------------------------------------------------------------------------
#define KC    32
#define NCH   (C_ / KC)          // 32 chunks
#define QROWH 40                 // row stride in halves
#define STGH  (2 * 128 * QROWH)  // halves per stage
#define QKV_SMEM (2 * STGH * 2)  // 40960 bytes

__global__ __launch_bounds__(256, 2) void qkv_mma_kernel(
    const float* __restrict__ bq, const float* __restrict__ bk,
    const float* __restrict__ bv) {
    extern __shared__ char smc[];
    uint32_t sb = smem_u32(smc);
    int tid = threadIdx.x;
    int wid = tid >> 5, lane = tid & 31;
    int gid = lane >> 2, tig = lane & 3;
    int wm = wid >> 2, wn = wid & 3;
    int sel = blockIdx.z;
    const __half* Wt = g_Wth[sel];
    const float* bias = sel == 0 ? bq : sel == 1 ? bk : bv;
    int n0 = blockIdx.x * 128, m0 = blockIdx.y * 128;

    int lrow = tid >> 1, lcb = (tid & 1) * 16;
    const __half* Ap = g_Xh + (size_t)(m0 + lrow) * C_ + lcb;
    const __half* Bp = Wt + (size_t)(n0 + lrow) * C_ + lcb;
    uint32_t adst = sb + (uint32_t)(lrow * QROWH + lcb) * 2;
    uint32_t bdst = adst + 128 * QROWH * 2;

    float acc[4][4][4];
#pragma unroll
    for (int i = 0; i < 4; i++)
#pragma unroll
        for (int j = 0; j < 4; j++)
#pragma unroll
            for (int r = 0; r < 4; r++) acc[i][j][r] = 0.0f;

    cp_async16(adst, Ap); cp_async16(adst + 16, Ap + 8);
    cp_async16(bdst, Bp); cp_async16(bdst + 16, Bp + 8);
    CP_COMMIT();

#pragma unroll 1
    for (int c = 0; c < NCH; c++) {
        if (c + 1 < NCH) {
            uint32_t so = ((c + 1) & 1) * STGH * 2;
            const __half* An = Ap + (c + 1) * KC;
            const __half* Bn = Bp + (c + 1) * KC;
            cp_async16(adst + so, An); cp_async16(adst + so + 16, An + 8);
            cp_async16(bdst + so, Bn); cp_async16(bdst + so + 16, Bn + 8);
            CP_COMMIT();
            CP_WAIT(1);
        } else {
            CP_WAIT(0);
        }
        __syncthreads();

        const uint32_t* As = reinterpret_cast<const uint32_t*>(smc) +
                             (c & 1) * (STGH / 2);
        const uint32_t* Bs = As + 128 * (QROWH / 2);
#pragma unroll
        for (int ks = 0; ks < 2; ks++) {
            int kwo = ks * 8 + tig;
            uint32_t af[4][4];
#pragma unroll
            for (int mi = 0; mi < 4; mi++) {
                int r = (wm * 64 + mi * 16 + gid) * 20;
                af[mi][0] = As[r + kwo];
                af[mi][1] = As[r + 160 + kwo];
                af[mi][2] = As[r + kwo + 4];
                af[mi][3] = As[r + 160 + kwo + 4];
            }
            uint32_t bf[4][2];
#pragma unroll
            for (int ni = 0; ni < 4; ni++) {
                int nr = (wn * 32 + ni * 8 + gid) * 20;
                bf[ni][0] = Bs[nr + kwo];
                bf[ni][1] = Bs[nr + kwo + 4];
            }
#pragma unroll
            for (int mi = 0; mi < 4; mi++)
#pragma unroll
                for (int ni = 0; ni < 4; ni++)
                    MMA_F16(acc[mi][ni], af[mi], bf[ni]);
        }
        __syncthreads();
    }

#pragma unroll
    for (int mi = 0; mi < 4; mi++) {
        int gr0 = m0 + wm * 64 + mi * 16 + gid;
#pragma unroll
        for (int ni = 0; ni < 4; ni++) {
            int gc = n0 + wn * 32 + ni * 8 + 2 * tig;
            float b0v = bias[gc], b1v = bias[gc + 1];
            float v00 = fmaxf(acc[mi][ni][0] + b0v, 0.0f);
            float v01 = fmaxf(acc[mi][ni][1] + b1v, 0.0f);
            float v10 = fmaxf(acc[mi][ni][2] + b0v, 0.0f);
            float v11 = fmaxf(acc[mi][ni][3] + b1v, 0.0f);
            if (sel == 2) {
                int bb = gr0 >> 11, tl = gr0 & (T_ - 1);
                int h = gc >> 6, d = gc & 63;
                __half* vp = g_Vth + ((size_t)(bb * H_ + h) * 64 + d) * T_;
                vp[tl] = __float2half(v00);
                vp[T_ + tl] = __float2half(v01);
                vp[tl + 8] = __float2half(v10);
                vp[T_ + tl + 8] = __float2half(v11);
            } else {
                __half* Y = (sel == 0 ? g_Qh : g_Kh);
                *reinterpret_cast<uint32_t*>(&Y[(size_t)gr0 * U_ + gc]) =
                    packh2(v00, v01);
                *reinterpret_cast<uint32_t*>(&Y[(size_t)(gr0 + 8) * U_ + gc]) =
                    packh2(v10, v11);
            }
        }
    }
}

// ---------------------------------------------------------------------------
// Flash-attention fp16, NO online max: Q,K >= 0 (relu) so scores in [0,~48],
// exp(s/8) safe in fp16. Masks applied multiplicatively on p (exact: no max
// state). l accumulated by an extra MMA against all-ones B. exp via
// ex2.approx.f16x2 (p = 2^(s*0.125*log2e)).
// ---------------------------------------------------------------------------
#define KS_B(bb) ((bb) * 9216)
#define VS_B(bb) (18432 + (bb) * 9216)
#define MS_B(bb) (36864 + (bb) * 128)
#define ATT_SMEM 37120
#define SPH 72   // tile row stride in halves (36 words)

__global__ __launch_bounds__(128, 4) void attn_mma_kernel() {
    extern __shared__ char smc[];
    uint32_t sb = smem_u32(smc);

    int tid = threadIdx.x;
    int lane = tid & 31;
    int gid = lane >> 2, tig = lane & 3;
    int qt = (int)gridDim.x - 1 - (int)blockIdx.x;   // big tiles first
    int bh = blockIdx.y;
    int b = bh >> 4;
    size_t baseU = (size_t)b * T_ * U_;
    int hcol = (bh & 15) * DH_;
    int qrow0 = (tid >> 5) * 16;

    int lrow = tid >> 1, lcb = (tid & 1) * 32;       // halves

    const __half* Kb = g_Kh + baseU + hcol + lcb;
    const __half* Vb = g_Vth + ((size_t)bh * 64 + lrow) * T_ + lcb;

    // prologue: tile 0
    {
        const __half* ks = Kb + (size_t)lrow * U_;
        uint32_t kd = sb + KS_B(0) + (uint32_t)(lrow * SPH + lcb) * 2;
        uint32_t vd = sb + VS_B(0) + (uint32_t)(lrow * SPH + lcb) * 2;
#pragma unroll
        for (int i = 0; i < 4; i++) {
            cp_async16(kd + i * 16, ks + i * 8);
            cp_async16(vd + i * 16, Vb + i * 8);
        }
        if (tid < 8)
            cp_async16(sb + MS_B(0) + tid * 16, g_maskh + b * T_ + tid * 8);
        CP_COMMIT();
    }

    // Q fragments
    uint32_t aq[4][4];
    {
        int qg = qt * 64 + qrow0 + gid;
        const __half* q0 = g_Qh + baseU + (size_t)qg * U_ + hcol;
        const __half* q1 = q0 + 8 * U_;
#pragma unroll
        for (int ks = 0; ks < 4; ks++) {
            int kh = ks * 16 + 2 * tig;
            aq[ks][0] = *reinterpret_cast<const uint32_t*>(q0 + kh);
            aq[ks][1] = *reinterpret_cast<const uint32_t*>(q1 + kh);
            aq[ks][2] = *reinterpret_cast<const uint32_t*>(q0 + kh + 8);
            aq[ks][3] = *reinterpret_cast<const uint32_t*>(q1 + kh + 8);
        }
    }

    float o[8][4];
#pragma unroll
    for (int d = 0; d < 8; d++)
#pragma unroll
        for (int r = 0; r < 4; r++) o[d][r] = 0.0f;
    float lacc[4] = {0.0f, 0.0f, 0.0f, 0.0f};

    const float CE = 0.18033688f;   // 0.125 * log2(e)
    int r0l = qrow0 + gid, r1l = r0l + 8;

#pragma unroll 1
    for (int kt = 0; kt <= qt; kt++) {
        if (kt < qt) {
            int bb = (kt + 1) & 1;
            const __half* ksrc = Kb + (size_t)((kt + 1) * 64 + lrow) * U_;
            const __half* vsrc = Vb + (kt + 1) * 64;
            uint32_t kd = sb + KS_B(bb) + (uint32_t)(lrow * SPH + lcb) * 2;
            uint32_t vd = sb + VS_B(bb) + (uint32_t)(lrow * SPH + lcb) * 2;
#pragma unroll
            for (int i = 0; i < 4; i++) {
                cp_async16(kd + i * 16, ksrc + i * 8);
                cp_async16(vd + i * 16, vsrc + i * 8);
            }
            if (tid < 8)
                cp_async16(sb + MS_B(bb) + tid * 16,
                           g_maskh + b * T_ + (kt + 1) * 64 + tid * 8);
            CP_COMMIT();
            CP_WAIT(1);
        } else {
            CP_WAIT(0);
        }
        __syncthreads();

        const uint32_t* Ksw = reinterpret_cast<const uint32_t*>(smc + KS_B(kt & 1));
        const uint32_t* Vw  = reinterpret_cast<const uint32_t*>(smc + VS_B(kt & 1));
        const uint32_t* Mh  = reinterpret_cast<const uint32_t*>(smc + MS_B(kt & 1));

        // S = Q K^T
        float s[8][4];
#pragma unroll
        for (int ni = 0; ni < 8; ni++)
#pragma unroll
            for (int r = 0; r < 4; r++) s[ni][r] = 0.0f;
#pragma unroll
        for (int ks = 0; ks < 4; ks++) {
            int kwo = ks * 8 + tig;
#pragma unroll
            for (int ni = 0; ni < 8; ni++) {
                int nr = (ni * 8 + gid) * 36;
                uint32_t bf[2] = {Ksw[nr + kwo], Ksw[nr + kwo + 4]};
                MMA_F16(s[ni], aq[ks], bf);
            }
        }

        // P = exp2(s*CE) * keymask (* causal on diag tile), packed half2
        bool diag = (kt == qt);
        uint32_t ph[8][2];
#pragma unroll
        for (int ni = 0; ni < 8; ni++) {
            int c0 = ni * 8 + 2 * tig;
            uint32_t km2 = Mh[c0 >> 1];
            uint32_t p0 = mulh2(ex2h2(packh2(s[ni][0] * CE, s[ni][1] * CE)), km2);
            uint32_t p1 = mulh2(ex2h2(packh2(s[ni][2] * CE, s[ni][3] * CE)), km2);
            if (diag) {
                uint32_t cm0 = packh2(c0 <= r0l ? 1.0f : 0.0f,
                                      c0 + 1 <= r0l ? 1.0f : 0.0f);
                uint32_t cm1 = packh2(c0 <= r1l ? 1.0f : 0.0f,
                                      c0 + 1 <= r1l ? 1.0f : 0.0f);
                p0 = mulh2(p0, cm0);
                p1 = mulh2(p1, cm1);
            }
            ph[ni][0] = p0;
            ph[ni][1] = p1;
        }

        // O += P V^T ; l += P @ ones
#pragma unroll
        for (int ks = 0; ks < 4; ks++) {
            uint32_t pa[4] = {ph[2 * ks][0], ph[2 * ks][1],
                              ph[2 * ks + 1][0], ph[2 * ks + 1][1]};
            uint32_t onesb[2] = {0x3C003C00u, 0x3C003C00u};
            MMA_F16(lacc, pa, onesb);
            int kwo = ks * 8 + tig;
#pragma unroll
            for (int d = 0; d < 8; d++) {
                int nr = (d * 8 + gid) * 36;
                uint32_t bf[2] = {Vw[nr + kwo], Vw[nr + kwo + 4]};
                MMA_F16(o[d], pa, bf);
            }
        }
        __syncthreads();
    }

    // epilogue: normalize by l, query mask, write f32 [q][d]
    {
        int qg0 = qt * 64 + qrow0 + gid;
        int qg1 = qg0 + 8;
        float inv0 = g_mask[b * T_ + qg0] / lacc[0];
        float inv1 = g_mask[b * T_ + qg1] / lacc[2];
        float* o0p = g_O + baseU + (size_t)qg0 * U_ + hcol;
        float* o1p = g_O + baseU + (size_t)qg1 * U_ + hcol;
#pragma unroll
        for (int d = 0; d < 8; d++) {
            int c = d * 8 + 2 * tig;
            *reinterpret_cast<float2*>(o0p + c) =
                make_float2(o[d][0] * inv0, o[d][1] * inv0);
            *reinterpret_cast<float2*>(o1p + c) =
                make_float2(o[d][2] * inv1, o[d][3] * inv1);
        }
    }
}

// ---------------------------------------------------------------------------
// Residual + LayerNorm (biased variance, eps=1e-8) + affine
// ---------------------------------------------------------------------------
__global__ __launch_bounds__(256) void ln_kernel(
    const float* __restrict__ x, const float* __restrict__ gamma,
    const float* __restrict__ beta, float* __restrict__ out) {
    int row = blockIdx.x;
    int tid = threadIdx.x;
    __shared__ float rsum[8], rsq[8];
    __shared__ float smean, srstd;

    const float4* x4 = reinterpret_cast<const float4*>(x + (size_t)row * U_);
    const float4* o4 = reinterpret_cast<const float4*>(g_O + (size_t)row * U_);
    float4 xv = x4[tid], ov = o4[tid];
    float4 sv = make_float4(xv.x + ov.x, xv.y + ov.y, xv.z + ov.z, xv.w + ov.w);

    float s1 = sv.x + sv.y + sv.z + sv.w;
    float s2 = sv.x * sv.x + sv.y * sv.y + sv.z * sv.z + sv.w * sv.w;
#pragma unroll
    for (int o = 16; o; o >>= 1) {
        s1 += __shfl_xor_sync(0xffffffffu, s1, o);
        s2 += __shfl_xor_sync(0xffffffffu, s2, o);
    }
    if ((tid & 31) == 0) { rsum[tid >> 5] = s1; rsq[tid >> 5] = s2; }
    __syncthreads();
    if (tid == 0) {
        float t1 = 0, t2 = 0;
#pragma unroll
        for (int i = 0; i < 8; i++) { t1 += rsum[i]; t2 += rsq[i]; }
        float mean = t1 * (1.0f / U_);
        float var = t2 * (1.0f / U_) - mean * mean;
        smean = mean;
        srstd = rsqrtf(var + 1e-8f);
    }
    __syncthreads();
    float mean = smean, rstd = srstd;

    const float4* g4 = reinterpret_cast<const float4*>(gamma);
    const float4* b4 = reinterpret_cast<const float4*>(beta);
    float4 gv = g4[tid], bv = b4[tid];
    float4 o;
    o.x = gv.x * ((sv.x - mean) * rstd) + bv.x;
    o.y = gv.y * ((sv.y - mean) * rstd) + bv.y;
    o.z = gv.z * ((sv.z - mean) * rstd) + bv.z;
    o.w = gv.w * ((sv.w - mean) * rstd) + bv.w;
    reinterpret_cast<float4*>(out + (size_t)row * U_)[tid] = o;
}

// ---------------------------------------------------------------------------
extern "C" void kernel_launch(void* const* d_in, const int* in_sizes, int n_in,
                              void* d_out, int out_size) {
    const float* x     = (const float*)d_in[0];
    const float* Wq    = (const float*)d_in[1];
    const float* bq    = (const float*)d_in[2];
    const float* Wk    = (const float*)d_in[3];
    const float* bk    = (const float*)d_in[4];
    const float* Wv    = (const float*)d_in[5];
    const float* bv    = (const float*)d_in[6];
    const float* gamma = (const float*)d_in[7];
    const float* beta  = (const float*)d_in[8];
    float* out = (float*)d_out;

    cudaFuncSetAttribute(qkv_mma_kernel,
                         cudaFuncAttributeMaxDynamicSharedMemorySize, QKV_SMEM);
    cudaFuncSetAttribute(attn_mma_kernel,
                         cudaFuncAttributeMaxDynamicSharedMemorySize, ATT_SMEM);

    xconv_kernel<<<M_, 128>>>(x);
    wtrans_kernel<<<dim3(32, 32, 3), dim3(32, 8)>>>(Wq, Wk, Wv);
    qkv_mma_kernel<<<dim3(U_ / 128, M_ / 128, 3), 256, QKV_SMEM>>>(bq, bk, bv);
    attn_mma_kernel<<<dim3(T_ / 64, B_ * H_), 128, ATT_SMEM>>>();
    ln_kernel<<<M_, 256>>>(x, gamma, beta, out);
}

// round 11
// speedup vs baseline: 5.2622x; 1.0426x over previous
#include <cuda_runtime.h>
#include <cuda_fp16.h>
#include <math.h>
#include <stdint.h>

// Problem constants
#define B_  2
#define T_  2048
#define C_  1024
#define U_  1024
#define H_  16
#define DH_ 64
#define M_  4096   // B_*T_

// Scratch (device globals; no allocation allowed)
__device__ __half g_Xh[(size_t)M_ * C_];        // x in fp16
__device__ __half g_Wth[3][(size_t)C_ * U_];    // W^T [N][K] fp16
__device__ __half g_Qh[(size_t)M_ * U_];        // Q fp16 [t][U]
__device__ __half g_Kh[(size_t)M_ * U_];        // K fp16 [t][U]
__device__ __half g_Vth[(size_t)M_ * U_];       // V fp16 transposed: [(b*H+h)*64+d][T]
__device__ float  g_O[(size_t)M_ * U_];
__device__ float  g_mask[M_];
__device__ __half g_maskh[M_];

__device__ __forceinline__ uint32_t smem_u32(const void* p) {
    uint32_t a;
    asm("{ .reg .u64 t; cvta.to.shared.u64 t, %1; cvt.u32.u64 %0, t; }"
        : "=r"(a) : "l"(p));
    return a;
}
__device__ __forceinline__ void cp_async16(uint32_t dst, const void* src) {
    asm volatile("cp.async.cg.shared.global [%0], [%1], 16;"
                 :: "r"(dst), "l"(src));
}
#define CP_COMMIT() asm volatile("cp.async.commit_group;" ::: "memory")
#define CP_WAIT(n)  asm volatile("cp.async.wait_group %0;" :: "n"(n) : "memory")

#define MMA_F16(d, a, b) \
    asm volatile("mma.sync.aligned.m16n8k16.row.col.f32.f16.f16.f32 " \
        "{%0,%1,%2,%3}, {%4,%5,%6,%7}, {%8,%9}, {%0,%1,%2,%3};" \
        : "+f"((d)[0]), "+f"((d)[1]), "+f"((d)[2]), "+f"((d)[3]) \
        : "r"((a)[0]), "r"((a)[1]), "r"((a)[2]), "r"((a)[3]), \
          "r"((b)[0]), "r"((b)[1]))

#define LDSM_X4(r0, r1, r2, r3, addr) \
    asm volatile("ldmatrix.sync.aligned.m8n8.x4.shared.b16 {%0,%1,%2,%3}, [%4];" \
        : "=r"(r0), "=r"(r1), "=r"(r2), "=r"(r3) : "r"(addr))

__device__ __forceinline__ uint32_t packh2(float lo, float hi) {
    __half2 h = __floats2half2_rn(lo, hi);
    return *reinterpret_cast<uint32_t*>(&h);
}
__device__ __forceinline__ uint32_t ex2h2(uint32_t t) {
    uint32_t r;
    asm("ex2.approx.f16x2 %0, %1;" : "=r"(r) : "r"(t));
    return r;
}
__device__ __forceinline__ uint32_t mulh2(uint32_t a, uint32_t b) {
    __half2 r = __hmul2(*reinterpret_cast<__half2*>(&a),
                        *reinterpret_cast<__half2*>(&b));
    return *reinterpret_cast<uint32_t*>(&r);
}

// ---------------------------------------------------------------------------
// x -> fp16 + row-sum mask (fused); mask stored f32 + f16
// ---------------------------------------------------------------------------
__global__ __launch_bounds__(128) void xconv_kernel(const float* __restrict__ x) {
    int row = blockIdx.x, tid = threadIdx.x;
    const float4* xr = reinterpret_cast<const float4*>(x + (size_t)row * C_);
    float4 a = xr[tid * 2], b = xr[tid * 2 + 1];
    float s = a.x + a.y + a.z + a.w + b.x + b.y + b.z + b.w;
    uint4 pk;
    pk.x = packh2(a.x, a.y); pk.y = packh2(a.z, a.w);
    pk.z = packh2(b.x, b.y); pk.w = packh2(b.z, b.w);
    *reinterpret_cast<uint4*>(g_Xh + (size_t)row * C_ + tid * 8) = pk;

    __shared__ float red[4];
#pragma unroll
    for (int o = 16; o; o >>= 1) s += __shfl_xor_sync(0xffffffffu, s, o);
    if ((tid & 31) == 0) red[tid >> 5] = s;
    __syncthreads();
    if (tid == 0) {
        float t = red[0] + red[1] + red[2] + red[3];
        float m = (t != 0.0f) ? 1.0f : 0.0f;
        g_mask[row] = m;
        g_maskh[row] = __float2half(m);
    }
}

// ---------------------------------------------------------------------------
// W [K,N] f32 -> Wt [N,K] fp16
// ---------------------------------------------------------------------------
__global__ __launch_bounds__(256) void wtrans_kernel(
    const float* __restrict__ Wq, const float* __restrict__ Wk,
    const float* __restrict__ Wv) {
    __shared__ float t[32][33];
    const float* W = blockIdx.z == 0 ? Wq : blockIdx.z == 1 ? Wk : Wv;
    __half* Wt = g_Wth[blockIdx.z];
    int x = blockIdx.x * 32 + threadIdx.x;
    int y0 = blockIdx.y * 32;
#pragma unroll
    for (int j = 0; j < 32; j += 8)
        t[threadIdx.y + j][threadIdx.x] = W[(size_t)(y0 + threadIdx.y + j) * U_ + x];
    __syncthreads();
    int ox = y0 + threadIdx.x;
    int oy0 = blockIdx.x * 32;
#pragma unroll
    for (int j = 0; j < 32; j += 8)
        Wt[(size_t)(oy0 + threadIdx.y + j) * C_ + ox] =
            __float2half(t[threadIdx.x][threadIdx.y + j]);
}

// ---------------------------------------------------------------------------
// QKV projection via mma.sync fp16 m16n8k16 + ldmatrix fragment loads.
// ---------------------------------------------------------------------------
#define KC    32
#define NCH   (C_ / KC)          // 32 chunks
#define QROWH 40                 // row stride in halves (80 B)
#define STGH  (2 * 128 * QROWH)  // halves per stage
#define QKV_SMEM (2 * STGH * 2)  // 40960 bytes

__global__ __launch_bounds__(256, 2) void qkv_mma_kernel(
    const float* __restrict__ bq, const float* __restrict__ bk,
    const float* __restrict__ bv) {
    extern __shared__ char smc[];
    uint32_t sb = smem_u32(smc);
    int tid = threadIdx.x;
    int wid = tid >> 5, lane = tid & 31;
    int gid = lane >> 2, tig = lane & 3;
    int lg = lane >> 3, lr = lane & 7;
    int wm = wid >> 2, wn = wid & 3;
    int sel = blockIdx.z;
    const __half* Wt = g_Wth[sel];
    const float* bias = sel == 0 ? bq : sel == 1 ? bk : bv;
    int n0 = blockIdx.x * 128, m0 = blockIdx.y * 128;

    int lrow = tid >> 1, lcb = (tid & 1) * 16;
    const __half* Ap = g_Xh + (size_t)(m0 + lrow) * C_ + lcb;
    const __half* Bp = Wt + (size_t)(n0 + lrow) * C_ + lcb;
    uint32_t adst = sb + (uint32_t)(lrow * QROWH + lcb) * 2;
    uint32_t bdst = adst + 128 * QROWH * 2;

    // ldmatrix per-lane address offsets (bytes)
    // A: m0..m3 = {r-lo,k-lo},{r-hi,k-lo},{r-lo,k-hi},{r-hi,k-hi}
    uint32_t aoff = (uint32_t)(((lg & 1) * 8 + lr) * (QROWH * 2) + (lg >> 1) * 16)
                    + (uint32_t)(wm * 64) * (QROWH * 2);
    // B: m0..m3 = {n-lo,k-lo},{n-lo,k-hi},{n-hi,k-lo},{n-hi,k-hi}
    uint32_t boff = (uint32_t)(((lg >> 1) * 8 + lr) * (QROWH * 2) + (lg & 1) * 16)
                    + (uint32_t)(wn * 32) * (QROWH * 2) + 128 * QROWH * 2;

    float acc[4][4][4];
#pragma unroll
    for (int i = 0; i < 4; i++)
#pragma unroll
        for (int j = 0; j < 4; j++)
#pragma unroll
            for (int r = 0; r < 4; r++) acc[i][j][r] = 0.0f;

    cp_async16(adst, Ap); cp_async16(adst + 16, Ap + 8);
    cp_async16(bdst, Bp); cp_async16(bdst + 16, Bp + 8);
    CP_COMMIT();

#pragma unroll 1
    for (int c = 0; c < NCH; c++) {
        if (c + 1 < NCH) {
            uint32_t so = ((c + 1) & 1) * STGH * 2;
            const __half* An = Ap + (c + 1) * KC;
            const __half* Bn = Bp + (c + 1) * KC;
            cp_async16(adst + so, An); cp_async16(adst + so + 16, An + 8);
            cp_async16(bdst + so, Bn); cp_async16(bdst + so + 16, Bn + 8);
            CP_COMMIT();
            CP_WAIT(1);
        } else {
            CP_WAIT(0);
        }
        __syncthreads();

        uint32_t stage = sb + (uint32_t)((c & 1) * STGH * 2);
#pragma unroll
        for (int ks = 0; ks < 2; ks++) {
            uint32_t kso = ks * 32;   // 16 halves
            uint32_t af[4][4];
#pragma unroll
            for (int mi = 0; mi < 4; mi++)
                LDSM_X4(af[mi][0], af[mi][1], af[mi][2], af[mi][3],
                        stage + aoff + mi * 16 * (QROWH * 2) + kso);
            uint32_t bf[4][2];
#pragma unroll
            for (int np = 0; np < 2; np++)
                LDSM_X4(bf[2 * np][0], bf[2 * np][1],
                        bf[2 * np + 1][0], bf[2 * np + 1][1],
                        stage + boff + np * 16 * (QROWH * 2) + kso);
#pragma unroll
            for (int mi = 0; mi < 4; mi++)
#pragma unroll
                for (int ni = 0; ni < 4; ni++)
                    MMA_F16(acc[mi][ni], af[mi], bf[ni]);
        }
        __syncthreads();
    }

#pragma unroll
    for (int mi = 0; mi < 4; mi++) {
        int gr0 = m0 + wm * 64 + mi * 16 + gid;
#pragma unroll
        for (int ni = 0; ni < 4; ni++) {
            int gc = n0 + wn * 32 + ni * 8 + 2 * tig;
            float b0v = bias[gc], b1v = bias[gc + 1];
            float v00 = fmaxf(acc[mi][ni][0] + b0v, 0.0f);
            float v01 = fmaxf(acc[mi][ni][1] + b1v, 0.0f);
            float v10 = fmaxf(acc[mi][ni][2] + b0v, 0.0f);
            float v11 = fmaxf(acc[mi][ni][3] + b1v, 0.0f);
            if (sel == 2) {
                int bb = gr0 >> 11, tl = gr0 & (T_ - 1);
                int h = gc >> 6, d = gc & 63;
                __half* vp = g_Vth + ((size_t)(bb * H_ + h) * 64 + d) * T_;
                vp[tl] = __float2half(v00);
                vp[T_ + tl] = __float2half(v01);
                vp[tl + 8] = __float2half(v10);
                vp[T_ + tl + 8] = __float2half(v11);
            } else {
                __half* Y = (sel == 0 ? g_Qh : g_Kh);
                *reinterpret_cast<uint32_t*>(&Y[(size_t)gr0 * U_ + gc]) =
                    packh2(v00, v01);
                *reinterpret_cast<uint32_t*>(&Y[(size_t)(gr0 + 8) * U_ + gc]) =
                    packh2(v10, v11);
            }
        }
    }
}

// ---------------------------------------------------------------------------
// Flash-attention fp16, softmax-free (Q,K>=0), ldmatrix fragment loads.
// ---------------------------------------------------------------------------
#define KS_B(bb) ((bb) * 9216)
#define VS_B(bb) (18432 + (bb) * 9216)
#define MS_B(bb) (36864 + (bb) * 128)
#define ATT_SMEM 37120
#define SPH 72   // tile row stride in halves (144 B)

__global__ __launch_bounds__(128, 4) void attn_mma_kernel() {
    extern __shared__ char smc[];
    uint32_t sb = smem_u32(smc);

    int tid = threadIdx.x;
    int lane = tid & 31;
    int gid = lane >> 2, tig = lane & 3;
    int lg = lane >> 3, lr = lane & 7;
    int qt = (int)gridDim.x - 1 - (int)blockIdx.x;   // big tiles first
    int bh = blockIdx.y;
    int b = bh >> 4;
    size_t baseU = (size_t)b * T_ * U_;
    int hcol = (bh & 15) * DH_;
    int qrow0 = (tid >> 5) * 16;

    int lrow = tid >> 1, lcb = (tid & 1) * 32;       // halves

    const __half* Kb = g_Kh + baseU + hcol + lcb;
    const __half* Vb = g_Vth + ((size_t)bh * 64 + lrow) * T_ + lcb;

    // ldmatrix B-operand lane offset: m0..m3 = {n-lo,k-lo},{n-lo,k-hi},
    // {n-hi,k-lo},{n-hi,k-hi}; rows stride 144 B
    uint32_t ldoff = (uint32_t)(((lg >> 1) * 8 + lr) * (SPH * 2) + (lg & 1) * 16);

    // prologue: tile 0
    {
        const __half* ks = Kb + (size_t)lrow * U_;
        uint32_t kd = sb + KS_B(0) + (uint32_t)(lrow * SPH + lcb) * 2;
        uint32_t vd = sb + VS_B(0) + (uint32_t)(lrow * SPH + lcb) * 2;
#pragma unroll
        for (int i = 0; i < 4; i++) {
            cp_async16(kd + i * 16, ks + i * 8);
            cp_async16(vd + i * 16, Vb + i * 8);
        }
        if (tid < 8)
            cp_async16(sb + MS_B(0) + tid * 16, g_maskh + b * T_ + tid * 8);
        CP_COMMIT();
    }

    // Q fragments
    uint32_t aq[4][4];
    {
        int qg = qt * 64 + qrow0 + gid;
        const __half* q0 = g_Qh + baseU + (size_t)qg * U_ + hcol;
        const __half* q1 = q0 + 8 * U_;
#pragma unroll
        for (int ks = 0; ks < 4; ks++) {
            int kh = ks * 16 + 2 * tig;
            aq[ks][0] = *reinterpret_cast<const uint32_t*>(q0 + kh);
            aq[ks][1] = *reinterpret_cast<const uint32_t*>(q1 + kh);
            aq[ks][2] = *reinterpret_cast<const uint32_t*>(q0 + kh + 8);
            aq[ks][3] = *reinterpret_cast<const uint32_t*>(q1 + kh + 8);
        }
    }

    float o[8][4];
#pragma unroll
    for (int d = 0; d < 8; d++)
#pragma unroll
        for (int r = 0; r < 4; r++) o[d][r] = 0.0f;
    float lacc[4] = {0.0f, 0.0f, 0.0f, 0.0f};

    const float CE = 0.18033688f;   // 0.125 * log2(e)
    int r0l = qrow0 + gid, r1l = r0l + 8;

#pragma unroll 1
    for (int kt = 0; kt <= qt; kt++) {
        if (kt < qt) {
            int bb = (kt + 1) & 1;
            const __half* ksrc = Kb + (size_t)((kt + 1) * 64 + lrow) * U_;
            const __half* vsrc = Vb + (kt + 1) * 64;
            uint32_t kd = sb + KS_B(bb) + (uint32_t)(lrow * SPH + lcb) * 2;
            uint32_t vd = sb + VS_B(bb) + (uint32_t)(lrow * SPH + lcb) * 2;
#pragma unroll
            for (int i = 0; i < 4; i++) {
                cp_async16(kd + i * 16, ksrc + i * 8);
                cp_async16(vd + i * 16, vsrc + i * 8);
            }
            if (tid < 8)
                cp_async16(sb + MS_B(bb) + tid * 16,
                           g_maskh + b * T_ + (kt + 1) * 64 + tid * 8);
            CP_COMMIT();
            CP_WAIT(1);
        } else {
            CP_WAIT(0);
        }
        __syncthreads();

        uint32_t kbuf = sb + KS_B(kt & 1) + ldoff;
        uint32_t vbuf = sb + VS_B(kt & 1) + ldoff;
        const uint32_t* Mh = reinterpret_cast<const uint32_t*>(smc + MS_B(kt & 1));

        // S = Q K^T
        float s[8][4];
#pragma unroll
        for (int ni = 0; ni < 8; ni++)
#pragma unroll
            for (int r = 0; r < 4; r++) s[ni][r] = 0.0f;
#pragma unroll
        for (int ks = 0; ks < 4; ks++) {
            uint32_t kso = ks * 32;
#pragma unroll
            for (int np = 0; np < 4; np++) {
                uint32_t bf[2][2];
                LDSM_X4(bf[0][0], bf[0][1], bf[1][0], bf[1][1],
                        kbuf + np * 16 * (SPH * 2) + kso);
                MMA_F16(s[2 * np], aq[ks], bf[0]);
                MMA_F16(s[2 * np + 1], aq[ks], bf[1]);
            }
        }

        // P = exp2(s*CE) * keymask (* causal on diag tile), packed half2
        bool diag = (kt == qt);
        uint32_t ph[8][2];
#pragma unroll
        for (int ni = 0; ni < 8; ni++) {
            int c0 = ni * 8 + 2 * tig;
            uint32_t km2 = Mh[c0 >> 1];
            uint32_t p0 = mulh2(ex2h2(packh2(s[ni][0] * CE, s[ni][1] * CE)), km2);
            uint32_t p1 = mulh2(ex2h2(packh2(s[ni][2] * CE, s[ni][3] * CE)), km2);
            if (diag) {
                uint32_t cm0 = packh2(c0 <= r0l ? 1.0f : 0.0f,
                                      c0 + 1 <= r0l ? 1.0f : 0.0f);
                uint32_t cm1 = packh2(c0 <= r1l ? 1.0f : 0.0f,
                                      c0 + 1 <= r1l ? 1.0f : 0.0f);
                p0 = mulh2(p0, cm0);
                p1 = mulh2(p1, cm1);
            }
            ph[ni][0] = p0;
            ph[ni][1] = p1;
        }

        // O += P V^T ; l += P @ ones
#pragma unroll
        for (int ks = 0; ks < 4; ks++) {
            uint32_t pa[4] = {ph[2 * ks][0], ph[2 * ks][1],
                              ph[2 * ks + 1][0], ph[2 * ks + 1][1]};
            uint32_t onesb[2] = {0x3C003C00u, 0x3C003C00u};
            MMA_F16(lacc, pa, onesb);
            uint32_t kso = ks * 32;
#pragma unroll
            for (int dp = 0; dp < 4; dp++) {
                uint32_t bf[2][2];
                LDSM_X4(bf[0][0], bf[0][1], bf[1][0], bf[1][1],
                        vbuf + dp * 16 * (SPH * 2) + kso);
                MMA_F16(o[2 * dp], pa, bf[0]);
                MMA_F16(o[2 * dp + 1], pa, bf[1]);
            }
        }
        __syncthreads();
    }

    // epilogue: normalize by l, query mask, write f32 [q][d]
    {
        int qg0 = qt * 64 + qrow0 + gid;
        int qg1 = qg0 + 8;
        float inv0 = g_mask[b * T_ + qg0] / lacc[0];
        float inv1 = g_mask[b * T_ + qg1] / lacc[2];
        float* o0p = g_O + baseU + (size_t)qg0 * U_ + hcol;
        float* o1p = g_O + baseU + (size_t)qg1 * U_ + hcol;
#pragma unroll
        for (int d = 0; d < 8; d++) {
            int c = d * 8 + 2 * tig;
            *reinterpret_cast<float2*>(o0p + c) =
                make_float2(o[d][0] * inv0, o[d][1] * inv0);
            *reinterpret_cast<float2*>(o1p + c) =
                make_float2(o[d][2] * inv1, o[d][3] * inv1);
        }
    }
}

// ---------------------------------------------------------------------------
// Residual + LayerNorm (biased variance, eps=1e-8) + affine
// ---------------------------------------------------------------------------
__global__ __launch_bounds__(256) void ln_kernel(
    const float* __restrict__ x, const float* __restrict__ gamma,
    const float* __restrict__ beta, float* __restrict__ out) {
    int row = blockIdx.x;
    int tid = threadIdx.x;
    __shared__ float rsum[8], rsq[8];
    __shared__ float smean, srstd;

    const float4* x4 = reinterpret_cast<const float4*>(x + (size_t)row * U_);
    const float4* o4 = reinterpret_cast<const float4*>(g_O + (size_t)row * U_);
    float4 xv = x4[tid], ov = o4[tid];
    float4 sv = make_float4(xv.x + ov.x, xv.y + ov.y, xv.z + ov.z, xv.w + ov.w);

    float s1 = sv.x + sv.y + sv.z + sv.w;
    float s2 = sv.x * sv.x + sv.y * sv.y + sv.z * sv.z + sv.w * sv.w;
#pragma unroll
    for (int o = 16; o; o >>= 1) {
        s1 += __shfl_xor_sync(0xffffffffu, s1, o);
        s2 += __shfl_xor_sync(0xffffffffu, s2, o);
    }
    if ((tid & 31) == 0) { rsum[tid >> 5] = s1; rsq[tid >> 5] = s2; }
    __syncthreads();
    if (tid == 0) {
        float t1 = 0, t2 = 0;
#pragma unroll
        for (int i = 0; i < 8; i++) { t1 += rsum[i]; t2 += rsq[i]; }
        float mean = t1 * (1.0f / U_);
        float var = t2 * (1.0f / U_) - mean * mean;
        smean = mean;
        srstd = rsqrtf(var + 1e-8f);
    }
    __syncthreads();
    float mean = smean, rstd = srstd;

    const float4* g4 = reinterpret_cast<const float4*>(gamma);
    const float4* b4 = reinterpret_cast<const float4*>(beta);
    float4 gv = g4[tid], bv = b4[tid];
    float4 o;
    o.x = gv.x * ((sv.x - mean) * rstd) + bv.x;
    o.y = gv.y * ((sv.y - mean) * rstd) + bv.y;
    o.z = gv.z * ((sv.z - mean) * rstd) + bv.z;
    o.w = gv.w * ((sv.w - mean) * rstd) + bv.w;
    reinterpret_cast<float4*>(out + (size_t)row * U_)[tid] = o;
}

// ---------------------------------------------------------------------------
extern "C" void kernel_launch(void* const* d_in, const int* in_sizes, int n_in,
                              void* d_out, int out_size) {
    const float* x     = (const float*)d_in[0];
    const float* Wq    = (const float*)d_in[1];
    const float* bq    = (const float*)d_in[2];
    const float* Wk    = (const float*)d_in[3];
    const float* bk    = (const float*)d_in[4];
    const float* Wv    = (const float*)d_in[5];
    const float* bv    = (const float*)d_in[6];
    const float* gamma = (const float*)d_in[7];
    const float* beta  = (const float*)d_in[8];
    float* out = (float*)d_out;

    cudaFuncSetAttribute(qkv_mma_kernel,
                         cudaFuncAttributeMaxDynamicSharedMemorySize, QKV_SMEM);
    cudaFuncSetAttribute(attn_mma_kernel,
                         cudaFuncAttributeMaxDynamicSharedMemorySize, ATT_SMEM);

    xconv_kernel<<<M_, 128>>>(x);
    wtrans_kernel<<<dim3(32, 32, 3), dim3(32, 8)>>>(Wq, Wk, Wv);
    qkv_mma_kernel<<<dim3(U_ / 128, M_ / 128, 3), 256, QKV_SMEM>>>(bq, bk, bv);
    attn_mma_kernel<<<dim3(T_ / 64, B_ * H_), 128, ATT_SMEM>>>();
    ln_kernel<<<M_, 256>>>(x, gamma, beta, out);
}

// round 12
// speedup vs baseline: 5.4039x; 1.0269x over previous
#include <cuda_runtime.h>
#include <cuda_fp16.h>
#include <math.h>
#include <stdint.h>

// Problem constants
#define B_  2
#define T_  2048
#define C_  1024
#define U_  1024
#define H_  16
#define DH_ 64
#define M_  4096   // B_*T_

// Scratch (device globals; no allocation allowed)
__device__ __half g_Xh[(size_t)M_ * C_];        // x in fp16
__device__ __half g_Wth[3][(size_t)C_ * U_];    // W^T [N][K] fp16
__device__ __half g_Qh[(size_t)M_ * U_];        // Q fp16 [t][U], pre-scaled by 0.125*log2(e)
__device__ __half g_Kh[(size_t)M_ * U_];        // K fp16 [t][U]
__device__ __half g_Vth[(size_t)M_ * U_];       // V fp16 transposed: [(b*H+h)*64+d][T]
__device__ float  g_O[(size_t)M_ * U_];
__device__ float  g_mask[M_];
__device__ __half g_maskh[M_];

__device__ __forceinline__ uint32_t smem_u32(const void* p) {
    uint32_t a;
    asm("{ .reg .u64 t; cvta.to.shared.u64 t, %1; cvt.u32.u64 %0, t; }"
        : "=r"(a) : "l"(p));
    return a;
}
__device__ __forceinline__ void cp_async16(uint32_t dst, const void* src) {
    asm volatile("cp.async.cg.shared.global [%0], [%1], 16;"
                 :: "r"(dst), "l"(src));
}
#define CP_COMMIT() asm volatile("cp.async.commit_group;" ::: "memory")
#define CP_WAIT(n)  asm volatile("cp.async.wait_group %0;" :: "n"(n) : "memory")

#define MMA_F16(d, a, b) \
    asm volatile("mma.sync.aligned.m16n8k16.row.col.f32.f16.f16.f32 " \
        "{%0,%1,%2,%3}, {%4,%5,%6,%7}, {%8,%9}, {%0,%1,%2,%3};" \
        : "+f"((d)[0]), "+f"((d)[1]), "+f"((d)[2]), "+f"((d)[3]) \
        : "r"((a)[0]), "r"((a)[1]), "r"((a)[2]), "r"((a)[3]), \
          "r"((b)[0]), "r"((b)[1]))

#define LDSM_X4(r0, r1, r2, r3, addr) \
    asm volatile("ldmatrix.sync.aligned.m8n8.x4.shared.b16 {%0,%1,%2,%3}, [%4];" \
        : "=r"(r0), "=r"(r1), "=r"(r2), "=r"(r3) : "r"(addr))

__device__ __forceinline__ uint32_t packh2(float lo, float hi) {
    __half2 h = __floats2half2_rn(lo, hi);
    return *reinterpret_cast<uint32_t*>(&h);
}
__device__ __forceinline__ uint32_t ex2h2(uint32_t t) {
    uint32_t r;
    asm("ex2.approx.f16x2 %0, %1;" : "=r"(r) : "r"(t));
    return r;
}
__device__ __forceinline__ uint32_t mulh2(uint32_t a, uint32_t b) {
    __half2 r = __hmul2(*reinterpret_cast<__half2*>(&a),
                        *reinterpret_cast<__half2*>(&b));
    return *reinterpret_cast<uint32_t*>(&r);
}

// ---------------------------------------------------------------------------
// x -> fp16 + row-sum mask (fused); mask stored f32 + f16
// ---------------------------------------------------------------------------
__global__ __launch_bounds__(128) void xconv_kernel(const float* __restrict__ x) {
    int row = blockIdx.x, tid = threadIdx.x;
    const float4* xr = reinterpret_cast<const float4*>(x + (size_t)row * C_);
    float4 a = xr[tid * 2], b = xr[tid * 2 + 1];
    float s = a.x + a.y + a.z + a.w + b.x + b.y + b.z + b.w;
    uint4 pk;
    pk.x = packh2(a.x, a.y); pk.y = packh2(a.z, a.w);
    pk.z = packh2(b.x, b.y); pk.w = packh2(b.z, b.w);
    *reinterpret_cast<uint4*>(g_Xh + (size_t)row * C_ + tid * 8) = pk;

    __shared__ float red[4];
#pragma unroll
    for (int o = 16; o; o >>= 1) s += __shfl_xor_sync(0xffffffffu, s, o);
    if ((tid & 31) == 0) red[tid >> 5] = s;
    __syncthreads();
    if (tid == 0) {
        float t = red[0] + red[1] + red[2] + red[3];
        float m = (t != 0.0f) ? 1.0f : 0.0f;
        g_mask[row] = m;
        g_maskh[row] = __float2half(m);
    }
}

// ---------------------------------------------------------------------------
// W [K,N] f32 -> Wt [N,K] fp16
// ---------------------------------------------------------------------------
__global__ __launch_bounds__(256) void wtrans_kernel(
    const float* __restrict__ Wq, const float* __restrict__ Wk,
    const float* __restrict__ Wv) {
    __shared__ float t[32][33];
    const float* W = blockIdx.z == 0 ? Wq : blockIdx.z == 1 ? Wk : Wv;
    __half* Wt = g_Wth[blockIdx.z];
    int x = blockIdx.x * 32 + threadIdx.x;
    int y0 = blockIdx.y * 32;
#pragma unroll
    for (int j = 0; j < 32; j += 8)
        t[threadIdx.y + j][threadIdx.x] = W[(size_t)(y0 + threadIdx.y + j) * U_ + x];
    __syncthreads();
    int ox = y0 + threadIdx.x;
    int oy0 = blockIdx.x * 32;
#pragma unroll
    for (int j = 0; j < 32; j += 8)
        Wt[(size_t)(oy0 + threadIdx.y + j) * C_ + ox] =
            __float2half(t[threadIdx.x][threadIdx.y + j]);
}

// ---------------------------------------------------------------------------
// QKV projection via mma.sync fp16 m16n8k16 + ldmatrix. Kc=64 (16 chunks).
// ---------------------------------------------------------------------------
#define KCQ   64
#define NCHQ  (C_ / KCQ)         // 16 chunks
#define QROWH 72                 // row stride in halves (144 B)
#define STGH  (2 * 128 * QROWH)  // halves per stage (A+B)
#define QKV_SMEM (2 * STGH * 2)  // 73728 bytes

__global__ __launch_bounds__(256, 2) void qkv_mma_kernel(
    const float* __restrict__ bq, const float* __restrict__ bk,
    const float* __restrict__ bv) {
    extern __shared__ char smc[];
    uint32_t sb = smem_u32(smc);
    int tid = threadIdx.x;
    int wid = tid >> 5, lane = tid & 31;
    int gid = lane >> 2, tig = lane & 3;
    int lg = lane >> 3, lr = lane & 7;
    int wm = wid >> 2, wn = wid & 3;
    int sel = blockIdx.z;
    const __half* Wt = g_Wth[sel];
    const float* bias = sel == 0 ? bq : sel == 1 ? bk : bv;
    int n0 = blockIdx.x * 128, m0 = blockIdx.y * 128;

    int lrow = tid >> 1, lcb = (tid & 1) * 32;   // halves
    const __half* Ap = g_Xh + (size_t)(m0 + lrow) * C_ + lcb;
    const __half* Bp = Wt + (size_t)(n0 + lrow) * C_ + lcb;
    uint32_t adst = sb + (uint32_t)(lrow * QROWH + lcb) * 2;
    uint32_t bdst = adst + 128 * QROWH * 2;

    // ldmatrix per-lane address offsets (bytes)
    uint32_t aoff = (uint32_t)(((lg & 1) * 8 + lr) * (QROWH * 2) + (lg >> 1) * 16)
                    + (uint32_t)(wm * 64) * (QROWH * 2);
    uint32_t boff = (uint32_t)(((lg >> 1) * 8 + lr) * (QROWH * 2) + (lg & 1) * 16)
                    + (uint32_t)(wn * 32) * (QROWH * 2) + 128 * QROWH * 2;

    float acc[4][4][4];
#pragma unroll
    for (int i = 0; i < 4; i++)
#pragma unroll
        for (int j = 0; j < 4; j++)
#pragma unroll
            for (int r = 0; r < 4; r++) acc[i][j][r] = 0.0f;

    // prologue: chunk 0 (64 halves per tensor per thread-row-half = 4x cp16)
#pragma unroll
    for (int i = 0; i < 4; i++) {
        cp_async16(adst + i * 16, Ap + i * 8);
        cp_async16(bdst + i * 16, Bp + i * 8);
    }
    CP_COMMIT();

#pragma unroll 1
    for (int c = 0; c < NCHQ; c++) {
        if (c + 1 < NCHQ) {
            uint32_t so = ((c + 1) & 1) * STGH * 2;
            const __half* An = Ap + (c + 1) * KCQ;
            const __half* Bn = Bp + (c + 1) * KCQ;
#pragma unroll
            for (int i = 0; i < 4; i++) {
                cp_async16(adst + so + i * 16, An + i * 8);
                cp_async16(bdst + so + i * 16, Bn + i * 8);
            }
            CP_COMMIT();
            CP_WAIT(1);
        } else {
            CP_WAIT(0);
        }
        __syncthreads();

        uint32_t stage = sb + (uint32_t)((c & 1) * STGH * 2);
#pragma unroll
        for (int ks = 0; ks < 4; ks++) {
            uint32_t kso = ks * 32;   // 16 halves per k-step
            uint32_t af[4][4];
#pragma unroll
            for (int mi = 0; mi < 4; mi++)
                LDSM_X4(af[mi][0], af[mi][1], af[mi][2], af[mi][3],
                        stage + aoff + mi * 16 * (QROWH * 2) + kso);
            uint32_t bf[4][2];
#pragma unroll
            for (int np = 0; np < 2; np++)
                LDSM_X4(bf[2 * np][0], bf[2 * np][1],
                        bf[2 * np + 1][0], bf[2 * np + 1][1],
                        stage + boff + np * 16 * (QROWH * 2) + kso);
#pragma unroll
            for (int mi = 0; mi < 4; mi++)
#pragma unroll
                for (int ni = 0; ni < 4; ni++)
                    MMA_F16(acc[mi][ni], af[mi], bf[ni]);
        }
        __syncthreads();
    }

    // Epilogue: bias + relu -> fp16. Q pre-scaled by CE; V transposed [d][t].
    float sc = (sel == 0) ? 0.18033688f : 1.0f;   // 0.125 * log2(e)
#pragma unroll
    for (int mi = 0; mi < 4; mi++) {
        int gr0 = m0 + wm * 64 + mi * 16 + gid;
#pragma unroll
        for (int ni = 0; ni < 4; ni++) {
            int gc = n0 + wn * 32 + ni * 8 + 2 * tig;
            float b0v = bias[gc], b1v = bias[gc + 1];
            float v00 = fmaxf(acc[mi][ni][0] + b0v, 0.0f) * sc;
            float v01 = fmaxf(acc[mi][ni][1] + b1v, 0.0f) * sc;
            float v10 = fmaxf(acc[mi][ni][2] + b0v, 0.0f) * sc;
            float v11 = fmaxf(acc[mi][ni][3] + b1v, 0.0f) * sc;
            if (sel == 2) {
                int bb = gr0 >> 11, tl = gr0 & (T_ - 1);
                int h = gc >> 6, d = gc & 63;
                __half* vp = g_Vth + ((size_t)(bb * H_ + h) * 64 + d) * T_;
                vp[tl] = __float2half(v00);
                vp[T_ + tl] = __float2half(v01);
                vp[tl + 8] = __float2half(v10);
                vp[T_ + tl + 8] = __float2half(v11);
            } else {
                __half* Y = (sel == 0 ? g_Qh : g_Kh);
                *reinterpret_cast<uint32_t*>(&Y[(size_t)gr0 * U_ + gc]) =
                    packh2(v00, v01);
                *reinterpret_cast<uint32_t*>(&Y[(size_t)(gr0 + 8) * U_ + gc]) =
                    packh2(v10, v11);
            }
        }
    }
}

// ---------------------------------------------------------------------------
// Flash-attention fp16, softmax-free, ldmatrix, 3-stage ring, ONE sync/iter.
// Q pre-scaled so P = ex2(S) directly.
// ---------------------------------------------------------------------------
#define KS_B(bb) ((bb) * 9216)
#define VS_B(bb) (27648 + (bb) * 9216)
#define MS_B(bb) (55296 + (bb) * 128)
#define ATT_SMEM 55680
#define SPH 72   // tile row stride in halves (144 B)

__global__ __launch_bounds__(128, 4) void attn_mma_kernel() {
    extern __shared__ char smc[];
    uint32_t sb = smem_u32(smc);

    int tid = threadIdx.x;
    int lane = tid & 31;
    int gid = lane >> 2, tig = lane & 3;
    int lg = lane >> 3, lr = lane & 7;
    int qt = (int)gridDim.x - 1 - (int)blockIdx.x;   // big tiles first
    int bh = blockIdx.y;
    int b = bh >> 4;
    size_t baseU = (size_t)b * T_ * U_;
    int hcol = (bh & 15) * DH_;
    int qrow0 = (tid >> 5) * 16;

    int lrow = tid >> 1, lcb = (tid & 1) * 32;       // halves

    const __half* Kb = g_Kh + baseU + hcol + lcb;
    const __half* Vb = g_Vth + ((size_t)bh * 64 + lrow) * T_ + lcb;

    uint32_t ldoff = (uint32_t)(((lg >> 1) * 8 + lr) * (SPH * 2) + (lg & 1) * 16);
    uint32_t ldst = (uint32_t)(lrow * SPH + lcb) * 2;

    // prologue: tile 0 into buffer 0
    {
        const __half* ks = Kb + (size_t)lrow * U_;
        uint32_t kd = sb + KS_B(0) + ldst;
        uint32_t vd = sb + VS_B(0) + ldst;
#pragma unroll
        for (int i = 0; i < 4; i++) {
            cp_async16(kd + i * 16, ks + i * 8);
            cp_async16(vd + i * 16, Vb + i * 8);
        }
        if (tid < 8)
            cp_async16(sb + MS_B(0) + tid * 16, g_maskh + b * T_ + tid * 8);
        CP_COMMIT();
    }

    // Q fragments (pre-scaled by CE)
    uint32_t aq[4][4];
    {
        int qg = qt * 64 + qrow0 + gid;
        const __half* q0 = g_Qh + baseU + (size_t)qg * U_ + hcol;
        const __half* q1 = q0 + 8 * U_;
#pragma unroll
        for (int ks = 0; ks < 4; ks++) {
            int kh = ks * 16 + 2 * tig;
            aq[ks][0] = *reinterpret_cast<const uint32_t*>(q0 + kh);
            aq[ks][1] = *reinterpret_cast<const uint32_t*>(q1 + kh);
            aq[ks][2] = *reinterpret_cast<const uint32_t*>(q0 + kh + 8);
            aq[ks][3] = *reinterpret_cast<const uint32_t*>(q1 + kh + 8);
        }
    }

    float o[8][4];
#pragma unroll
    for (int d = 0; d < 8; d++)
#pragma unroll
        for (int r = 0; r < 4; r++) o[d][r] = 0.0f;
    float lacc[4] = {0.0f, 0.0f, 0.0f, 0.0f};

    int r0l = qrow0 + gid, r1l = r0l + 8;
    int cb = 0;   // compute buffer = kt % 3

#pragma unroll 1
    for (int kt = 0; kt <= qt; kt++) {
        int ib = (cb == 2) ? 0 : cb + 1;   // issue buffer = (kt+1) % 3
        if (kt < qt) {
            const __half* ksrc = Kb + (size_t)((kt + 1) * 64 + lrow) * U_;
            const __half* vsrc = Vb + (kt + 1) * 64;
            uint32_t kd = sb + KS_B(ib) + ldst;
            uint32_t vd = sb + VS_B(ib) + ldst;
#pragma unroll
            for (int i = 0; i < 4; i++) {
                cp_async16(kd + i * 16, ksrc + i * 8);
                cp_async16(vd + i * 16, vsrc + i * 8);
            }
            if (tid < 8)
                cp_async16(sb + MS_B(ib) + tid * 16,
                           g_maskh + b * T_ + (kt + 1) * 64 + tid * 8);
            CP_COMMIT();
            CP_WAIT(1);
        } else {
            CP_WAIT(0);
        }
        __syncthreads();   // the ONLY barrier per iteration

        uint32_t kbuf = sb + KS_B(cb) + ldoff;
        uint32_t vbuf = sb + VS_B(cb) + ldoff;
        const uint32_t* Mh = reinterpret_cast<const uint32_t*>(smc + MS_B(cb));

        // S = Q K^T (Q pre-scaled)
        float s[8][4];
#pragma unroll
        for (int ni = 0; ni < 8; ni++)
#pragma unroll
            for (int r = 0; r < 4; r++) s[ni][r] = 0.0f;
#pragma unroll
        for (int ks = 0; ks < 4; ks++) {
            uint32_t kso = ks * 32;
#pragma unroll
            for (int np = 0; np < 4; np++) {
                uint32_t bf[2][2];
                LDSM_X4(bf[0][0], bf[0][1], bf[1][0], bf[1][1],
                        kbuf + np * 16 * (SPH * 2) + kso);
                MMA_F16(s[2 * np], aq[ks], bf[0]);
                MMA_F16(s[2 * np + 1], aq[ks], bf[1]);
            }
        }

        // P = exp2(s) * keymask (* causal on diag tile), packed half2
        bool diag = (kt == qt);
        uint32_t ph[8][2];
#pragma unroll
        for (int ni = 0; ni < 8; ni++) {
            int c0 = ni * 8 + 2 * tig;
            uint32_t km2 = Mh[c0 >> 1];
            uint32_t p0 = mulh2(ex2h2(packh2(s[ni][0], s[ni][1])), km2);
            uint32_t p1 = mulh2(ex2h2(packh2(s[ni][2], s[ni][3])), km2);
            if (diag) {
                uint32_t cm0 = packh2(c0 <= r0l ? 1.0f : 0.0f,
                                      c0 + 1 <= r0l ? 1.0f : 0.0f);
                uint32_t cm1 = packh2(c0 <= r1l ? 1.0f : 0.0f,
                                      c0 + 1 <= r1l ? 1.0f : 0.0f);
                p0 = mulh2(p0, cm0);
                p1 = mulh2(p1, cm1);
            }
            ph[ni][0] = p0;
            ph[ni][1] = p1;
        }

        // O += P V^T ; l += P @ ones
#pragma unroll
        for (int ks = 0; ks < 4; ks++) {
            uint32_t pa[4] = {ph[2 * ks][0], ph[2 * ks][1],
                              ph[2 * ks + 1][0], ph[2 * ks + 1][1]};
            uint32_t onesb[2] = {0x3C003C00u, 0x3C003C00u};
            MMA_F16(lacc, pa, onesb);
            uint32_t kso = ks * 32;
#pragma unroll
            for (int dp = 0; dp < 4; dp++) {
                uint32_t bf[2][2];
                LDSM_X4(bf[0][0], bf[0][1], bf[1][0], bf[1][1],
                        vbuf + dp * 16 * (SPH * 2) + kso);
                MMA_F16(o[2 * dp], pa, bf[0]);
                MMA_F16(o[2 * dp + 1], pa, bf[1]);
            }
        }
        cb = ib;
    }

    // epilogue: normalize by l, query mask, write f32 [q][d]
    {
        int qg0 = qt * 64 + qrow0 + gid;
        int qg1 = qg0 + 8;
        float inv0 = g_mask[b * T_ + qg0] / lacc[0];
        float inv1 = g_mask[b * T_ + qg1] / lacc[2];
        float* o0p = g_O + baseU + (size_t)qg0 * U_ + hcol;
        float* o1p = g_O + baseU + (size_t)qg1 * U_ + hcol;
#pragma unroll
        for (int d = 0; d < 8; d++) {
            int c = d * 8 + 2 * tig;
            *reinterpret_cast<float2*>(o0p + c) =
                make_float2(o[d][0] * inv0, o[d][1] * inv0);
            *reinterpret_cast<float2*>(o1p + c) =
                make_float2(o[d][2] * inv1, o[d][3] * inv1);
        }
    }
}

// ---------------------------------------------------------------------------
// Residual + LayerNorm (biased variance, eps=1e-8) + affine
// ---------------------------------------------------------------------------
__global__ __launch_bounds__(256) void ln_kernel(
    const float* __restrict__ x, const float* __restrict__ gamma,
    const float* __restrict__ beta, float* __restrict__ out) {
    int row = blockIdx.x;
    int tid = threadIdx.x;
    __shared__ float rsum[8], rsq[8];
    __shared__ float smean, srstd;

    const float4* x4 = reinterpret_cast<const float4*>(x + (size_t)row * U_);
    const float4* o4 = reinterpret_cast<const float4*>(g_O + (size_t)row * U_);
    float4 xv = x4[tid], ov = o4[tid];
    float4 sv = make_float4(xv.x + ov.x, xv.y + ov.y, xv.z + ov.z, xv.w + ov.w);

    float s1 = sv.x + sv.y + sv.z + sv.w;
    float s2 = sv.x * sv.x + sv.y * sv.y + sv.z * sv.z + sv.w * sv.w;
#pragma unroll
    for (int o = 16; o; o >>= 1) {
        s1 += __shfl_xor_sync(0xffffffffu, s1, o);
        s2 += __shfl_xor_sync(0xffffffffu, s2, o);
    }
    if ((tid & 31) == 0) { rsum[tid >> 5] = s1; rsq[tid >> 5] = s2; }
    __syncthreads();
    if (tid == 0) {
        float t1 = 0, t2 = 0;
#pragma unroll
        for (int i = 0; i < 8; i++) { t1 += rsum[i]; t2 += rsq[i]; }
        float mean = t1 * (1.0f / U_);
        float var = t2 * (1.0f / U_) - mean * mean;
        smean = mean;
        srstd = rsqrtf(var + 1e-8f);
    }
    __syncthreads();
    float mean = smean, rstd = srstd;

    const float4* g4 = reinterpret_cast<const float4*>(gamma);
    const float4* b4 = reinterpret_cast<const float4*>(beta);
    float4 gv = g4[tid], bv = b4[tid];
    float4 o;
    o.x = gv.x * ((sv.x - mean) * rstd) + bv.x;
    o.y = gv.y * ((sv.y - mean) * rstd) + bv.y;
    o.z = gv.z * ((sv.z - mean) * rstd) + bv.z;
    o.w = gv.w * ((sv.w - mean) * rstd) + bv.w;
    reinterpret_cast<float4*>(out + (size_t)row * U_)[tid] = o;
}

// ---------------------------------------------------------------------------
extern "C" void kernel_launch(void* const* d_in, const int* in_sizes, int n_in,
                              void* d_out, int out_size) {
    const float* x     = (const float*)d_in[0];
    const float* Wq    = (const float*)d_in[1];
    const float* bq    = (const float*)d_in[2];
    const float* Wk    = (const float*)d_in[3];
    const float* bk    = (const float*)d_in[4];
    const float* Wv    = (const float*)d_in[5];
    const float* bv    = (const float*)d_in[6];
    const float* gamma = (const float*)d_in[7];
    const float* beta  = (const float*)d_in[8];
    float* out = (float*)d_out;

    cudaFuncSetAttribute(qkv_mma_kernel,
                         cudaFuncAttributeMaxDynamicSharedMemorySize, QKV_SMEM);
    cudaFuncSetAttribute(attn_mma_kernel,
                         cudaFuncAttributeMaxDynamicSharedMemorySize, ATT_SMEM);

    xconv_kernel<<<M_, 128>>>(x);
    wtrans_kernel<<<dim3(32, 32, 3), dim3(32, 8)>>>(Wq, Wk, Wv);
    qkv_mma_kernel<<<dim3(U_ / 128, M_ / 128, 3), 256, QKV_SMEM>>>(bq, bk, bv);
    attn_mma_kernel<<<dim3(T_ / 64, B_ * H_), 128, ATT_SMEM>>>();
    ln_kernel<<<M_, 256>>>(x, gamma, beta, out);
}